// round 10
// baseline (speedup 1.0000x reference)
#include <cuda_runtime.h>
#include <cuda_fp16.h>
#include <mma.h>
using namespace nvcuda;

// Problem constants
#define MAXN 50000
#define MAXE 400000
#define MAXTOT (MAXN + MAXE)
#define GAT_EPS 1e-5f

// ------------------------- scratch (device globals) ------------------------
__device__ float g_xw  [MAXN * 128];
__device__ float g_aux [MAXN * 128];
__device__ float g_h1  [MAXN * 128];
__device__ float g_h2  [MAXN * 128];
__device__ float g_es  [MAXN * 4];
__device__ float g_ed  [MAXN * 4];
__device__ int   g_cnt [MAXN];
__device__ int   g_off [MAXN + 1];
__device__ int   g_cur [MAXN];
__device__ int   g_csr [MAXTOT + 8];
__device__ int   g_bsum[64];
__device__ __align__(16) __half g_Bh[3 * 16384];
__device__ __align__(16) __half g_Bl[3 * 16384];

// ------------------------- preB (+ fused zcnt) ------------------------------
__global__ void preB_zcnt(const float* __restrict__ W1, const float* __restrict__ Wres,
                          const float* __restrict__ W2, int n) {
    int i = blockIdx.x * blockDim.x + threadIdx.x;
    if (i < n) g_cnt[i] = 0;
    if (i >= 3 * 16384) return;
    const float* W = (i < 16384) ? W1 : (i < 32768 ? Wres : W2);
    float v = W[i & 16383];
    __half h = __float2half_rn(v);
    g_Bh[i] = h;
    g_Bl[i] = __float2half_rn(v - __half2float(h));
}

__global__ void histo_kernel(const int* __restrict__ dst, int E, int n) {
    int i = blockIdx.x * blockDim.x + threadIdx.x;
    if (i >= E + n) return;
    int dd = (i < E) ? dst[i] : (i - E);
    atomicAdd(&g_cnt[dd], 1);
}

__global__ void scan1_kernel(int n) {
    __shared__ int wsum[8];
    int tid = threadIdx.x;
    int base = blockIdx.x * 1024 + tid * 4;
    int c0 = (base + 0 < n) ? g_cnt[base + 0] : 0;
    int c1 = (base + 1 < n) ? g_cnt[base + 1] : 0;
    int c2 = (base + 2 < n) ? g_cnt[base + 2] : 0;
    int c3 = (base + 3 < n) ? g_cnt[base + 3] : 0;
    int t = c0 + c1 + c2 + c3;
    int lane = tid & 31, wid = tid >> 5;
    int incl = t;
    #pragma unroll
    for (int o = 1; o < 32; o <<= 1) {
        int v = __shfl_up_sync(0xffffffffu, incl, o);
        if (lane >= o) incl += v;
    }
    if (lane == 31) wsum[wid] = incl;
    __syncthreads();
    if (tid == 0) {
        int r = 0;
        #pragma unroll
        for (int k = 0; k < 8; k++) { int v = wsum[k]; wsum[k] = r; r += v; }
        g_bsum[blockIdx.x] = r;
    }
    __syncthreads();
    int run = wsum[wid] + incl - t;
    if (base + 0 < n) g_off[base + 0] = run; run += c0;
    if (base + 1 < n) g_off[base + 1] = run; run += c1;
    if (base + 2 < n) g_off[base + 2] = run; run += c2;
    if (base + 3 < n) g_off[base + 3] = run;
}

__global__ void scan23_kernel(int nb, int n) {
    __shared__ int sboff[64];
    __shared__ int sgrand;
    int tid = threadIdx.x;
    if (tid < 32) {
        int lane = tid;
        int v0 = (lane < nb) ? g_bsum[lane] : 0;
        int v1 = (32 + lane < nb) ? g_bsum[32 + lane] : 0;
        int i0 = v0;
        #pragma unroll
        for (int o = 1; o < 32; o <<= 1) {
            int q = __shfl_up_sync(0xffffffffu, i0, o);
            if (lane >= o) i0 += q;
        }
        int tot0 = __shfl_sync(0xffffffffu, i0, 31);
        int i1 = v1;
        #pragma unroll
        for (int o = 1; o < 32; o <<= 1) {
            int q = __shfl_up_sync(0xffffffffu, i1, o);
            if (lane >= o) i1 += q;
        }
        i1 += tot0;
        sboff[lane] = i0 - v0;
        sboff[32 + lane] = i1 - v1;
        if (lane == 31) sgrand = i1;
    }
    __syncthreads();
    int i = blockIdx.x * blockDim.x + tid;
    if (i < n) {
        int o = g_off[i] + sboff[i >> 10];
        g_off[i] = o;
        g_cur[i] = o;
    }
    if (blockIdx.x == 0 && tid == 0) g_off[n] = sgrand;
}

__global__ void scatter_kernel(const int* __restrict__ src, const int* __restrict__ dst,
                               int E, int n) {
    int i = blockIdx.x * blockDim.x + threadIdx.x;
    if (i >= E + n) return;
    int ss, dd;
    if (i < E) { ss = src[i]; dd = dst[i]; }
    else       { ss = dd = i - E; }
    int p = atomicAdd(&g_cur[dd], 1);
    g_csr[p] = ss;
}

// ------------------------- GEMM: M-tile 64, 2 CTAs/SM -----------------------
#define LDH 136                                   // half stride (128 + 8 pad)
#define SM64 ((2 * 128 * LDH + 2 * 64 * LDH) * 2) // 104448 B

__device__ __forceinline__ void cp16(__half* dst, const __half* src) {
    unsigned d = (unsigned)__cvta_generic_to_shared(dst);
    asm volatile("cp.async.cg.shared.global [%0], [%1], 16;\n" :: "r"(d), "l"(src));
}

// C[M,128] = A[M,128] @ B[128,128], fp16x3 split, whole K, one sync.
// 256 threads = 8 warps: wm = wid&1 (32-row band), wn = wid>>1 (32-col band).
__global__ void __launch_bounds__(256, 2)
hgemm64(const float* __restrict__ A, float* __restrict__ C, int M, int boff,
        const float* __restrict__ a_s, const float* __restrict__ a_d) {
    extern __shared__ __half sm[];
    __half* sBh = sm;
    __half* sBl = sBh + 128 * LDH;
    __half* sAh = sBl + 128 * LDH;
    __half* sAl = sAh + 64 * LDH;
    int tid = threadIdx.x;
    int wid = tid >> 5, lane = tid & 31;
    int wm = wid & 1, wn = wid >> 1;
    int row0 = blockIdx.x * 64;

    // B: 4096 16B chunks via cp.async (hi plane 2048 + lo plane 2048)
    #pragma unroll
    for (int it = 0; it < 16; it++) {
        int idx = tid + it * 256;
        int c4 = idx & 15, row = (idx >> 4) & 127, hl = idx >> 11;
        const __half* src = (hl ? g_Bl : g_Bh) + boff + row * 128 + c4 * 8;
        __half* dst = (hl ? sBl : sBh) + row * LDH + c4 * 8;
        cp16(dst, src);
    }
    asm volatile("cp.async.commit_group;\n");

    // A: 64 rows x 128 cols fp32 -> hi/lo fp16 (overlaps with B cp.async)
    #pragma unroll
    for (int it = 0; it < 16; it++) {
        int idx = tid + it * 256;
        int c2 = idx & 63, r = idx >> 6;
        int gr = row0 + r;
        float2 v = make_float2(0.f, 0.f);
        if (gr < M) v = *(const float2*)(A + (size_t)gr * 128 + c2 * 2);
        __half hx = __float2half_rn(v.x), hy = __float2half_rn(v.y);
        *(__half2*)(sAh + r * LDH + c2 * 2) = __halves2half2(hx, hy);
        *(__half2*)(sAl + r * LDH + c2 * 2) =
            __halves2half2(__float2half_rn(v.x - __half2float(hx)),
                           __float2half_rn(v.y - __half2float(hy)));
    }
    asm volatile("cp.async.wait_group 0;\n");
    __syncthreads();

    wmma::fragment<wmma::accumulator, 16, 16, 16, float> acc[2][2];
    #pragma unroll
    for (int i = 0; i < 2; i++)
        #pragma unroll
        for (int j = 0; j < 2; j++)
            wmma::fill_fragment(acc[i][j], 0.f);

    #pragma unroll
    for (int kk = 0; kk < 8; kk++) {
        wmma::fragment<wmma::matrix_a, 16, 16, 16, __half, wmma::row_major> ah[2], al[2];
        #pragma unroll
        for (int i = 0; i < 2; i++) {
            wmma::load_matrix_sync(ah[i], sAh + (wm * 32 + i * 16) * LDH + kk * 16, LDH);
            wmma::load_matrix_sync(al[i], sAl + (wm * 32 + i * 16) * LDH + kk * 16, LDH);
        }
        #pragma unroll
        for (int j = 0; j < 2; j++) {
            wmma::fragment<wmma::matrix_b, 16, 16, 16, __half, wmma::row_major> bh, bl;
            wmma::load_matrix_sync(bh, sBh + kk * 16 * LDH + wn * 32 + j * 16, LDH);
            wmma::load_matrix_sync(bl, sBl + kk * 16 * LDH + wn * 32 + j * 16, LDH);
            #pragma unroll
            for (int i = 0; i < 2; i++) {
                wmma::mma_sync(acc[i][j], ah[i], bh, acc[i][j]);
                wmma::mma_sync(acc[i][j], al[i], bh, acc[i][j]);
                wmma::mma_sync(acc[i][j], ah[i], bl, acc[i][j]);
            }
        }
    }

    #pragma unroll
    for (int i = 0; i < 2; i++) {
        int gr = row0 + wm * 32 + i * 16;
        if (gr < M) {
            #pragma unroll
            for (int j = 0; j < 2; j++)
                wmma::store_matrix_sync(C + (size_t)gr * 128 + wn * 32 + j * 16,
                                        acc[i][j], 128, wmma::mem_row_major);
        }
    }

    // fused dots: 8 warps x 8 rows (reads freshly stored C)
    if (a_s) {
        __syncthreads();
        float4 asv = *(const float4*)(a_s + lane * 4);
        float4 adv = *(const float4*)(a_d + lane * 4);
        #pragma unroll
        for (int rr = 0; rr < 8; rr++) {
            int row = row0 + wid * 8 + rr;
            if (row >= M) break;
            float4 xv = *(const float4*)(C + (size_t)row * 128 + lane * 4);
            float ps = xv.x * asv.x + xv.y * asv.y + xv.z * asv.z + xv.w * asv.w;
            float pd = xv.x * adv.x + xv.y * adv.y + xv.z * adv.z + xv.w * adv.w;
            ps += __shfl_xor_sync(0xffffffffu, ps, 1);
            ps += __shfl_xor_sync(0xffffffffu, ps, 2);
            ps += __shfl_xor_sync(0xffffffffu, ps, 4);
            pd += __shfl_xor_sync(0xffffffffu, pd, 1);
            pd += __shfl_xor_sync(0xffffffffu, pd, 2);
            pd += __shfl_xor_sync(0xffffffffu, pd, 4);
            if ((lane & 7) == 0) {
                int h = lane >> 3;
                g_es[row * 4 + h] = ps;
                g_ed[row * 4 + h] = pd;
            }
        }
    }
}

// ------------------------- layer-3 GEMM (40 cols) + fused dots --------------
__global__ void gemm40(const float* __restrict__ A, const float* __restrict__ B,
                       const float* __restrict__ a_s, const float* __restrict__ a_d,
                       float* __restrict__ C, int M) {
    __shared__ float Ws[128 * 40];
    for (int i = threadIdx.x; i < 128 * 40; i += blockDim.x) Ws[i] = B[i];
    __syncthreads();
    int row  = blockIdx.x * 8 + (threadIdx.x >> 5);
    int lane = threadIdx.x & 31;
    if (row >= M) return;
    const float* a = A + (size_t)row * 128;
    float acc1 = 0.f, acc2 = 0.f;
    #pragma unroll 8
    for (int k = 0; k < 128; k++) {
        float av = __ldg(a + k);
        acc1 += av * Ws[k * 40 + lane];
        if (lane < 8) acc2 += av * Ws[k * 40 + 32 + lane];
    }
    C[(size_t)row * 40 + lane] = acc1;
    if (lane < 8) C[(size_t)row * 40 + 32 + lane] = acc2;
    float ps = acc1 * a_s[lane] + ((lane < 8) ? acc2 * a_s[32 + lane] : 0.f);
    float pd = acc1 * a_d[lane] + ((lane < 8) ? acc2 * a_d[32 + lane] : 0.f);
    #pragma unroll
    for (int o = 16; o; o >>= 1) {
        ps += __shfl_xor_sync(0xffffffffu, ps, o);
        pd += __shfl_xor_sync(0xffffffffu, pd, o);
    }
    if (lane == 0) { g_es[row] = ps; g_ed[row] = pd; }
}

// ------------------------- fused GAT agg: stats + gather + BN/res/ELU -------
__global__ void agg128(const float* __restrict__ xw,
                       const float* __restrict__ bias,
                       const float* __restrict__ gam, const float* __restrict__ bet,
                       const float* __restrict__ mean, const float* __restrict__ var,
                       const float* __restrict__ res, float* __restrict__ out, int n) {
    int node = blockIdx.x * 8 + (threadIdx.x >> 5);
    if (node >= n) return;
    int lane = threadIdx.x & 31;
    int head = lane >> 3, esub = lane & 7;
    float ed = g_ed[node * 4 + head];
    int s = g_off[node], e = g_off[node + 1];

    float m = -1e30f, den = 0.f;
    for (int base = s; base < e; base += 8) {
        int i = base + esub;
        bool val = i < e;
        int u = val ? g_csr[i] : 0;
        float ev = g_es[u * 4 + head] + ed;
        ev = ev > 0.f ? ev : 0.2f * ev;
        if (!val) ev = -1e30f;
        float gm = ev;
        gm = fmaxf(gm, __shfl_xor_sync(0xffffffffu, gm, 1));
        gm = fmaxf(gm, __shfl_xor_sync(0xffffffffu, gm, 2));
        gm = fmaxf(gm, __shfl_xor_sync(0xffffffffu, gm, 4));
        float nm = fmaxf(m, gm);
        float w = __expf(ev - nm);
        w += __shfl_xor_sync(0xffffffffu, w, 1);
        w += __shfl_xor_sync(0xffffffffu, w, 2);
        w += __shfl_xor_sync(0xffffffffu, w, 4);
        den = den * __expf(m - nm) + w;
        m = nm;
    }
    float rinv = 1.f / den;

    float4 acc = make_float4(0.f, 0.f, 0.f, 0.f);
    int u = g_csr[s];
    for (int i = s; i < e; i++) {
        int un = g_csr[i + 1];
        float ev = g_es[u * 4 + head] + ed;
        ev = ev > 0.f ? ev : 0.2f * ev;
        float w = __expf(ev - m);
        float4 xv = *(const float4*)(xw + (size_t)u * 128 + lane * 4);
        acc.x += w * xv.x; acc.y += w * xv.y;
        acc.z += w * xv.z; acc.w += w * xv.w;
        u = un;
    }

    int c = lane * 4;
    float4 b4 = *(const float4*)(bias + c);
    float4 g4 = *(const float4*)(gam + c);
    float4 e4 = *(const float4*)(bet + c);
    float4 m4 = *(const float4*)(mean + c);
    float4 v4 = *(const float4*)(var + c);
    float4 r4 = *(const float4*)(res + (size_t)node * 128 + c);
    float o0 = (acc.x * rinv + b4.x - m4.x) * rsqrtf(v4.x + GAT_EPS) * g4.x + e4.x + r4.x;
    float o1 = (acc.y * rinv + b4.y - m4.y) * rsqrtf(v4.y + GAT_EPS) * g4.y + e4.y + r4.y;
    float o2 = (acc.z * rinv + b4.z - m4.z) * rsqrtf(v4.z + GAT_EPS) * g4.z + e4.z + r4.z;
    float o3 = (acc.w * rinv + b4.w - m4.w) * rsqrtf(v4.w + GAT_EPS) * g4.w + e4.w + r4.w;
    float4 o = make_float4(o0 > 0.f ? o0 : expm1f(o0),
                           o1 > 0.f ? o1 : expm1f(o1),
                           o2 > 0.f ? o2 : expm1f(o2),
                           o3 > 0.f ? o3 : expm1f(o3));
    *(float4*)(out + (size_t)node * 128 + c) = o;
}

// ------------------------- layer-3 agg (two-pass, branch-free) --------------
__global__ void agg40(const float* __restrict__ xw, const float* __restrict__ bias,
                      float* __restrict__ out, int n) {
    int node = blockIdx.x * 8 + (threadIdx.x >> 5);
    if (node >= n) return;
    int lane = threadIdx.x & 31;
    float ed = g_ed[node];
    int s = g_off[node], e = g_off[node + 1];

    float m = -1e30f, den = 0.f;
    for (int base = s; base < e; base += 32) {
        int i = base + lane;
        bool val = i < e;
        int u = val ? g_csr[i] : 0;
        float ev = g_es[u] + ed;
        ev = ev > 0.f ? ev : 0.2f * ev;
        if (!val) ev = -1e30f;
        float gm = ev;
        #pragma unroll
        for (int o = 16; o; o >>= 1) gm = fmaxf(gm, __shfl_xor_sync(0xffffffffu, gm, o));
        float nm = fmaxf(m, gm);
        float w = __expf(ev - nm);
        #pragma unroll
        for (int o = 16; o; o >>= 1) w += __shfl_xor_sync(0xffffffffu, w, o);
        den = den * __expf(m - nm) + w;
        m = nm;
    }
    float rinv = 1.f / den;

    float a1 = 0.f, a2 = 0.f;
    int u = g_csr[s];
    for (int i = s; i < e; i++) {
        int un = g_csr[i + 1];
        float ev = g_es[u] + ed;
        ev = ev > 0.f ? ev : 0.2f * ev;
        float w = __expf(ev - m);
        a1 += w * xw[(size_t)u * 40 + lane];
        if (lane < 8) a2 += w * xw[(size_t)u * 40 + 32 + lane];
        u = un;
    }
    out[(size_t)node * 40 + lane] = a1 * rinv + bias[lane];
    if (lane < 8) out[(size_t)node * 40 + 32 + lane] = a2 * rinv + bias[32 + lane];
}

// ------------------------- launch ------------------------------------------
extern "C" void kernel_launch(void* const* d_in, const int* in_sizes, int n_in,
                              void* d_out, int out_size) {
    const float* x    = (const float*)d_in[0];
    const int*   ei   = (const int*)  d_in[1];
    const float* W1   = (const float*)d_in[2];
    const float* as1  = (const float*)d_in[3];
    const float* ad1  = (const float*)d_in[4];
    const float* b1   = (const float*)d_in[5];
    const float* W2   = (const float*)d_in[6];
    const float* as2  = (const float*)d_in[7];
    const float* ad2  = (const float*)d_in[8];
    const float* b2   = (const float*)d_in[9];
    const float* W3   = (const float*)d_in[10];
    const float* as3  = (const float*)d_in[11];
    const float* ad3  = (const float*)d_in[12];
    const float* b3   = (const float*)d_in[13];
    const float* Wres = (const float*)d_in[14];
    const float* g1   = (const float*)d_in[15];
    const float* be1  = (const float*)d_in[16];
    const float* m1   = (const float*)d_in[17];
    const float* v1   = (const float*)d_in[18];
    const float* g2   = (const float*)d_in[19];
    const float* be2  = (const float*)d_in[20];
    const float* m2   = (const float*)d_in[21];
    const float* v2   = (const float*)d_in[22];

    int n = in_sizes[0] / 128;
    int E = in_sizes[1] / 2;
    const int* src = ei;
    const int* dst = ei + E;
    int tot = E + n;
    int nblk = (n + 1023) / 1024;

    float *p_xw, *p_aux, *p_h1, *p_h2;
    cudaGetSymbolAddress((void**)&p_xw,  g_xw);
    cudaGetSymbolAddress((void**)&p_aux, g_aux);
    cudaGetSymbolAddress((void**)&p_h1,  g_h1);
    cudaGetSymbolAddress((void**)&p_h2,  g_h2);

    cudaFuncSetAttribute(hgemm64, cudaFuncAttributeMaxDynamicSharedMemorySize, SM64);

    int nb_gemm = (n + 63) / 64;
    int nb_warp = (n + 7) / 8;

    preB_zcnt <<<196, 256>>>(W1, Wres, W2, n);                             // 1
    histo_kernel <<<(tot + 255) / 256, 256>>>(dst, E, n);                  // 2
    scan1_kernel <<<nblk, 256>>>(n);                                       // 3
    hgemm64 <<<nb_gemm, 256, SM64>>>(x, p_xw, n, 0, as1, ad1);             // 4 (profiled)
    hgemm64 <<<nb_gemm, 256, SM64>>>(x, p_aux, n, 16384, nullptr, nullptr);// 5
    scan23_kernel <<<(n + 255) / 256, 256>>>(nblk, n);                     // 6
    scatter_kernel <<<(tot + 255) / 256, 256>>>(src, dst, E, n);           // 7

    // ---- layer 1 aggregation ----
    agg128 <<<nb_warp, 256>>>(p_xw, b1, g1, be1, m1, v1, p_aux, p_h1, n);  // 8

    // ---- layer 2 ----
    hgemm64 <<<nb_gemm, 256, SM64>>>(p_h1, p_xw, n, 32768, as2, ad2);      // 9
    agg128 <<<nb_warp, 256>>>(p_xw, b2, g2, be2, m2, v2, p_h1, p_h2, n);   // 10

    // ---- layer 3 ----
    gemm40 <<<nb_warp, 256>>>(p_h2, W3, as3, ad3, p_aux, n);               // 11
    agg40  <<<nb_warp, 256>>>(p_aux, b3, (float*)d_out, n);                // 12
}

// round 11
// speedup vs baseline: 1.0440x; 1.0440x over previous
#include <cuda_runtime.h>
#include <cuda_fp16.h>
#include <mma.h>
using namespace nvcuda;

// Problem constants
#define MAXN 50000
#define MAXE 400000
#define MAXTOT (MAXN + MAXE)
#define GAT_EPS 1e-5f

// ------------------------- scratch (device globals) ------------------------
__device__ float g_xw  [MAXN * 128];
__device__ float g_aux [MAXN * 128];
__device__ float g_h1  [MAXN * 128];
__device__ float g_h2  [MAXN * 128];
__device__ float g_es  [MAXN * 4];
__device__ float g_ed  [MAXN * 4];
__device__ int   g_cnt [MAXN];
__device__ int   g_off [MAXN + 1];
__device__ int   g_cur [MAXN];
__device__ int   g_csr [MAXTOT + 8];
__device__ int   g_bsum[64];
__device__ __align__(16) __half g_Bh[3 * 16384];
__device__ __align__(16) __half g_Bl[3 * 16384];
__device__ __align__(16) __half g_xwh[MAXN * 128];   // fp16 gather operand

// ------------------------- preB (+ fused zcnt) ------------------------------
__global__ void preB_zcnt(const float* __restrict__ W1, const float* __restrict__ Wres,
                          const float* __restrict__ W2, int n) {
    int i = blockIdx.x * blockDim.x + threadIdx.x;
    if (i < n) g_cnt[i] = 0;
    if (i >= 3 * 16384) return;
    const float* W = (i < 16384) ? W1 : (i < 32768 ? Wres : W2);
    float v = W[i & 16383];
    __half h = __float2half_rn(v);
    g_Bh[i] = h;
    g_Bl[i] = __float2half_rn(v - __half2float(h));
}

__global__ void histo_kernel(const int* __restrict__ dst, int E, int n) {
    int i = blockIdx.x * blockDim.x + threadIdx.x;
    if (i >= E + n) return;
    int dd = (i < E) ? dst[i] : (i - E);
    atomicAdd(&g_cnt[dd], 1);
}

__global__ void scan1_kernel(int n) {
    __shared__ int wsum[8];
    int tid = threadIdx.x;
    int base = blockIdx.x * 1024 + tid * 4;
    int c0 = (base + 0 < n) ? g_cnt[base + 0] : 0;
    int c1 = (base + 1 < n) ? g_cnt[base + 1] : 0;
    int c2 = (base + 2 < n) ? g_cnt[base + 2] : 0;
    int c3 = (base + 3 < n) ? g_cnt[base + 3] : 0;
    int t = c0 + c1 + c2 + c3;
    int lane = tid & 31, wid = tid >> 5;
    int incl = t;
    #pragma unroll
    for (int o = 1; o < 32; o <<= 1) {
        int v = __shfl_up_sync(0xffffffffu, incl, o);
        if (lane >= o) incl += v;
    }
    if (lane == 31) wsum[wid] = incl;
    __syncthreads();
    if (tid == 0) {
        int r = 0;
        #pragma unroll
        for (int k = 0; k < 8; k++) { int v = wsum[k]; wsum[k] = r; r += v; }
        g_bsum[blockIdx.x] = r;
    }
    __syncthreads();
    int run = wsum[wid] + incl - t;
    if (base + 0 < n) g_off[base + 0] = run; run += c0;
    if (base + 1 < n) g_off[base + 1] = run; run += c1;
    if (base + 2 < n) g_off[base + 2] = run; run += c2;
    if (base + 3 < n) g_off[base + 3] = run;
}

__global__ void scan23_kernel(int nb, int n) {
    __shared__ int sboff[64];
    __shared__ int sgrand;
    int tid = threadIdx.x;
    if (tid < 32) {
        int lane = tid;
        int v0 = (lane < nb) ? g_bsum[lane] : 0;
        int v1 = (32 + lane < nb) ? g_bsum[32 + lane] : 0;
        int i0 = v0;
        #pragma unroll
        for (int o = 1; o < 32; o <<= 1) {
            int q = __shfl_up_sync(0xffffffffu, i0, o);
            if (lane >= o) i0 += q;
        }
        int tot0 = __shfl_sync(0xffffffffu, i0, 31);
        int i1 = v1;
        #pragma unroll
        for (int o = 1; o < 32; o <<= 1) {
            int q = __shfl_up_sync(0xffffffffu, i1, o);
            if (lane >= o) i1 += q;
        }
        i1 += tot0;
        sboff[lane] = i0 - v0;
        sboff[32 + lane] = i1 - v1;
        if (lane == 31) sgrand = i1;
    }
    __syncthreads();
    int i = blockIdx.x * blockDim.x + tid;
    if (i < n) {
        int o = g_off[i] + sboff[i >> 10];
        g_off[i] = o;
        g_cur[i] = o;
    }
    if (blockIdx.x == 0 && tid == 0) g_off[n] = sgrand;
}

__global__ void scatter_kernel(const int* __restrict__ src, const int* __restrict__ dst,
                               int E, int n) {
    int i = blockIdx.x * blockDim.x + threadIdx.x;
    if (i >= E + n) return;
    int ss, dd;
    if (i < E) { ss = src[i]; dd = dst[i]; }
    else       { ss = dd = i - E; }
    int p = atomicAdd(&g_cur[dd], 1);
    g_csr[p] = ss;
}

// ------------------------- GEMM helpers -------------------------------------
#define LDAH 136
#define LDBH 272
#define LDBS 136
#define SM_DUAL ((2 * 128 * LDBH + 2 * 128 * LDAH) * 2)   // 208896 B
#define SM_SNGL ((2 * 128 * LDBS + 2 * 128 * LDAH) * 2)   // 139264 B

__device__ __forceinline__ void cp16(__half* dst, const __half* src) {
    unsigned d = (unsigned)__cvta_generic_to_shared(dst);
    asm volatile("cp.async.cg.shared.global [%0], [%1], 16;\n" :: "r"(d), "l"(src));
}

// write one row's lane*4 channels to g_xwh as packed fp16
__device__ __forceinline__ void store_xwh(int row, int lane, float4 xv) {
    __half2 ha = __floats2half2_rn(xv.x, xv.y);
    __half2 hb = __floats2half2_rn(xv.z, xv.w);
    uint2 p = make_uint2(*(unsigned*)&ha, *(unsigned*)&hb);
    *(uint2*)(g_xwh + (size_t)row * 128 + lane * 4) = p;
}

// ------------------------- dual WMMA GEMM (layer 1) -------------------------
__global__ void __launch_bounds__(512, 1)
hgemm_dual(const float* __restrict__ A, float* __restrict__ C1, float* __restrict__ C2,
           int M, int boff1, int boff2,
           const float* __restrict__ a_s, const float* __restrict__ a_d) {
    extern __shared__ __half sm[];
    __half* sBh = sm;
    __half* sBl = sBh + 128 * LDBH;
    __half* sAh = sBl + 128 * LDBH;
    __half* sAl = sAh + 128 * LDAH;
    int tid = threadIdx.x;
    int wid = tid >> 5, lane = tid & 31;
    int wm = wid & 3, wn = wid >> 2;
    int mi = wn >> 1, nsub = wn & 1;
    int row0 = blockIdx.x * 128;

    #pragma unroll
    for (int it = 0; it < 16; it++) {
        int idx = tid + it * 512;
        int c4 = idx & 15, row = (idx >> 4) & 127, mat = (idx >> 11) & 1, hl = idx >> 12;
        const __half* src = (hl ? g_Bl : g_Bh) + (mat ? boff2 : boff1) + row * 128 + c4 * 8;
        __half* dst = (hl ? sBl : sBh) + row * LDBH + mat * 128 + c4 * 8;
        cp16(dst, src);
    }
    asm volatile("cp.async.commit_group;\n");

    #pragma unroll
    for (int it = 0; it < 16; it++) {
        int idx = tid + it * 512;
        int c2 = idx & 63, r = idx >> 6;
        int gr = row0 + r;
        float2 v = make_float2(0.f, 0.f);
        if (gr < M) v = *(const float2*)(A + (size_t)gr * 128 + c2 * 2);
        __half hx = __float2half_rn(v.x), hy = __float2half_rn(v.y);
        *(__half2*)(sAh + r * LDAH + c2 * 2) = __halves2half2(hx, hy);
        *(__half2*)(sAl + r * LDAH + c2 * 2) =
            __halves2half2(__float2half_rn(v.x - __half2float(hx)),
                           __float2half_rn(v.y - __half2float(hy)));
    }
    asm volatile("cp.async.wait_group 0;\n");
    __syncthreads();

    wmma::fragment<wmma::accumulator, 16, 16, 16, float> acc[2][4];
    #pragma unroll
    for (int i = 0; i < 2; i++)
        #pragma unroll
        for (int j = 0; j < 4; j++)
            wmma::fill_fragment(acc[i][j], 0.f);

    #pragma unroll
    for (int kk = 0; kk < 8; kk++) {
        wmma::fragment<wmma::matrix_a, 16, 16, 16, __half, wmma::row_major> ah[2], al[2];
        #pragma unroll
        for (int i = 0; i < 2; i++) {
            wmma::load_matrix_sync(ah[i], sAh + (wm * 32 + i * 16) * LDAH + kk * 16, LDAH);
            wmma::load_matrix_sync(al[i], sAl + (wm * 32 + i * 16) * LDAH + kk * 16, LDAH);
        }
        #pragma unroll
        for (int j = 0; j < 4; j++) {
            wmma::fragment<wmma::matrix_b, 16, 16, 16, __half, wmma::row_major> bh, bl;
            wmma::load_matrix_sync(bh, sBh + kk * 16 * LDBH + wn * 64 + j * 16, LDBH);
            wmma::load_matrix_sync(bl, sBl + kk * 16 * LDBH + wn * 64 + j * 16, LDBH);
            #pragma unroll
            for (int i = 0; i < 2; i++) {
                wmma::mma_sync(acc[i][j], ah[i], bh, acc[i][j]);
                wmma::mma_sync(acc[i][j], al[i], bh, acc[i][j]);
                wmma::mma_sync(acc[i][j], ah[i], bl, acc[i][j]);
            }
        }
    }

    float* C = mi ? C2 : C1;
    #pragma unroll
    for (int i = 0; i < 2; i++) {
        int gr = row0 + wm * 32 + i * 16;
        if (gr < M) {
            #pragma unroll
            for (int j = 0; j < 4; j++)
                wmma::store_matrix_sync(C + (size_t)gr * 128 + nsub * 64 + j * 16,
                                        acc[i][j], 128, wmma::mem_row_major);
        }
    }

    // fused dots + fp16 mirror of C1 (xw)
    __syncthreads();
    float4 asv = *(const float4*)(a_s + lane * 4);
    float4 adv = *(const float4*)(a_d + lane * 4);
    #pragma unroll
    for (int rr = 0; rr < 8; rr++) {
        int row = row0 + wid * 8 + rr;
        if (row >= M) break;
        float4 xv = *(const float4*)(C1 + (size_t)row * 128 + lane * 4);
        store_xwh(row, lane, xv);
        float ps = xv.x * asv.x + xv.y * asv.y + xv.z * asv.z + xv.w * asv.w;
        float pd = xv.x * adv.x + xv.y * adv.y + xv.z * adv.z + xv.w * adv.w;
        ps += __shfl_xor_sync(0xffffffffu, ps, 1);
        ps += __shfl_xor_sync(0xffffffffu, ps, 2);
        ps += __shfl_xor_sync(0xffffffffu, ps, 4);
        pd += __shfl_xor_sync(0xffffffffu, pd, 1);
        pd += __shfl_xor_sync(0xffffffffu, pd, 2);
        pd += __shfl_xor_sync(0xffffffffu, pd, 4);
        if ((lane & 7) == 0) {
            int h = lane >> 3;
            g_es[row * 4 + h] = ps;
            g_ed[row * 4 + h] = pd;
        }
    }
}

// ------------------------- single WMMA GEMM (layer 2) -----------------------
__global__ void __launch_bounds__(512, 1)
hgemm128(const float* __restrict__ A, float* __restrict__ C, int M, int boff,
         const float* __restrict__ a_s, const float* __restrict__ a_d) {
    extern __shared__ __half sm[];
    __half* sBh = sm;
    __half* sBl = sBh + 128 * LDBS;
    __half* sAh = sBl + 128 * LDBS;
    __half* sAl = sAh + 128 * LDAH;
    int tid = threadIdx.x;
    int wid = tid >> 5, lane = tid & 31;
    int wm = wid & 3, wn = wid >> 2;
    int row0 = blockIdx.x * 128;

    #pragma unroll
    for (int it = 0; it < 8; it++) {
        int idx = tid + it * 512;
        int c4 = idx & 15, row = (idx >> 4) & 127, hl = idx >> 11;
        const __half* src = (hl ? g_Bl : g_Bh) + boff + row * 128 + c4 * 8;
        __half* dst = (hl ? sBl : sBh) + row * LDBS + c4 * 8;
        cp16(dst, src);
    }
    asm volatile("cp.async.commit_group;\n");

    #pragma unroll
    for (int it = 0; it < 16; it++) {
        int idx = tid + it * 512;
        int c2 = idx & 63, r = idx >> 6;
        int gr = row0 + r;
        float2 v = make_float2(0.f, 0.f);
        if (gr < M) v = *(const float2*)(A + (size_t)gr * 128 + c2 * 2);
        __half hx = __float2half_rn(v.x), hy = __float2half_rn(v.y);
        *(__half2*)(sAh + r * LDAH + c2 * 2) = __halves2half2(hx, hy);
        *(__half2*)(sAl + r * LDAH + c2 * 2) =
            __halves2half2(__float2half_rn(v.x - __half2float(hx)),
                           __float2half_rn(v.y - __half2float(hy)));
    }
    asm volatile("cp.async.wait_group 0;\n");
    __syncthreads();

    wmma::fragment<wmma::accumulator, 16, 16, 16, float> acc[2][2];
    #pragma unroll
    for (int i = 0; i < 2; i++)
        #pragma unroll
        for (int j = 0; j < 2; j++)
            wmma::fill_fragment(acc[i][j], 0.f);

    #pragma unroll
    for (int kk = 0; kk < 8; kk++) {
        wmma::fragment<wmma::matrix_a, 16, 16, 16, __half, wmma::row_major> ah[2], al[2];
        #pragma unroll
        for (int i = 0; i < 2; i++) {
            wmma::load_matrix_sync(ah[i], sAh + (wm * 32 + i * 16) * LDAH + kk * 16, LDAH);
            wmma::load_matrix_sync(al[i], sAl + (wm * 32 + i * 16) * LDAH + kk * 16, LDAH);
        }
        #pragma unroll
        for (int j = 0; j < 2; j++) {
            wmma::fragment<wmma::matrix_b, 16, 16, 16, __half, wmma::row_major> bh, bl;
            wmma::load_matrix_sync(bh, sBh + kk * 16 * LDBS + wn * 32 + j * 16, LDBS);
            wmma::load_matrix_sync(bl, sBl + kk * 16 * LDBS + wn * 32 + j * 16, LDBS);
            #pragma unroll
            for (int i = 0; i < 2; i++) {
                wmma::mma_sync(acc[i][j], ah[i], bh, acc[i][j]);
                wmma::mma_sync(acc[i][j], al[i], bh, acc[i][j]);
                wmma::mma_sync(acc[i][j], ah[i], bl, acc[i][j]);
            }
        }
    }

    #pragma unroll
    for (int i = 0; i < 2; i++) {
        int gr = row0 + wm * 32 + i * 16;
        if (gr < M) {
            #pragma unroll
            for (int j = 0; j < 2; j++)
                wmma::store_matrix_sync(C + (size_t)gr * 128 + wn * 32 + j * 16,
                                        acc[i][j], 128, wmma::mem_row_major);
        }
    }

    // fused dots + fp16 mirror
    __syncthreads();
    float4 asv = *(const float4*)(a_s + lane * 4);
    float4 adv = *(const float4*)(a_d + lane * 4);
    #pragma unroll
    for (int rr = 0; rr < 8; rr++) {
        int row = row0 + wid * 8 + rr;
        if (row >= M) break;
        float4 xv = *(const float4*)(C + (size_t)row * 128 + lane * 4);
        store_xwh(row, lane, xv);
        float ps = xv.x * asv.x + xv.y * asv.y + xv.z * asv.z + xv.w * asv.w;
        float pd = xv.x * adv.x + xv.y * adv.y + xv.z * adv.z + xv.w * adv.w;
        ps += __shfl_xor_sync(0xffffffffu, ps, 1);
        ps += __shfl_xor_sync(0xffffffffu, ps, 2);
        ps += __shfl_xor_sync(0xffffffffu, ps, 4);
        pd += __shfl_xor_sync(0xffffffffu, pd, 1);
        pd += __shfl_xor_sync(0xffffffffu, pd, 2);
        pd += __shfl_xor_sync(0xffffffffu, pd, 4);
        if ((lane & 7) == 0) {
            int h = lane >> 3;
            g_es[row * 4 + h] = ps;
            g_ed[row * 4 + h] = pd;
        }
    }
}

// ------------------------- layer-3 GEMM (40 cols) + fused dots --------------
__global__ void gemm40(const float* __restrict__ A, const float* __restrict__ B,
                       const float* __restrict__ a_s, const float* __restrict__ a_d,
                       float* __restrict__ C, int M) {
    __shared__ float Ws[128 * 40];
    for (int i = threadIdx.x; i < 128 * 40; i += blockDim.x) Ws[i] = B[i];
    __syncthreads();
    int row  = blockIdx.x * 8 + (threadIdx.x >> 5);
    int lane = threadIdx.x & 31;
    if (row >= M) return;
    const float* a = A + (size_t)row * 128;
    float acc1 = 0.f, acc2 = 0.f;
    #pragma unroll 8
    for (int k = 0; k < 128; k++) {
        float av = __ldg(a + k);
        acc1 += av * Ws[k * 40 + lane];
        if (lane < 8) acc2 += av * Ws[k * 40 + 32 + lane];
    }
    C[(size_t)row * 40 + lane] = acc1;
    if (lane < 8) C[(size_t)row * 40 + 32 + lane] = acc2;
    float ps = acc1 * a_s[lane] + ((lane < 8) ? acc2 * a_s[32 + lane] : 0.f);
    float pd = acc1 * a_d[lane] + ((lane < 8) ? acc2 * a_d[32 + lane] : 0.f);
    #pragma unroll
    for (int o = 16; o; o >>= 1) {
        ps += __shfl_xor_sync(0xffffffffu, ps, o);
        pd += __shfl_xor_sync(0xffffffffu, pd, o);
    }
    if (lane == 0) { g_es[row] = ps; g_ed[row] = pd; }
}

// ------------------------- fused GAT agg (fp16 gather) ----------------------
__global__ void agg128(const float* __restrict__ bias,
                       const float* __restrict__ gam, const float* __restrict__ bet,
                       const float* __restrict__ mean, const float* __restrict__ var,
                       const float* __restrict__ res, float* __restrict__ out, int n) {
    int node = blockIdx.x * 8 + (threadIdx.x >> 5);
    if (node >= n) return;
    int lane = threadIdx.x & 31;
    int head = lane >> 3, esub = lane & 7;
    float ed = g_ed[node * 4 + head];
    int s = g_off[node], e = g_off[node + 1];

    float m = -1e30f, den = 0.f;
    for (int base = s; base < e; base += 8) {
        int i = base + esub;
        bool val = i < e;
        int u = val ? g_csr[i] : 0;
        float ev = g_es[u * 4 + head] + ed;
        ev = ev > 0.f ? ev : 0.2f * ev;
        if (!val) ev = -1e30f;
        float gm = ev;
        gm = fmaxf(gm, __shfl_xor_sync(0xffffffffu, gm, 1));
        gm = fmaxf(gm, __shfl_xor_sync(0xffffffffu, gm, 2));
        gm = fmaxf(gm, __shfl_xor_sync(0xffffffffu, gm, 4));
        float nm = fmaxf(m, gm);
        float w = __expf(ev - nm);
        w += __shfl_xor_sync(0xffffffffu, w, 1);
        w += __shfl_xor_sync(0xffffffffu, w, 2);
        w += __shfl_xor_sync(0xffffffffu, w, 4);
        den = den * __expf(m - nm) + w;
        m = nm;
    }
    float rinv = 1.f / den;

    // pass 2: weighted gather on fp16 xw rows (256B per row per warp)
    float4 acc = make_float4(0.f, 0.f, 0.f, 0.f);
    int u = g_csr[s];
    for (int i = s; i < e; i++) {
        int un = g_csr[i + 1];
        float ev = g_es[u * 4 + head] + ed;
        ev = ev > 0.f ? ev : 0.2f * ev;
        float w = __expf(ev - m);
        uint2 pv = *(const uint2*)(g_xwh + (size_t)u * 128 + lane * 4);
        float2 f0 = __half22float2(*(__half2*)&pv.x);
        float2 f1 = __half22float2(*(__half2*)&pv.y);
        acc.x += w * f0.x; acc.y += w * f0.y;
        acc.z += w * f1.x; acc.w += w * f1.y;
        u = un;
    }

    int c = lane * 4;
    float4 b4 = *(const float4*)(bias + c);
    float4 g4 = *(const float4*)(gam + c);
    float4 e4 = *(const float4*)(bet + c);
    float4 m4 = *(const float4*)(mean + c);
    float4 v4 = *(const float4*)(var + c);
    float4 r4 = *(const float4*)(res + (size_t)node * 128 + c);
    float o0 = (acc.x * rinv + b4.x - m4.x) * rsqrtf(v4.x + GAT_EPS) * g4.x + e4.x + r4.x;
    float o1 = (acc.y * rinv + b4.y - m4.y) * rsqrtf(v4.y + GAT_EPS) * g4.y + e4.y + r4.y;
    float o2 = (acc.z * rinv + b4.z - m4.z) * rsqrtf(v4.z + GAT_EPS) * g4.z + e4.z + r4.z;
    float o3 = (acc.w * rinv + b4.w - m4.w) * rsqrtf(v4.w + GAT_EPS) * g4.w + e4.w + r4.w;
    float4 o = make_float4(o0 > 0.f ? o0 : expm1f(o0),
                           o1 > 0.f ? o1 : expm1f(o1),
                           o2 > 0.f ? o2 : expm1f(o2),
                           o3 > 0.f ? o3 : expm1f(o3));
    *(float4*)(out + (size_t)node * 128 + c) = o;
}

// ------------------------- layer-3 agg (fp32, two-pass) ---------------------
__global__ void agg40(const float* __restrict__ xw, const float* __restrict__ bias,
                      float* __restrict__ out, int n) {
    int node = blockIdx.x * 8 + (threadIdx.x >> 5);
    if (node >= n) return;
    int lane = threadIdx.x & 31;
    float ed = g_ed[node];
    int s = g_off[node], e = g_off[node + 1];

    float m = -1e30f, den = 0.f;
    for (int base = s; base < e; base += 32) {
        int i = base + lane;
        bool val = i < e;
        int u = val ? g_csr[i] : 0;
        float ev = g_es[u] + ed;
        ev = ev > 0.f ? ev : 0.2f * ev;
        if (!val) ev = -1e30f;
        float gm = ev;
        #pragma unroll
        for (int o = 16; o; o >>= 1) gm = fmaxf(gm, __shfl_xor_sync(0xffffffffu, gm, o));
        float nm = fmaxf(m, gm);
        float w = __expf(ev - nm);
        #pragma unroll
        for (int o = 16; o; o >>= 1) w += __shfl_xor_sync(0xffffffffu, w, o);
        den = den * __expf(m - nm) + w;
        m = nm;
    }
    float rinv = 1.f / den;

    float a1 = 0.f, a2 = 0.f;
    int u = g_csr[s];
    for (int i = s; i < e; i++) {
        int un = g_csr[i + 1];
        float ev = g_es[u] + ed;
        ev = ev > 0.f ? ev : 0.2f * ev;
        float w = __expf(ev - m);
        a1 += w * xw[(size_t)u * 40 + lane];
        if (lane < 8) a2 += w * xw[(size_t)u * 40 + 32 + lane];
        u = un;
    }
    out[(size_t)node * 40 + lane] = a1 * rinv + bias[lane];
    if (lane < 8) out[(size_t)node * 40 + 32 + lane] = a2 * rinv + bias[32 + lane];
}

// ------------------------- launch ------------------------------------------
extern "C" void kernel_launch(void* const* d_in, const int* in_sizes, int n_in,
                              void* d_out, int out_size) {
    const float* x    = (const float*)d_in[0];
    const int*   ei   = (const int*)  d_in[1];
    const float* W1   = (const float*)d_in[2];
    const float* as1  = (const float*)d_in[3];
    const float* ad1  = (const float*)d_in[4];
    const float* b1   = (const float*)d_in[5];
    const float* W2   = (const float*)d_in[6];
    const float* as2  = (const float*)d_in[7];
    const float* ad2  = (const float*)d_in[8];
    const float* b2   = (const float*)d_in[9];
    const float* W3   = (const float*)d_in[10];
    const float* as3  = (const float*)d_in[11];
    const float* ad3  = (const float*)d_in[12];
    const float* b3   = (const float*)d_in[13];
    const float* Wres = (const float*)d_in[14];
    const float* g1   = (const float*)d_in[15];
    const float* be1  = (const float*)d_in[16];
    const float* m1   = (const float*)d_in[17];
    const float* v1   = (const float*)d_in[18];
    const float* g2   = (const float*)d_in[19];
    const float* be2  = (const float*)d_in[20];
    const float* m2   = (const float*)d_in[21];
    const float* v2   = (const float*)d_in[22];

    int n = in_sizes[0] / 128;
    int E = in_sizes[1] / 2;
    const int* src = ei;
    const int* dst = ei + E;
    int tot = E + n;
    int nblk = (n + 1023) / 1024;

    float *p_xw, *p_aux, *p_h1, *p_h2;
    cudaGetSymbolAddress((void**)&p_xw,  g_xw);
    cudaGetSymbolAddress((void**)&p_aux, g_aux);
    cudaGetSymbolAddress((void**)&p_h1,  g_h1);
    cudaGetSymbolAddress((void**)&p_h2,  g_h2);

    cudaFuncSetAttribute(hgemm_dual, cudaFuncAttributeMaxDynamicSharedMemorySize, SM_DUAL);
    cudaFuncSetAttribute(hgemm128,   cudaFuncAttributeMaxDynamicSharedMemorySize, SM_SNGL);

    int nb_gemm = (n + 127) / 128;
    int nb_warp = (n + 7) / 8;

    preB_zcnt <<<196, 256>>>(W1, Wres, W2, n);                             // 1
    histo_kernel <<<(tot + 255) / 256, 256>>>(dst, E, n);                  // 2
    scan1_kernel <<<nblk, 256>>>(n);                                       // 3
    hgemm_dual <<<nb_gemm, 512, SM_DUAL>>>(x, p_xw, p_aux, n, 0, 16384, as1, ad1); // 4 (profiled)
    scan23_kernel <<<(n + 255) / 256, 256>>>(nblk, n);                     // 5
    scatter_kernel <<<(tot + 255) / 256, 256>>>(src, dst, E, n);           // 6

    // ---- layer 1 aggregation ----
    agg128 <<<nb_warp, 256>>>(b1, g1, be1, m1, v1, p_aux, p_h1, n);        // 7

    // ---- layer 2 ----
    hgemm128 <<<nb_gemm, 512, SM_SNGL>>>(p_h1, p_xw, n, 32768, as2, ad2);  // 8
    agg128 <<<nb_warp, 256>>>(b2, g2, be2, m2, v2, p_h1, p_h2, n);         // 9

    // ---- layer 3 ----
    gemm40 <<<nb_warp, 256>>>(p_h2, W3, as3, ad3, p_aux, n);               // 10
    agg40  <<<nb_warp, 256>>>(p_aux, b3, (float*)d_out, n);                // 11
}

// round 12
// speedup vs baseline: 1.1362x; 1.0884x over previous
#include <cuda_runtime.h>
#include <cuda_fp16.h>
#include <mma.h>
using namespace nvcuda;

// Problem constants
#define MAXN 50000
#define MAXE 400000
#define MAXTOT (MAXN + MAXE)
#define GAT_EPS 1e-5f

// ------------------------- scratch (device globals) ------------------------
__device__ float g_aux [MAXN * 128];
__device__ float g_h1  [MAXN * 128];
__device__ float g_h2  [MAXN * 128];
__device__ float g_xw3 [MAXN * 40];
__device__ float g_es  [MAXN * 4];
__device__ float g_ed  [MAXN * 4];
__device__ int   g_cnt [MAXN];
__device__ int   g_off [MAXN + 1];
__device__ int   g_cur [MAXN];
__device__ int   g_csr [MAXTOT + 8];
__device__ int   g_bsum[64];
__device__ __align__(16) __half g_Bh[3 * 16384];
__device__ __align__(16) __half g_xwh[MAXN * 128];   // fp16 gather operand

// ------------------------- preB (hi plane only) + zcnt ----------------------
__global__ void preB_zcnt(const float* __restrict__ W1, const float* __restrict__ Wres,
                          const float* __restrict__ W2, int n) {
    int i = blockIdx.x * blockDim.x + threadIdx.x;
    if (i < n) g_cnt[i] = 0;
    if (i >= 3 * 16384) return;
    const float* W = (i < 16384) ? W1 : (i < 32768 ? Wres : W2);
    g_Bh[i] = __float2half_rn(W[i & 16383]);
}

__global__ void histo_kernel(const int* __restrict__ dst, int E, int n) {
    int i = blockIdx.x * blockDim.x + threadIdx.x;
    if (i >= E + n) return;
    int dd = (i < E) ? dst[i] : (i - E);
    atomicAdd(&g_cnt[dd], 1);
}

__global__ void scan1_kernel(int n) {
    __shared__ int wsum[8];
    int tid = threadIdx.x;
    int base = blockIdx.x * 1024 + tid * 4;
    int c0 = (base + 0 < n) ? g_cnt[base + 0] : 0;
    int c1 = (base + 1 < n) ? g_cnt[base + 1] : 0;
    int c2 = (base + 2 < n) ? g_cnt[base + 2] : 0;
    int c3 = (base + 3 < n) ? g_cnt[base + 3] : 0;
    int t = c0 + c1 + c2 + c3;
    int lane = tid & 31, wid = tid >> 5;
    int incl = t;
    #pragma unroll
    for (int o = 1; o < 32; o <<= 1) {
        int v = __shfl_up_sync(0xffffffffu, incl, o);
        if (lane >= o) incl += v;
    }
    if (lane == 31) wsum[wid] = incl;
    __syncthreads();
    if (tid == 0) {
        int r = 0;
        #pragma unroll
        for (int k = 0; k < 8; k++) { int v = wsum[k]; wsum[k] = r; r += v; }
        g_bsum[blockIdx.x] = r;
    }
    __syncthreads();
    int run = wsum[wid] + incl - t;
    if (base + 0 < n) g_off[base + 0] = run; run += c0;
    if (base + 1 < n) g_off[base + 1] = run; run += c1;
    if (base + 2 < n) g_off[base + 2] = run; run += c2;
    if (base + 3 < n) g_off[base + 3] = run;
}

__global__ void scan23_kernel(int nb, int n) {
    __shared__ int sboff[64];
    __shared__ int sgrand;
    int tid = threadIdx.x;
    if (tid < 32) {
        int lane = tid;
        int v0 = (lane < nb) ? g_bsum[lane] : 0;
        int v1 = (32 + lane < nb) ? g_bsum[32 + lane] : 0;
        int i0 = v0;
        #pragma unroll
        for (int o = 1; o < 32; o <<= 1) {
            int q = __shfl_up_sync(0xffffffffu, i0, o);
            if (lane >= o) i0 += q;
        }
        int tot0 = __shfl_sync(0xffffffffu, i0, 31);
        int i1 = v1;
        #pragma unroll
        for (int o = 1; o < 32; o <<= 1) {
            int q = __shfl_up_sync(0xffffffffu, i1, o);
            if (lane >= o) i1 += q;
        }
        i1 += tot0;
        sboff[lane] = i0 - v0;
        sboff[32 + lane] = i1 - v1;
        if (lane == 31) sgrand = i1;
    }
    __syncthreads();
    int i = blockIdx.x * blockDim.x + tid;
    if (i < n) {
        int o = g_off[i] + sboff[i >> 10];
        g_off[i] = o;
        g_cur[i] = o;
    }
    if (blockIdx.x == 0 && tid == 0) g_off[n] = sgrand;
}

__global__ void scatter_kernel(const int* __restrict__ src, const int* __restrict__ dst,
                               int E, int n) {
    int i = blockIdx.x * blockDim.x + threadIdx.x;
    if (i >= E + n) return;
    int ss, dd;
    if (i < E) { ss = src[i]; dd = dst[i]; }
    else       { ss = dd = i - E; }
    int p = atomicAdd(&g_cur[dd], 1);
    g_csr[p] = ss;
}

// ------------------------- GEMM helpers -------------------------------------
#define LDAH 136
#define LDBH 272
#define LDBS 136
#define LDC  132
#define SM_DUAL ((128 * LDBH + 2 * 128 * LDAH) * 2)   // 139264 B
#define SM_SNGL ((128 * LDBS + 2 * 128 * LDAH) * 2)   // 104448 B

__device__ __forceinline__ void cp16(__half* dst, const __half* src) {
    unsigned d = (unsigned)__cvta_generic_to_shared(dst);
    asm volatile("cp.async.cg.shared.global [%0], [%1], 16;\n" :: "r"(d), "l"(src));
}

__device__ __forceinline__ void store_xwh(int row, int lane, float4 xv) {
    __half2 ha = __floats2half2_rn(xv.x, xv.y);
    __half2 hb = __floats2half2_rn(xv.z, xv.w);
    uint2 p = make_uint2(*(unsigned*)&ha, *(unsigned*)&hb);
    *(uint2*)(g_xwh + (size_t)row * 128 + lane * 4) = p;
}

// dots from SMEM C tile + fp16 mirror; 16 warps x 8 rows
__device__ __forceinline__ void dots_epilogue(const float* Cs, int row0, int M,
                                              int wid, int lane,
                                              const float* a_s, const float* a_d) {
    float4 asv = *(const float4*)(a_s + lane * 4);
    float4 adv = *(const float4*)(a_d + lane * 4);
    #pragma unroll
    for (int rr = 0; rr < 8; rr++) {
        int r = wid * 8 + rr;
        int row = row0 + r;
        if (row >= M) break;
        float4 xv = *(const float4*)(Cs + (size_t)r * LDC + lane * 4);
        store_xwh(row, lane, xv);
        float ps = xv.x * asv.x + xv.y * asv.y + xv.z * asv.z + xv.w * asv.w;
        float pd = xv.x * adv.x + xv.y * adv.y + xv.z * adv.z + xv.w * adv.w;
        ps += __shfl_xor_sync(0xffffffffu, ps, 1);
        ps += __shfl_xor_sync(0xffffffffu, ps, 2);
        ps += __shfl_xor_sync(0xffffffffu, ps, 4);
        pd += __shfl_xor_sync(0xffffffffu, pd, 1);
        pd += __shfl_xor_sync(0xffffffffu, pd, 2);
        pd += __shfl_xor_sync(0xffffffffu, pd, 4);
        if ((lane & 7) == 0) {
            int h = lane >> 3;
            g_es[row * 4 + h] = ps;
            g_ed[row * 4 + h] = pd;
        }
    }
}

// ------------------------- dual WMMA GEMM (layer 1), x2 split ---------------
// xw path -> SMEM + fp16; aux path -> fp32 global.
__global__ void __launch_bounds__(512, 1)
hgemm_dual(const float* __restrict__ A, float* __restrict__ C2,
           int M, int boff1, int boff2,
           const float* __restrict__ a_s, const float* __restrict__ a_d) {
    extern __shared__ __half sm[];
    __half* sBh = sm;
    __half* sAh = sBh + 128 * LDBH;
    __half* sAl = sAh + 128 * LDAH;
    int tid = threadIdx.x;
    int wid = tid >> 5, lane = tid & 31;
    int wm = wid & 3, wn = wid >> 2;
    int mi = wn >> 1, nsub = wn & 1;
    int row0 = blockIdx.x * 128;

    // B (hi only): 4096 16B chunks
    #pragma unroll
    for (int it = 0; it < 8; it++) {
        int idx = tid + it * 512;
        int c4 = idx & 15, row = (idx >> 4) & 127, mat = idx >> 11;
        const __half* src = g_Bh + (mat ? boff2 : boff1) + row * 128 + c4 * 8;
        __half* dst = sBh + row * LDBH + mat * 128 + c4 * 8;
        cp16(dst, src);
    }
    asm volatile("cp.async.commit_group;\n");

    #pragma unroll
    for (int it = 0; it < 16; it++) {
        int idx = tid + it * 512;
        int c2 = idx & 63, r = idx >> 6;
        int gr = row0 + r;
        float2 v = make_float2(0.f, 0.f);
        if (gr < M) v = *(const float2*)(A + (size_t)gr * 128 + c2 * 2);
        __half hx = __float2half_rn(v.x), hy = __float2half_rn(v.y);
        *(__half2*)(sAh + r * LDAH + c2 * 2) = __halves2half2(hx, hy);
        *(__half2*)(sAl + r * LDAH + c2 * 2) =
            __halves2half2(__float2half_rn(v.x - __half2float(hx)),
                           __float2half_rn(v.y - __half2float(hy)));
    }
    asm volatile("cp.async.wait_group 0;\n");
    __syncthreads();

    wmma::fragment<wmma::accumulator, 16, 16, 16, float> acc[2][4];
    #pragma unroll
    for (int i = 0; i < 2; i++)
        #pragma unroll
        for (int j = 0; j < 4; j++)
            wmma::fill_fragment(acc[i][j], 0.f);

    #pragma unroll
    for (int kk = 0; kk < 8; kk++) {
        wmma::fragment<wmma::matrix_a, 16, 16, 16, __half, wmma::row_major> ah[2], al[2];
        #pragma unroll
        for (int i = 0; i < 2; i++) {
            wmma::load_matrix_sync(ah[i], sAh + (wm * 32 + i * 16) * LDAH + kk * 16, LDAH);
            wmma::load_matrix_sync(al[i], sAl + (wm * 32 + i * 16) * LDAH + kk * 16, LDAH);
        }
        #pragma unroll
        for (int j = 0; j < 4; j++) {
            wmma::fragment<wmma::matrix_b, 16, 16, 16, __half, wmma::row_major> bh;
            wmma::load_matrix_sync(bh, sBh + kk * 16 * LDBH + mi * 128 + nsub * 64 + j * 16, LDBH);
            #pragma unroll
            for (int i = 0; i < 2; i++) {
                wmma::mma_sync(acc[i][j], ah[i], bh, acc[i][j]);
                wmma::mma_sync(acc[i][j], al[i], bh, acc[i][j]);
            }
        }
    }

    __syncthreads();                 // all reads of sB/sA done; reuse as Cs
    float* Cs = (float*)sm;          // 128 x LDC fp32 (67.6KB < 139KB)
    #pragma unroll
    for (int i = 0; i < 2; i++) {
        int r = wm * 32 + i * 16;
        int gr = row0 + r;
        if (mi == 0) {
            #pragma unroll
            for (int j = 0; j < 4; j++)
                wmma::store_matrix_sync(Cs + (size_t)r * LDC + nsub * 64 + j * 16,
                                        acc[i][j], LDC, wmma::mem_row_major);
        } else if (gr < M) {
            #pragma unroll
            for (int j = 0; j < 4; j++)
                wmma::store_matrix_sync(C2 + (size_t)gr * 128 + nsub * 64 + j * 16,
                                        acc[i][j], 128, wmma::mem_row_major);
        }
    }
    __syncthreads();
    dots_epilogue(Cs, row0, M, wid, lane, a_s, a_d);
}

// ------------------------- single WMMA GEMM (layer 2), x2 split -------------
__global__ void __launch_bounds__(512, 1)
hgemm128(const float* __restrict__ A, int M, int boff,
         const float* __restrict__ a_s, const float* __restrict__ a_d) {
    extern __shared__ __half sm[];
    __half* sBh = sm;
    __half* sAh = sBh + 128 * LDBS;
    __half* sAl = sAh + 128 * LDAH;
    int tid = threadIdx.x;
    int wid = tid >> 5, lane = tid & 31;
    int wm = wid & 3, wn = wid >> 2;
    int row0 = blockIdx.x * 128;

    // B (hi only): 2048 16B chunks
    #pragma unroll
    for (int it = 0; it < 4; it++) {
        int idx = tid + it * 512;
        int c4 = idx & 15, row = idx >> 4;
        cp16(sBh + row * LDBS + c4 * 8, g_Bh + boff + row * 128 + c4 * 8);
    }
    asm volatile("cp.async.commit_group;\n");

    #pragma unroll
    for (int it = 0; it < 16; it++) {
        int idx = tid + it * 512;
        int c2 = idx & 63, r = idx >> 6;
        int gr = row0 + r;
        float2 v = make_float2(0.f, 0.f);
        if (gr < M) v = *(const float2*)(A + (size_t)gr * 128 + c2 * 2);
        __half hx = __float2half_rn(v.x), hy = __float2half_rn(v.y);
        *(__half2*)(sAh + r * LDAH + c2 * 2) = __halves2half2(hx, hy);
        *(__half2*)(sAl + r * LDAH + c2 * 2) =
            __halves2half2(__float2half_rn(v.x - __half2float(hx)),
                           __float2half_rn(v.y - __half2float(hy)));
    }
    asm volatile("cp.async.wait_group 0;\n");
    __syncthreads();

    wmma::fragment<wmma::accumulator, 16, 16, 16, float> acc[2][2];
    #pragma unroll
    for (int i = 0; i < 2; i++)
        #pragma unroll
        for (int j = 0; j < 2; j++)
            wmma::fill_fragment(acc[i][j], 0.f);

    #pragma unroll
    for (int kk = 0; kk < 8; kk++) {
        wmma::fragment<wmma::matrix_a, 16, 16, 16, __half, wmma::row_major> ah[2], al[2];
        #pragma unroll
        for (int i = 0; i < 2; i++) {
            wmma::load_matrix_sync(ah[i], sAh + (wm * 32 + i * 16) * LDAH + kk * 16, LDAH);
            wmma::load_matrix_sync(al[i], sAl + (wm * 32 + i * 16) * LDAH + kk * 16, LDAH);
        }
        #pragma unroll
        for (int j = 0; j < 2; j++) {
            wmma::fragment<wmma::matrix_b, 16, 16, 16, __half, wmma::row_major> bh;
            wmma::load_matrix_sync(bh, sBh + kk * 16 * LDBS + wn * 32 + j * 16, LDBS);
            #pragma unroll
            for (int i = 0; i < 2; i++) {
                wmma::mma_sync(acc[i][j], ah[i], bh, acc[i][j]);
                wmma::mma_sync(acc[i][j], al[i], bh, acc[i][j]);
            }
        }
    }

    __syncthreads();
    float* Cs = (float*)sm;          // 67.6KB < 104.4KB
    #pragma unroll
    for (int i = 0; i < 2; i++) {
        int r = wm * 32 + i * 16;
        #pragma unroll
        for (int j = 0; j < 2; j++)
            wmma::store_matrix_sync(Cs + (size_t)r * LDC + wn * 32 + j * 16,
                                    acc[i][j], LDC, wmma::mem_row_major);
    }
    __syncthreads();
    dots_epilogue(Cs, row0, M, wid, lane, a_s, a_d);
}

// ------------------------- layer-3 GEMM (40 cols) + fused dots --------------
__global__ void gemm40(const float* __restrict__ A, const float* __restrict__ B,
                       const float* __restrict__ a_s, const float* __restrict__ a_d,
                       float* __restrict__ C, int M) {
    __shared__ float Ws[128 * 40];
    for (int i = threadIdx.x; i < 128 * 40; i += blockDim.x) Ws[i] = B[i];
    __syncthreads();
    int row  = blockIdx.x * 8 + (threadIdx.x >> 5);
    int lane = threadIdx.x & 31;
    if (row >= M) return;
    const float* a = A + (size_t)row * 128;
    float acc1 = 0.f, acc2 = 0.f;
    #pragma unroll 8
    for (int k = 0; k < 128; k++) {
        float av = __ldg(a + k);
        acc1 += av * Ws[k * 40 + lane];
        if (lane < 8) acc2 += av * Ws[k * 40 + 32 + lane];
    }
    C[(size_t)row * 40 + lane] = acc1;
    if (lane < 8) C[(size_t)row * 40 + 32 + lane] = acc2;
    float ps = acc1 * a_s[lane] + ((lane < 8) ? acc2 * a_s[32 + lane] : 0.f);
    float pd = acc1 * a_d[lane] + ((lane < 8) ? acc2 * a_d[32 + lane] : 0.f);
    #pragma unroll
    for (int o = 16; o; o >>= 1) {
        ps += __shfl_xor_sync(0xffffffffu, ps, o);
        pd += __shfl_xor_sync(0xffffffffu, pd, o);
    }
    if (lane == 0) { g_es[row] = ps; g_ed[row] = pd; }
}

// ------------------------- fused GAT agg (fp16 gather) ----------------------
__global__ void agg128(const float* __restrict__ bias,
                       const float* __restrict__ gam, const float* __restrict__ bet,
                       const float* __restrict__ mean, const float* __restrict__ var,
                       const float* __restrict__ res, float* __restrict__ out, int n) {
    int node = blockIdx.x * 8 + (threadIdx.x >> 5);
    if (node >= n) return;
    int lane = threadIdx.x & 31;
    int head = lane >> 3, esub = lane & 7;
    float ed = g_ed[node * 4 + head];
    int s = g_off[node], e = g_off[node + 1];

    float m = -1e30f, den = 0.f;
    for (int base = s; base < e; base += 8) {
        int i = base + esub;
        bool val = i < e;
        int u = val ? g_csr[i] : 0;
        float ev = g_es[u * 4 + head] + ed;
        ev = ev > 0.f ? ev : 0.2f * ev;
        if (!val) ev = -1e30f;
        float gm = ev;
        gm = fmaxf(gm, __shfl_xor_sync(0xffffffffu, gm, 1));
        gm = fmaxf(gm, __shfl_xor_sync(0xffffffffu, gm, 2));
        gm = fmaxf(gm, __shfl_xor_sync(0xffffffffu, gm, 4));
        float nm = fmaxf(m, gm);
        float w = __expf(ev - nm);
        w += __shfl_xor_sync(0xffffffffu, w, 1);
        w += __shfl_xor_sync(0xffffffffu, w, 2);
        w += __shfl_xor_sync(0xffffffffu, w, 4);
        den = den * __expf(m - nm) + w;
        m = nm;
    }
    float rinv = 1.f / den;

    float4 acc = make_float4(0.f, 0.f, 0.f, 0.f);
    int u = g_csr[s];
    for (int i = s; i < e; i++) {
        int un = g_csr[i + 1];
        float ev = g_es[u * 4 + head] + ed;
        ev = ev > 0.f ? ev : 0.2f * ev;
        float w = __expf(ev - m);
        uint2 pv = *(const uint2*)(g_xwh + (size_t)u * 128 + lane * 4);
        float2 f0 = __half22float2(*(__half2*)&pv.x);
        float2 f1 = __half22float2(*(__half2*)&pv.y);
        acc.x += w * f0.x; acc.y += w * f0.y;
        acc.z += w * f1.x; acc.w += w * f1.y;
        u = un;
    }

    int c = lane * 4;
    float4 b4 = *(const float4*)(bias + c);
    float4 g4 = *(const float4*)(gam + c);
    float4 e4 = *(const float4*)(bet + c);
    float4 m4 = *(const float4*)(mean + c);
    float4 v4 = *(const float4*)(var + c);
    float4 r4 = *(const float4*)(res + (size_t)node * 128 + c);
    float o0 = (acc.x * rinv + b4.x - m4.x) * rsqrtf(v4.x + GAT_EPS) * g4.x + e4.x + r4.x;
    float o1 = (acc.y * rinv + b4.y - m4.y) * rsqrtf(v4.y + GAT_EPS) * g4.y + e4.y + r4.y;
    float o2 = (acc.z * rinv + b4.z - m4.z) * rsqrtf(v4.z + GAT_EPS) * g4.z + e4.z + r4.z;
    float o3 = (acc.w * rinv + b4.w - m4.w) * rsqrtf(v4.w + GAT_EPS) * g4.w + e4.w + r4.w;
    float4 o = make_float4(o0 > 0.f ? o0 : expm1f(o0),
                           o1 > 0.f ? o1 : expm1f(o1),
                           o2 > 0.f ? o2 : expm1f(o2),
                           o3 > 0.f ? o3 : expm1f(o3));
    *(float4*)(out + (size_t)node * 128 + c) = o;
}

// ------------------------- layer-3 agg (fp32, two-pass) ---------------------
__global__ void agg40(const float* __restrict__ xw, const float* __restrict__ bias,
                      float* __restrict__ out, int n) {
    int node = blockIdx.x * 8 + (threadIdx.x >> 5);
    if (node >= n) return;
    int lane = threadIdx.x & 31;
    float ed = g_ed[node];
    int s = g_off[node], e = g_off[node + 1];

    float m = -1e30f, den = 0.f;
    for (int base = s; base < e; base += 32) {
        int i = base + lane;
        bool val = i < e;
        int u = val ? g_csr[i] : 0;
        float ev = g_es[u] + ed;
        ev = ev > 0.f ? ev : 0.2f * ev;
        if (!val) ev = -1e30f;
        float gm = ev;
        #pragma unroll
        for (int o = 16; o; o >>= 1) gm = fmaxf(gm, __shfl_xor_sync(0xffffffffu, gm, o));
        float nm = fmaxf(m, gm);
        float w = __expf(ev - nm);
        #pragma unroll
        for (int o = 16; o; o >>= 1) w += __shfl_xor_sync(0xffffffffu, w, o);
        den = den * __expf(m - nm) + w;
        m = nm;
    }
    float rinv = 1.f / den;

    float a1 = 0.f, a2 = 0.f;
    int u = g_csr[s];
    for (int i = s; i < e; i++) {
        int un = g_csr[i + 1];
        float ev = g_es[u] + ed;
        ev = ev > 0.f ? ev : 0.2f * ev;
        float w = __expf(ev - m);
        a1 += w * xw[(size_t)u * 40 + lane];
        if (lane < 8) a2 += w * xw[(size_t)u * 40 + 32 + lane];
        u = un;
    }
    out[(size_t)node * 40 + lane] = a1 * rinv + bias[lane];
    if (lane < 8) out[(size_t)node * 40 + 32 + lane] = a2 * rinv + bias[32 + lane];
}

// ------------------------- launch ------------------------------------------
extern "C" void kernel_launch(void* const* d_in, const int* in_sizes, int n_in,
                              void* d_out, int out_size) {
    const float* x    = (const float*)d_in[0];
    const int*   ei   = (const int*)  d_in[1];
    const float* W1   = (const float*)d_in[2];
    const float* as1  = (const float*)d_in[3];
    const float* ad1  = (const float*)d_in[4];
    const float* b1   = (const float*)d_in[5];
    const float* W2   = (const float*)d_in[6];
    const float* as2  = (const float*)d_in[7];
    const float* ad2  = (const float*)d_in[8];
    const float* b2   = (const float*)d_in[9];
    const float* W3   = (const float*)d_in[10];
    const float* as3  = (const float*)d_in[11];
    const float* ad3  = (const float*)d_in[12];
    const float* b3   = (const float*)d_in[13];
    const float* Wres = (const float*)d_in[14];
    const float* g1   = (const float*)d_in[15];
    const float* be1  = (const float*)d_in[16];
    const float* m1   = (const float*)d_in[17];
    const float* v1   = (const float*)d_in[18];
    const float* g2   = (const float*)d_in[19];
    const float* be2  = (const float*)d_in[20];
    const float* m2   = (const float*)d_in[21];
    const float* v2   = (const float*)d_in[22];

    int n = in_sizes[0] / 128;
    int E = in_sizes[1] / 2;
    const int* src = ei;
    const int* dst = ei + E;
    int tot = E + n;
    int nblk = (n + 1023) / 1024;

    float *p_aux, *p_h1, *p_h2, *p_xw3;
    cudaGetSymbolAddress((void**)&p_aux, g_aux);
    cudaGetSymbolAddress((void**)&p_h1,  g_h1);
    cudaGetSymbolAddress((void**)&p_h2,  g_h2);
    cudaGetSymbolAddress((void**)&p_xw3, g_xw3);

    cudaFuncSetAttribute(hgemm_dual, cudaFuncAttributeMaxDynamicSharedMemorySize, SM_DUAL);
    cudaFuncSetAttribute(hgemm128,   cudaFuncAttributeMaxDynamicSharedMemorySize, SM_SNGL);

    int nb_gemm = (n + 127) / 128;
    int nb_warp = (n + 7) / 8;

    preB_zcnt <<<196, 256>>>(W1, Wres, W2, n);                             // 1
    histo_kernel <<<(tot + 255) / 256, 256>>>(dst, E, n);                  // 2
    scan1_kernel <<<nblk, 256>>>(n);                                       // 3
    hgemm_dual <<<nb_gemm, 512, SM_DUAL>>>(x, p_aux, n, 0, 16384, as1, ad1); // 4 (profiled)
    scan23_kernel <<<(n + 255) / 256, 256>>>(nblk, n);                     // 5
    scatter_kernel <<<(tot + 255) / 256, 256>>>(src, dst, E, n);           // 6

    // ---- layer 1 aggregation ----
    agg128 <<<nb_warp, 256>>>(b1, g1, be1, m1, v1, p_aux, p_h1, n);        // 7

    // ---- layer 2 ----
    hgemm128 <<<nb_gemm, 512, SM_SNGL>>>(p_h1, n, 32768, as2, ad2);        // 8
    agg128 <<<nb_warp, 256>>>(b2, g2, be2, m2, v2, p_h1, p_h2, n);         // 9

    // ---- layer 3 ----
    gemm40 <<<nb_warp, 256>>>(p_h2, W3, as3, ad3, p_xw3, n);               // 10
    agg40  <<<nb_warp, 256>>>(p_xw3, b3, (float*)d_out, n);                // 11
}

// round 13
// speedup vs baseline: 1.5929x; 1.4019x over previous
#include <cuda_runtime.h>
#include <cuda_fp16.h>
#include <mma.h>
using namespace nvcuda;

// Problem constants
#define MAXN 50000
#define MAXE 400000
#define MAXTOT (MAXN + MAXE)
#define GAT_EPS 1e-5f

// ------------------------- scratch (device globals) ------------------------
__device__ float g_aux [MAXN * 128];
__device__ float g_h1  [MAXN * 128];
__device__ float g_h2  [MAXN * 128];
__device__ float g_xw3 [MAXN * 40];
__device__ float g_es  [MAXN * 4];
__device__ float g_ed  [MAXN * 4];
__device__ int   g_cnt [MAXN];
__device__ int   g_off [MAXN + 1];
__device__ int   g_cur [MAXN];
__device__ int   g_csr [MAXTOT + 8];
__device__ int   g_bsum[64];
__device__ __align__(16) __half g_Bh[3 * 16384];
__device__ __align__(16) __half g_B3h[128 * 48];
__device__ __align__(16) __half g_xwh[MAXN * 128];   // fp16 gather operand

// ------------------------- preB (hi planes) + zcnt ---------------------------
__global__ void preB_zcnt(const float* __restrict__ W1, const float* __restrict__ Wres,
                          const float* __restrict__ W2, const float* __restrict__ W3,
                          int n) {
    int i = blockIdx.x * blockDim.x + threadIdx.x;
    if (i < n) g_cnt[i] = 0;
    if (i < 3 * 16384) {
        const float* W = (i < 16384) ? W1 : (i < 32768 ? Wres : W2);
        g_Bh[i] = __float2half_rn(W[i & 16383]);
    } else if (i < 3 * 16384 + 128 * 48) {
        int j = i - 3 * 16384;
        int k = j / 48, nn = j - k * 48;
        g_B3h[j] = (nn < 40) ? __float2half_rn(W3[k * 40 + nn]) : __half(0);
    }
}

__global__ void histo_kernel(const int* __restrict__ dst, int E, int n) {
    int i = blockIdx.x * blockDim.x + threadIdx.x;
    if (i >= E + n) return;
    int dd = (i < E) ? dst[i] : (i - E);
    atomicAdd(&g_cnt[dd], 1);
}

__global__ void scan1_kernel(int n) {
    __shared__ int wsum[8];
    int tid = threadIdx.x;
    int base = blockIdx.x * 1024 + tid * 4;
    int c0 = (base + 0 < n) ? g_cnt[base + 0] : 0;
    int c1 = (base + 1 < n) ? g_cnt[base + 1] : 0;
    int c2 = (base + 2 < n) ? g_cnt[base + 2] : 0;
    int c3 = (base + 3 < n) ? g_cnt[base + 3] : 0;
    int t = c0 + c1 + c2 + c3;
    int lane = tid & 31, wid = tid >> 5;
    int incl = t;
    #pragma unroll
    for (int o = 1; o < 32; o <<= 1) {
        int v = __shfl_up_sync(0xffffffffu, incl, o);
        if (lane >= o) incl += v;
    }
    if (lane == 31) wsum[wid] = incl;
    __syncthreads();
    if (tid == 0) {
        int r = 0;
        #pragma unroll
        for (int k = 0; k < 8; k++) { int v = wsum[k]; wsum[k] = r; r += v; }
        g_bsum[blockIdx.x] = r;
    }
    __syncthreads();
    int run = wsum[wid] + incl - t;
    if (base + 0 < n) g_off[base + 0] = run; run += c0;
    if (base + 1 < n) g_off[base + 1] = run; run += c1;
    if (base + 2 < n) g_off[base + 2] = run; run += c2;
    if (base + 3 < n) g_off[base + 3] = run;
}

__global__ void scan23_kernel(int nb, int n) {
    __shared__ int sboff[64];
    __shared__ int sgrand;
    int tid = threadIdx.x;
    if (tid < 32) {
        int lane = tid;
        int v0 = (lane < nb) ? g_bsum[lane] : 0;
        int v1 = (32 + lane < nb) ? g_bsum[32 + lane] : 0;
        int i0 = v0;
        #pragma unroll
        for (int o = 1; o < 32; o <<= 1) {
            int q = __shfl_up_sync(0xffffffffu, i0, o);
            if (lane >= o) i0 += q;
        }
        int tot0 = __shfl_sync(0xffffffffu, i0, 31);
        int i1 = v1;
        #pragma unroll
        for (int o = 1; o < 32; o <<= 1) {
            int q = __shfl_up_sync(0xffffffffu, i1, o);
            if (lane >= o) i1 += q;
        }
        i1 += tot0;
        sboff[lane] = i0 - v0;
        sboff[32 + lane] = i1 - v1;
        if (lane == 31) sgrand = i1;
    }
    __syncthreads();
    int i = blockIdx.x * blockDim.x + tid;
    if (i < n) {
        int o = g_off[i] + sboff[i >> 10];
        g_off[i] = o;
        g_cur[i] = o;
    }
    if (blockIdx.x == 0 && tid == 0) g_off[n] = sgrand;
}

__global__ void scatter_kernel(const int* __restrict__ src, const int* __restrict__ dst,
                               int E, int n) {
    int i = blockIdx.x * blockDim.x + threadIdx.x;
    if (i >= E + n) return;
    int ss, dd;
    if (i < E) { ss = src[i]; dd = dst[i]; }
    else       { ss = dd = i - E; }
    int p = atomicAdd(&g_cur[dd], 1);
    g_csr[p] = ss;
}

// ------------------------- GEMM helpers -------------------------------------
#define LDAH 136
#define LDBH 272
#define LDBS 136
#define LDC  132
#define LDB3 56
#define LDC3 56
#define SM_DUAL ((128 * LDBH + 2 * 128 * LDAH) * 2)   // 139264 B
#define SM_SNGL ((128 * LDBS + 2 * 128 * LDAH) * 2)   // 104448 B
#define SM_40   ((128 * LDB3 + 2 * 128 * LDAH) * 2)   // 83968 B

__device__ __forceinline__ void cp16(__half* dst, const __half* src) {
    unsigned d = (unsigned)__cvta_generic_to_shared(dst);
    asm volatile("cp.async.cg.shared.global [%0], [%1], 16;\n" :: "r"(d), "l"(src));
}

__device__ __forceinline__ void store_xwh(int row, int lane, float4 xv) {
    __half2 ha = __floats2half2_rn(xv.x, xv.y);
    __half2 hb = __floats2half2_rn(xv.z, xv.w);
    uint2 p = make_uint2(*(unsigned*)&ha, *(unsigned*)&hb);
    *(uint2*)(g_xwh + (size_t)row * 128 + lane * 4) = p;
}

__device__ __forceinline__ void dots_epilogue(const float* Cs, int row0, int M,
                                              int wid, int lane,
                                              const float* a_s, const float* a_d) {
    float4 asv = *(const float4*)(a_s + lane * 4);
    float4 adv = *(const float4*)(a_d + lane * 4);
    #pragma unroll
    for (int rr = 0; rr < 8; rr++) {
        int r = wid * 8 + rr;
        int row = row0 + r;
        if (row >= M) break;
        float4 xv = *(const float4*)(Cs + (size_t)r * LDC + lane * 4);
        store_xwh(row, lane, xv);
        float ps = xv.x * asv.x + xv.y * asv.y + xv.z * asv.z + xv.w * asv.w;
        float pd = xv.x * adv.x + xv.y * adv.y + xv.z * adv.z + xv.w * adv.w;
        ps += __shfl_xor_sync(0xffffffffu, ps, 1);
        ps += __shfl_xor_sync(0xffffffffu, ps, 2);
        ps += __shfl_xor_sync(0xffffffffu, ps, 4);
        pd += __shfl_xor_sync(0xffffffffu, pd, 1);
        pd += __shfl_xor_sync(0xffffffffu, pd, 2);
        pd += __shfl_xor_sync(0xffffffffu, pd, 4);
        if ((lane & 7) == 0) {
            int h = lane >> 3;
            g_es[row * 4 + h] = ps;
            g_ed[row * 4 + h] = pd;
        }
    }
}

// ------------------------- dual WMMA GEMM (layer 1), x2 split ---------------
__global__ void __launch_bounds__(512, 1)
hgemm_dual(const float* __restrict__ A, float* __restrict__ C2,
           int M, int boff1, int boff2,
           const float* __restrict__ a_s, const float* __restrict__ a_d) {
    extern __shared__ __half sm[];
    __half* sBh = sm;
    __half* sAh = sBh + 128 * LDBH;
    __half* sAl = sAh + 128 * LDAH;
    int tid = threadIdx.x;
    int wid = tid >> 5, lane = tid & 31;
    int wm = wid & 3, wn = wid >> 2;
    int mi = wn >> 1, nsub = wn & 1;
    int row0 = blockIdx.x * 128;

    #pragma unroll
    for (int it = 0; it < 8; it++) {
        int idx = tid + it * 512;
        int c4 = idx & 15, row = (idx >> 4) & 127, mat = idx >> 11;
        const __half* src = g_Bh + (mat ? boff2 : boff1) + row * 128 + c4 * 8;
        __half* dst = sBh + row * LDBH + mat * 128 + c4 * 8;
        cp16(dst, src);
    }
    asm volatile("cp.async.commit_group;\n");

    #pragma unroll
    for (int it = 0; it < 16; it++) {
        int idx = tid + it * 512;
        int c2 = idx & 63, r = idx >> 6;
        int gr = row0 + r;
        float2 v = make_float2(0.f, 0.f);
        if (gr < M) v = *(const float2*)(A + (size_t)gr * 128 + c2 * 2);
        __half hx = __float2half_rn(v.x), hy = __float2half_rn(v.y);
        *(__half2*)(sAh + r * LDAH + c2 * 2) = __halves2half2(hx, hy);
        *(__half2*)(sAl + r * LDAH + c2 * 2) =
            __halves2half2(__float2half_rn(v.x - __half2float(hx)),
                           __float2half_rn(v.y - __half2float(hy)));
    }
    asm volatile("cp.async.wait_group 0;\n");
    __syncthreads();

    wmma::fragment<wmma::accumulator, 16, 16, 16, float> acc[2][4];
    #pragma unroll
    for (int i = 0; i < 2; i++)
        #pragma unroll
        for (int j = 0; j < 4; j++)
            wmma::fill_fragment(acc[i][j], 0.f);

    #pragma unroll
    for (int kk = 0; kk < 8; kk++) {
        wmma::fragment<wmma::matrix_a, 16, 16, 16, __half, wmma::row_major> ah[2], al[2];
        #pragma unroll
        for (int i = 0; i < 2; i++) {
            wmma::load_matrix_sync(ah[i], sAh + (wm * 32 + i * 16) * LDAH + kk * 16, LDAH);
            wmma::load_matrix_sync(al[i], sAl + (wm * 32 + i * 16) * LDAH + kk * 16, LDAH);
        }
        #pragma unroll
        for (int j = 0; j < 4; j++) {
            wmma::fragment<wmma::matrix_b, 16, 16, 16, __half, wmma::row_major> bh;
            wmma::load_matrix_sync(bh, sBh + kk * 16 * LDBH + mi * 128 + nsub * 64 + j * 16, LDBH);
            #pragma unroll
            for (int i = 0; i < 2; i++) {
                wmma::mma_sync(acc[i][j], ah[i], bh, acc[i][j]);
                wmma::mma_sync(acc[i][j], al[i], bh, acc[i][j]);
            }
        }
    }

    __syncthreads();
    float* Cs = (float*)sm;
    #pragma unroll
    for (int i = 0; i < 2; i++) {
        int r = wm * 32 + i * 16;
        int gr = row0 + r;
        if (mi == 0) {
            #pragma unroll
            for (int j = 0; j < 4; j++)
                wmma::store_matrix_sync(Cs + (size_t)r * LDC + nsub * 64 + j * 16,
                                        acc[i][j], LDC, wmma::mem_row_major);
        } else if (gr < M) {
            #pragma unroll
            for (int j = 0; j < 4; j++)
                wmma::store_matrix_sync(C2 + (size_t)gr * 128 + nsub * 64 + j * 16,
                                        acc[i][j], 128, wmma::mem_row_major);
        }
    }
    __syncthreads();
    dots_epilogue(Cs, row0, M, wid, lane, a_s, a_d);
}

// ------------------------- single WMMA GEMM (layer 2), x2 split -------------
__global__ void __launch_bounds__(512, 1)
hgemm128(const float* __restrict__ A, int M, int boff,
         const float* __restrict__ a_s, const float* __restrict__ a_d) {
    extern __shared__ __half sm[];
    __half* sBh = sm;
    __half* sAh = sBh + 128 * LDBS;
    __half* sAl = sAh + 128 * LDAH;
    int tid = threadIdx.x;
    int wid = tid >> 5, lane = tid & 31;
    int wm = wid & 3, wn = wid >> 2;
    int row0 = blockIdx.x * 128;

    #pragma unroll
    for (int it = 0; it < 4; it++) {
        int idx = tid + it * 512;
        int c4 = idx & 15, row = idx >> 4;
        cp16(sBh + row * LDBS + c4 * 8, g_Bh + boff + row * 128 + c4 * 8);
    }
    asm volatile("cp.async.commit_group;\n");

    #pragma unroll
    for (int it = 0; it < 16; it++) {
        int idx = tid + it * 512;
        int c2 = idx & 63, r = idx >> 6;
        int gr = row0 + r;
        float2 v = make_float2(0.f, 0.f);
        if (gr < M) v = *(const float2*)(A + (size_t)gr * 128 + c2 * 2);
        __half hx = __float2half_rn(v.x), hy = __float2half_rn(v.y);
        *(__half2*)(sAh + r * LDAH + c2 * 2) = __halves2half2(hx, hy);
        *(__half2*)(sAl + r * LDAH + c2 * 2) =
            __halves2half2(__float2half_rn(v.x - __half2float(hx)),
                           __float2half_rn(v.y - __half2float(hy)));
    }
    asm volatile("cp.async.wait_group 0;\n");
    __syncthreads();

    wmma::fragment<wmma::accumulator, 16, 16, 16, float> acc[2][2];
    #pragma unroll
    for (int i = 0; i < 2; i++)
        #pragma unroll
        for (int j = 0; j < 2; j++)
            wmma::fill_fragment(acc[i][j], 0.f);

    #pragma unroll
    for (int kk = 0; kk < 8; kk++) {
        wmma::fragment<wmma::matrix_a, 16, 16, 16, __half, wmma::row_major> ah[2], al[2];
        #pragma unroll
        for (int i = 0; i < 2; i++) {
            wmma::load_matrix_sync(ah[i], sAh + (wm * 32 + i * 16) * LDAH + kk * 16, LDAH);
            wmma::load_matrix_sync(al[i], sAl + (wm * 32 + i * 16) * LDAH + kk * 16, LDAH);
        }
        #pragma unroll
        for (int j = 0; j < 2; j++) {
            wmma::fragment<wmma::matrix_b, 16, 16, 16, __half, wmma::row_major> bh;
            wmma::load_matrix_sync(bh, sBh + kk * 16 * LDBS + wn * 32 + j * 16, LDBS);
            #pragma unroll
            for (int i = 0; i < 2; i++) {
                wmma::mma_sync(acc[i][j], ah[i], bh, acc[i][j]);
                wmma::mma_sync(acc[i][j], al[i], bh, acc[i][j]);
            }
        }
    }

    __syncthreads();
    float* Cs = (float*)sm;
    #pragma unroll
    for (int i = 0; i < 2; i++) {
        int r = wm * 32 + i * 16;
        #pragma unroll
        for (int j = 0; j < 2; j++)
            wmma::store_matrix_sync(Cs + (size_t)r * LDC + wn * 32 + j * 16,
                                    acc[i][j], LDC, wmma::mem_row_major);
    }
    __syncthreads();
    dots_epilogue(Cs, row0, M, wid, lane, a_s, a_d);
}

// ------------------------- layer-3 WMMA GEMM (48-pad) + fused dots ----------
__global__ void __launch_bounds__(256, 2)
hgemm40(const float* __restrict__ A,
        const float* __restrict__ a_s, const float* __restrict__ a_d,
        float* __restrict__ C, int M) {
    extern __shared__ __half sm[];
    __half* sBh = sm;                       // 128 x LDB3
    __half* sAh = sBh + 128 * LDB3;
    __half* sAl = sAh + 128 * LDAH;
    int tid = threadIdx.x;
    int wid = tid >> 5, lane = tid & 31;
    int row0 = blockIdx.x * 128;

    // B3: 768 16B chunks (128 rows x 48 halves = 6 chunks/row)
    #pragma unroll
    for (int it = 0; it < 3; it++) {
        int idx = tid + it * 256;
        int row = idx / 6, c = idx - row * 6;
        cp16(sBh + row * LDB3 + c * 8, g_B3h + row * 48 + c * 8);
    }
    asm volatile("cp.async.commit_group;\n");

    // A: 8192 float2 pairs, 256 threads -> 32 iters
    #pragma unroll
    for (int it = 0; it < 32; it++) {
        int idx = tid + it * 256;
        int c2 = idx & 63, r = idx >> 6;
        int gr = row0 + r;
        float2 v = make_float2(0.f, 0.f);
        if (gr < M) v = *(const float2*)(A + (size_t)gr * 128 + c2 * 2);
        __half hx = __float2half_rn(v.x), hy = __float2half_rn(v.y);
        *(__half2*)(sAh + r * LDAH + c2 * 2) = __halves2half2(hx, hy);
        *(__half2*)(sAl + r * LDAH + c2 * 2) =
            __halves2half2(__float2half_rn(v.x - __half2float(hx)),
                           __float2half_rn(v.y - __half2float(hy)));
    }
    asm volatile("cp.async.wait_group 0;\n");
    __syncthreads();

    // warp tile: 16 rows x 48 cols
    wmma::fragment<wmma::accumulator, 16, 16, 16, float> acc[3];
    #pragma unroll
    for (int j = 0; j < 3; j++) wmma::fill_fragment(acc[j], 0.f);

    #pragma unroll
    for (int kk = 0; kk < 8; kk++) {
        wmma::fragment<wmma::matrix_a, 16, 16, 16, __half, wmma::row_major> ah, al;
        wmma::load_matrix_sync(ah, sAh + (wid * 16) * LDAH + kk * 16, LDAH);
        wmma::load_matrix_sync(al, sAl + (wid * 16) * LDAH + kk * 16, LDAH);
        #pragma unroll
        for (int j = 0; j < 3; j++) {
            wmma::fragment<wmma::matrix_b, 16, 16, 16, __half, wmma::row_major> bh;
            wmma::load_matrix_sync(bh, sBh + kk * 16 * LDB3 + j * 16, LDB3);
            wmma::mma_sync(acc[j], ah, bh, acc[j]);
            wmma::mma_sync(acc[j], al, bh, acc[j]);
        }
    }

    __syncthreads();
    float* Cs = (float*)sm;                 // 128 x LDC3 fp32 (28.7KB)
    #pragma unroll
    for (int j = 0; j < 3; j++)
        wmma::store_matrix_sync(Cs + (size_t)(wid * 16) * LDC3 + j * 16,
                                acc[j], LDC3, wmma::mem_row_major);
    __syncthreads();

    // fused dots + fp32 output (40 cols)
    float as1v = a_s[lane], ad1v = a_d[lane];
    float as2v = (lane < 8) ? a_s[32 + lane] : 0.f;
    float ad2v = (lane < 8) ? a_d[32 + lane] : 0.f;
    #pragma unroll
    for (int rr = 0; rr < 16; rr++) {
        int r = wid * 16 + rr;
        int row = row0 + r;
        if (row >= M) break;
        float x1 = Cs[(size_t)r * LDC3 + lane];
        float x2 = (lane < 8) ? Cs[(size_t)r * LDC3 + 32 + lane] : 0.f;
        C[(size_t)row * 40 + lane] = x1;
        if (lane < 8) C[(size_t)row * 40 + 32 + lane] = x2;
        float ps = x1 * as1v + x2 * as2v;
        float pd = x1 * ad1v + x2 * ad2v;
        #pragma unroll
        for (int o = 16; o; o >>= 1) {
            ps += __shfl_xor_sync(0xffffffffu, ps, o);
            pd += __shfl_xor_sync(0xffffffffu, pd, o);
        }
        if (lane == 0) { g_es[row] = ps; g_ed[row] = pd; }
    }
}

// ------------------------- fused GAT agg (fp16 gather, 2x unroll) -----------
__global__ void agg128(const float* __restrict__ bias,
                       const float* __restrict__ gam, const float* __restrict__ bet,
                       const float* __restrict__ mean, const float* __restrict__ var,
                       const float* __restrict__ res, float* __restrict__ out, int n) {
    int node = blockIdx.x * 8 + (threadIdx.x >> 5);
    if (node >= n) return;
    int lane = threadIdx.x & 31;
    int head = lane >> 3, esub = lane & 7;
    float ed = g_ed[node * 4 + head];
    int s = g_off[node], e = g_off[node + 1];

    float m = -1e30f, den = 0.f;
    for (int base = s; base < e; base += 8) {
        int i = base + esub;
        bool val = i < e;
        int u = val ? g_csr[i] : 0;
        float ev = g_es[u * 4 + head] + ed;
        ev = ev > 0.f ? ev : 0.2f * ev;
        if (!val) ev = -1e30f;
        float gm = ev;
        gm = fmaxf(gm, __shfl_xor_sync(0xffffffffu, gm, 1));
        gm = fmaxf(gm, __shfl_xor_sync(0xffffffffu, gm, 2));
        gm = fmaxf(gm, __shfl_xor_sync(0xffffffffu, gm, 4));
        float nm = fmaxf(m, gm);
        float w = __expf(ev - nm);
        w += __shfl_xor_sync(0xffffffffu, w, 1);
        w += __shfl_xor_sync(0xffffffffu, w, 2);
        w += __shfl_xor_sync(0xffffffffu, w, 4);
        den = den * __expf(m - nm) + w;
        m = nm;
    }
    float rinv = 1.f / den;

    // pass 2: 2-way unrolled weighted gather (independent load chains)
    float4 acc = make_float4(0.f, 0.f, 0.f, 0.f);
    int i = s;
    for (; i + 1 < e; i += 2) {
        int u0 = g_csr[i];
        int u1 = g_csr[i + 1];
        float e0 = g_es[u0 * 4 + head] + ed;
        float e1 = g_es[u1 * 4 + head] + ed;
        e0 = e0 > 0.f ? e0 : 0.2f * e0;
        e1 = e1 > 0.f ? e1 : 0.2f * e1;
        float w0 = __expf(e0 - m);
        float w1 = __expf(e1 - m);
        uint2 p0 = *(const uint2*)(g_xwh + (size_t)u0 * 128 + lane * 4);
        uint2 p1 = *(const uint2*)(g_xwh + (size_t)u1 * 128 + lane * 4);
        float2 a0 = __half22float2(*(__half2*)&p0.x);
        float2 b0 = __half22float2(*(__half2*)&p0.y);
        float2 a1 = __half22float2(*(__half2*)&p1.x);
        float2 b1 = __half22float2(*(__half2*)&p1.y);
        acc.x += w0 * a0.x + w1 * a1.x;
        acc.y += w0 * a0.y + w1 * a1.y;
        acc.z += w0 * b0.x + w1 * b1.x;
        acc.w += w0 * b0.y + w1 * b1.y;
    }
    if (i < e) {
        int u0 = g_csr[i];
        float e0 = g_es[u0 * 4 + head] + ed;
        e0 = e0 > 0.f ? e0 : 0.2f * e0;
        float w0 = __expf(e0 - m);
        uint2 p0 = *(const uint2*)(g_xwh + (size_t)u0 * 128 + lane * 4);
        float2 a0 = __half22float2(*(__half2*)&p0.x);
        float2 b0 = __half22float2(*(__half2*)&p0.y);
        acc.x += w0 * a0.x; acc.y += w0 * a0.y;
        acc.z += w0 * b0.x; acc.w += w0 * b0.y;
    }

    int c = lane * 4;
    float4 b4 = *(const float4*)(bias + c);
    float4 g4 = *(const float4*)(gam + c);
    float4 e4 = *(const float4*)(bet + c);
    float4 m4 = *(const float4*)(mean + c);
    float4 v4 = *(const float4*)(var + c);
    float4 r4 = *(const float4*)(res + (size_t)node * 128 + c);
    float o0 = (acc.x * rinv + b4.x - m4.x) * rsqrtf(v4.x + GAT_EPS) * g4.x + e4.x + r4.x;
    float o1 = (acc.y * rinv + b4.y - m4.y) * rsqrtf(v4.y + GAT_EPS) * g4.y + e4.y + r4.y;
    float o2 = (acc.z * rinv + b4.z - m4.z) * rsqrtf(v4.z + GAT_EPS) * g4.z + e4.z + r4.z;
    float o3 = (acc.w * rinv + b4.w - m4.w) * rsqrtf(v4.w + GAT_EPS) * g4.w + e4.w + r4.w;
    float4 o = make_float4(o0 > 0.f ? o0 : expm1f(o0),
                           o1 > 0.f ? o1 : expm1f(o1),
                           o2 > 0.f ? o2 : expm1f(o2),
                           o3 > 0.f ? o3 : expm1f(o3));
    *(float4*)(out + (size_t)node * 128 + c) = o;
}

// ------------------------- layer-3 agg (fp32, two-pass) ---------------------
__global__ void agg40(const float* __restrict__ xw, const float* __restrict__ bias,
                      float* __restrict__ out, int n) {
    int node = blockIdx.x * 8 + (threadIdx.x >> 5);
    if (node >= n) return;
    int lane = threadIdx.x & 31;
    float ed = g_ed[node];
    int s = g_off[node], e = g_off[node + 1];

    float m = -1e30f, den = 0.f;
    for (int base = s; base < e; base += 32) {
        int i = base + lane;
        bool val = i < e;
        int u = val ? g_csr[i] : 0;
        float ev = g_es[u] + ed;
        ev = ev > 0.f ? ev : 0.2f * ev;
        if (!val) ev = -1e30f;
        float gm = ev;
        #pragma unroll
        for (int o = 16; o; o >>= 1) gm = fmaxf(gm, __shfl_xor_sync(0xffffffffu, gm, o));
        float nm = fmaxf(m, gm);
        float w = __expf(ev - nm);
        #pragma unroll
        for (int o = 16; o; o >>= 1) w += __shfl_xor_sync(0xffffffffu, w, o);
        den = den * __expf(m - nm) + w;
        m = nm;
    }
    float rinv = 1.f / den;

    float a1 = 0.f, a2 = 0.f;
    int u = g_csr[s];
    for (int i = s; i < e; i++) {
        int un = g_csr[i + 1];
        float ev = g_es[u] + ed;
        ev = ev > 0.f ? ev : 0.2f * ev;
        float w = __expf(ev - m);
        a1 += w * xw[(size_t)u * 40 + lane];
        if (lane < 8) a2 += w * xw[(size_t)u * 40 + 32 + lane];
        u = un;
    }
    out[(size_t)node * 40 + lane] = a1 * rinv + bias[lane];
    if (lane < 8) out[(size_t)node * 40 + 32 + lane] = a2 * rinv + bias[32 + lane];
}

// ------------------------- launch ------------------------------------------
extern "C" void kernel_launch(void* const* d_in, const int* in_sizes, int n_in,
                              void* d_out, int out_size) {
    const float* x    = (const float*)d_in[0];
    const int*   ei   = (const int*)  d_in[1];
    const float* W1   = (const float*)d_in[2];
    const float* as1  = (const float*)d_in[3];
    const float* ad1  = (const float*)d_in[4];
    const float* b1   = (const float*)d_in[5];
    const float* W2   = (const float*)d_in[6];
    const float* as2  = (const float*)d_in[7];
    const float* ad2  = (const float*)d_in[8];
    const float* b2   = (const float*)d_in[9];
    const float* W3   = (const float*)d_in[10];
    const float* as3  = (const float*)d_in[11];
    const float* ad3  = (const float*)d_in[12];
    const float* b3   = (const float*)d_in[13];
    const float* Wres = (const float*)d_in[14];
    const float* g1   = (const float*)d_in[15];
    const float* be1  = (const float*)d_in[16];
    const float* m1   = (const float*)d_in[17];
    const float* v1   = (const float*)d_in[18];
    const float* g2   = (const float*)d_in[19];
    const float* be2  = (const float*)d_in[20];
    const float* m2   = (const float*)d_in[21];
    const float* v2   = (const float*)d_in[22];

    int n = in_sizes[0] / 128;
    int E = in_sizes[1] / 2;
    const int* src = ei;
    const int* dst = ei + E;
    int tot = E + n;
    int nblk = (n + 1023) / 1024;

    float *p_aux, *p_h1, *p_h2, *p_xw3;
    cudaGetSymbolAddress((void**)&p_aux, g_aux);
    cudaGetSymbolAddress((void**)&p_h1,  g_h1);
    cudaGetSymbolAddress((void**)&p_h2,  g_h2);
    cudaGetSymbolAddress((void**)&p_xw3, g_xw3);

    cudaFuncSetAttribute(hgemm_dual, cudaFuncAttributeMaxDynamicSharedMemorySize, SM_DUAL);
    cudaFuncSetAttribute(hgemm128,   cudaFuncAttributeMaxDynamicSharedMemorySize, SM_SNGL);
    cudaFuncSetAttribute(hgemm40,    cudaFuncAttributeMaxDynamicSharedMemorySize, SM_40);

    int nb_gemm = (n + 127) / 128;
    int nb_warp = (n + 7) / 8;

    preB_zcnt <<<216, 256>>>(W1, Wres, W2, W3, n);                         // 1
    histo_kernel <<<(tot + 255) / 256, 256>>>(dst, E, n);                  // 2
    scan1_kernel <<<nblk, 256>>>(n);                                       // 3
    hgemm_dual <<<nb_gemm, 512, SM_DUAL>>>(x, p_aux, n, 0, 16384, as1, ad1); // 4 (profiled)
    scan23_kernel <<<(n + 255) / 256, 256>>>(nblk, n);                     // 5
    scatter_kernel <<<(tot + 255) / 256, 256>>>(src, dst, E, n);           // 6

    // ---- layer 1 aggregation ----
    agg128 <<<nb_warp, 256>>>(b1, g1, be1, m1, v1, p_aux, p_h1, n);        // 7

    // ---- layer 2 ----
    hgemm128 <<<nb_gemm, 512, SM_SNGL>>>(p_h1, n, 32768, as2, ad2);        // 8
    agg128 <<<nb_warp, 256>>>(b2, g2, be2, m2, v2, p_h1, p_h2, n);         // 9

    // ---- layer 3 ----
    hgemm40 <<<nb_gemm, 256, SM_40>>>(p_h2, as3, ad3, p_xw3, n);           // 10
    agg40  <<<nb_warp, 256>>>(p_xw3, b3, (float*)d_out, n);                // 11
}

// round 14
// speedup vs baseline: 1.7110x; 1.0741x over previous
#include <cuda_runtime.h>
#include <cuda_fp16.h>
#include <mma.h>
using namespace nvcuda;

// Problem constants
#define MAXN 50000
#define MAXE 400000
#define MAXTOT (MAXN + MAXE)
#define GAT_EPS 1e-5f

// ------------------------- scratch (device globals) ------------------------
__device__ float g_aux [MAXN * 128];
__device__ float g_h1  [MAXN * 128];
__device__ float g_h2  [MAXN * 128];
__device__ float g_xw3 [MAXN * 40];
__device__ float g_es  [MAXN * 4];
__device__ float g_ed  [MAXN * 4];
__device__ int   g_cnt [MAXN];
__device__ int   g_off [MAXN + 1];
__device__ int   g_cur [MAXN];
__device__ int   g_csr [MAXTOT + 8];
__device__ int   g_bsum[64];
__device__ __align__(16) __half g_Bh[3 * 16384];
__device__ __align__(16) __half g_B3h[128 * 48];
__device__ __align__(16) __half g_xwh[MAXN * 128];   // fp16 gather operand

// ------------------------- preB (hi planes) + zcnt ---------------------------
__global__ void preB_zcnt(const float* __restrict__ W1, const float* __restrict__ Wres,
                          const float* __restrict__ W2, const float* __restrict__ W3,
                          int n) {
    int i = blockIdx.x * blockDim.x + threadIdx.x;
    if (i < n) g_cnt[i] = 0;
    if (i < 3 * 16384) {
        const float* W = (i < 16384) ? W1 : (i < 32768 ? Wres : W2);
        g_Bh[i] = __float2half_rn(W[i & 16383]);
    } else if (i < 3 * 16384 + 128 * 48) {
        int j = i - 3 * 16384;
        int k = j / 48, nn = j - k * 48;
        g_B3h[j] = (nn < 40) ? __float2half_rn(W3[k * 40 + nn]) : __half(0);
    }
}

__global__ void histo_kernel(const int* __restrict__ dst, int E, int n) {
    int i = blockIdx.x * blockDim.x + threadIdx.x;
    if (i >= E + n) return;
    int dd = (i < E) ? dst[i] : (i - E);
    atomicAdd(&g_cnt[dd], 1);
}

__global__ void scan1_kernel(int n) {
    __shared__ int wsum[8];
    int tid = threadIdx.x;
    int base = blockIdx.x * 1024 + tid * 4;
    int c0 = (base + 0 < n) ? g_cnt[base + 0] : 0;
    int c1 = (base + 1 < n) ? g_cnt[base + 1] : 0;
    int c2 = (base + 2 < n) ? g_cnt[base + 2] : 0;
    int c3 = (base + 3 < n) ? g_cnt[base + 3] : 0;
    int t = c0 + c1 + c2 + c3;
    int lane = tid & 31, wid = tid >> 5;
    int incl = t;
    #pragma unroll
    for (int o = 1; o < 32; o <<= 1) {
        int v = __shfl_up_sync(0xffffffffu, incl, o);
        if (lane >= o) incl += v;
    }
    if (lane == 31) wsum[wid] = incl;
    __syncthreads();
    if (tid == 0) {
        int r = 0;
        #pragma unroll
        for (int k = 0; k < 8; k++) { int v = wsum[k]; wsum[k] = r; r += v; }
        g_bsum[blockIdx.x] = r;
    }
    __syncthreads();
    int run = wsum[wid] + incl - t;
    if (base + 0 < n) g_off[base + 0] = run; run += c0;
    if (base + 1 < n) g_off[base + 1] = run; run += c1;
    if (base + 2 < n) g_off[base + 2] = run; run += c2;
    if (base + 3 < n) g_off[base + 3] = run;
}

__global__ void scan23_kernel(int nb, int n) {
    __shared__ int sboff[64];
    __shared__ int sgrand;
    int tid = threadIdx.x;
    if (tid < 32) {
        int lane = tid;
        int v0 = (lane < nb) ? g_bsum[lane] : 0;
        int v1 = (32 + lane < nb) ? g_bsum[32 + lane] : 0;
        int i0 = v0;
        #pragma unroll
        for (int o = 1; o < 32; o <<= 1) {
            int q = __shfl_up_sync(0xffffffffu, i0, o);
            if (lane >= o) i0 += q;
        }
        int tot0 = __shfl_sync(0xffffffffu, i0, 31);
        int i1 = v1;
        #pragma unroll
        for (int o = 1; o < 32; o <<= 1) {
            int q = __shfl_up_sync(0xffffffffu, i1, o);
            if (lane >= o) i1 += q;
        }
        i1 += tot0;
        sboff[lane] = i0 - v0;
        sboff[32 + lane] = i1 - v1;
        if (lane == 31) sgrand = i1;
    }
    __syncthreads();
    int i = blockIdx.x * blockDim.x + tid;
    if (i < n) {
        int o = g_off[i] + sboff[i >> 10];
        g_off[i] = o;
        g_cur[i] = o;
    }
    if (blockIdx.x == 0 && tid == 0) g_off[n] = sgrand;
}

__global__ void scatter_kernel(const int* __restrict__ src, const int* __restrict__ dst,
                               int E, int n) {
    int i = blockIdx.x * blockDim.x + threadIdx.x;
    if (i >= E + n) return;
    int ss, dd;
    if (i < E) { ss = src[i]; dd = dst[i]; }
    else       { ss = dd = i - E; }
    int p = atomicAdd(&g_cur[dd], 1);
    g_csr[p] = ss;
}

// ------------------------- GEMM helpers -------------------------------------
#define LDAH 136
#define LDBH 272
#define LDBS 136
#define LDC  132
#define LDB3 56
#define LDC3 56
#define SM_DUAL ((128 * LDBH + 128 * LDAH) * 2)   // 104448 B
#define SM_SNGL ((128 * LDBS + 128 * LDAH) * 2)   // 69632 B
#define SM_40   ((128 * LDB3 + 128 * LDAH) * 2)   // 49152 B

__device__ __forceinline__ void cp16(__half* dst, const __half* src) {
    unsigned d = (unsigned)__cvta_generic_to_shared(dst);
    asm volatile("cp.async.cg.shared.global [%0], [%1], 16;\n" :: "r"(d), "l"(src));
}

__device__ __forceinline__ void store_xwh(int row, int lane, float4 xv) {
    __half2 ha = __floats2half2_rn(xv.x, xv.y);
    __half2 hb = __floats2half2_rn(xv.z, xv.w);
    uint2 p = make_uint2(*(unsigned*)&ha, *(unsigned*)&hb);
    *(uint2*)(g_xwh + (size_t)row * 128 + lane * 4) = p;
}

__device__ __forceinline__ void dots_epilogue(const float* Cs, int row0, int M,
                                              int wid, int lane,
                                              const float* a_s, const float* a_d) {
    float4 asv = *(const float4*)(a_s + lane * 4);
    float4 adv = *(const float4*)(a_d + lane * 4);
    #pragma unroll
    for (int rr = 0; rr < 8; rr++) {
        int r = wid * 8 + rr;
        int row = row0 + r;
        if (row >= M) break;
        float4 xv = *(const float4*)(Cs + (size_t)r * LDC + lane * 4);
        store_xwh(row, lane, xv);
        float ps = xv.x * asv.x + xv.y * asv.y + xv.z * asv.z + xv.w * asv.w;
        float pd = xv.x * adv.x + xv.y * adv.y + xv.z * adv.z + xv.w * adv.w;
        ps += __shfl_xor_sync(0xffffffffu, ps, 1);
        ps += __shfl_xor_sync(0xffffffffu, ps, 2);
        ps += __shfl_xor_sync(0xffffffffu, ps, 4);
        pd += __shfl_xor_sync(0xffffffffu, pd, 1);
        pd += __shfl_xor_sync(0xffffffffu, pd, 2);
        pd += __shfl_xor_sync(0xffffffffu, pd, 4);
        if ((lane & 7) == 0) {
            int h = lane >> 3;
            g_es[row * 4 + h] = ps;
            g_ed[row * 4 + h] = pd;
        }
    }
}

// ------------------------- dual WMMA GEMM (layer 1), A-hi x B-hi ------------
__global__ void __launch_bounds__(512, 1)
hgemm_dual(const float* __restrict__ A, float* __restrict__ C2,
           int M, int boff1, int boff2,
           const float* __restrict__ a_s, const float* __restrict__ a_d) {
    extern __shared__ __half sm[];
    __half* sBh = sm;
    __half* sAh = sBh + 128 * LDBH;
    int tid = threadIdx.x;
    int wid = tid >> 5, lane = tid & 31;
    int wm = wid & 3, wn = wid >> 2;
    int mi = wn >> 1, nsub = wn & 1;
    int row0 = blockIdx.x * 128;

    #pragma unroll
    for (int it = 0; it < 8; it++) {
        int idx = tid + it * 512;
        int c4 = idx & 15, row = (idx >> 4) & 127, mat = idx >> 11;
        const __half* src = g_Bh + (mat ? boff2 : boff1) + row * 128 + c4 * 8;
        __half* dst = sBh + row * LDBH + mat * 128 + c4 * 8;
        cp16(dst, src);
    }
    asm volatile("cp.async.commit_group;\n");

    #pragma unroll
    for (int it = 0; it < 16; it++) {
        int idx = tid + it * 512;
        int c2 = idx & 63, r = idx >> 6;
        int gr = row0 + r;
        float2 v = make_float2(0.f, 0.f);
        if (gr < M) v = *(const float2*)(A + (size_t)gr * 128 + c2 * 2);
        *(__half2*)(sAh + r * LDAH + c2 * 2) = __floats2half2_rn(v.x, v.y);
    }
    asm volatile("cp.async.wait_group 0;\n");
    __syncthreads();

    wmma::fragment<wmma::accumulator, 16, 16, 16, float> acc[2][4];
    #pragma unroll
    for (int i = 0; i < 2; i++)
        #pragma unroll
        for (int j = 0; j < 4; j++)
            wmma::fill_fragment(acc[i][j], 0.f);

    #pragma unroll
    for (int kk = 0; kk < 8; kk++) {
        wmma::fragment<wmma::matrix_a, 16, 16, 16, __half, wmma::row_major> ah[2];
        #pragma unroll
        for (int i = 0; i < 2; i++)
            wmma::load_matrix_sync(ah[i], sAh + (wm * 32 + i * 16) * LDAH + kk * 16, LDAH);
        #pragma unroll
        for (int j = 0; j < 4; j++) {
            wmma::fragment<wmma::matrix_b, 16, 16, 16, __half, wmma::row_major> bh;
            wmma::load_matrix_sync(bh, sBh + kk * 16 * LDBH + mi * 128 + nsub * 64 + j * 16, LDBH);
            #pragma unroll
            for (int i = 0; i < 2; i++)
                wmma::mma_sync(acc[i][j], ah[i], bh, acc[i][j]);
        }
    }

    __syncthreads();
    float* Cs = (float*)sm;   // 128 x LDC fp32 = 67.6KB <= 104.4KB
    #pragma unroll
    for (int i = 0; i < 2; i++) {
        int r = wm * 32 + i * 16;
        int gr = row0 + r;
        if (mi == 0) {
            #pragma unroll
            for (int j = 0; j < 4; j++)
                wmma::store_matrix_sync(Cs + (size_t)r * LDC + nsub * 64 + j * 16,
                                        acc[i][j], LDC, wmma::mem_row_major);
        } else if (gr < M) {
            #pragma unroll
            for (int j = 0; j < 4; j++)
                wmma::store_matrix_sync(C2 + (size_t)gr * 128 + nsub * 64 + j * 16,
                                        acc[i][j], 128, wmma::mem_row_major);
        }
    }
    __syncthreads();
    dots_epilogue(Cs, row0, M, wid, lane, a_s, a_d);
}

// ------------------------- single WMMA GEMM (layer 2), A-hi x B-hi ----------
__global__ void __launch_bounds__(512, 2)
hgemm128(const float* __restrict__ A, int M, int boff,
         const float* __restrict__ a_s, const float* __restrict__ a_d) {
    extern __shared__ __half sm[];
    __half* sBh = sm;
    __half* sAh = sBh + 128 * LDBS;
    int tid = threadIdx.x;
    int wid = tid >> 5, lane = tid & 31;
    int wm = wid & 3, wn = wid >> 2;
    int row0 = blockIdx.x * 128;

    #pragma unroll
    for (int it = 0; it < 4; it++) {
        int idx = tid + it * 512;
        int c4 = idx & 15, row = idx >> 4;
        cp16(sBh + row * LDBS + c4 * 8, g_Bh + boff + row * 128 + c4 * 8);
    }
    asm volatile("cp.async.commit_group;\n");

    #pragma unroll
    for (int it = 0; it < 16; it++) {
        int idx = tid + it * 512;
        int c2 = idx & 63, r = idx >> 6;
        int gr = row0 + r;
        float2 v = make_float2(0.f, 0.f);
        if (gr < M) v = *(const float2*)(A + (size_t)gr * 128 + c2 * 2);
        *(__half2*)(sAh + r * LDAH + c2 * 2) = __floats2half2_rn(v.x, v.y);
    }
    asm volatile("cp.async.wait_group 0;\n");
    __syncthreads();

    wmma::fragment<wmma::accumulator, 16, 16, 16, float> acc[2][2];
    #pragma unroll
    for (int i = 0; i < 2; i++)
        #pragma unroll
        for (int j = 0; j < 2; j++)
            wmma::fill_fragment(acc[i][j], 0.f);

    #pragma unroll
    for (int kk = 0; kk < 8; kk++) {
        wmma::fragment<wmma::matrix_a, 16, 16, 16, __half, wmma::row_major> ah[2];
        #pragma unroll
        for (int i = 0; i < 2; i++)
            wmma::load_matrix_sync(ah[i], sAh + (wm * 32 + i * 16) * LDAH + kk * 16, LDAH);
        #pragma unroll
        for (int j = 0; j < 2; j++) {
            wmma::fragment<wmma::matrix_b, 16, 16, 16, __half, wmma::row_major> bh;
            wmma::load_matrix_sync(bh, sBh + kk * 16 * LDBS + wn * 32 + j * 16, LDBS);
            #pragma unroll
            for (int i = 0; i < 2; i++)
                wmma::mma_sync(acc[i][j], ah[i], bh, acc[i][j]);
        }
    }

    __syncthreads();
    float* Cs = (float*)sm;   // 67.6KB <= 69.6KB
    #pragma unroll
    for (int i = 0; i < 2; i++) {
        int r = wm * 32 + i * 16;
        #pragma unroll
        for (int j = 0; j < 2; j++)
            wmma::store_matrix_sync(Cs + (size_t)r * LDC + wn * 32 + j * 16,
                                    acc[i][j], LDC, wmma::mem_row_major);
    }
    __syncthreads();
    dots_epilogue(Cs, row0, M, wid, lane, a_s, a_d);
}

// ------------------------- layer-3 WMMA GEMM (48-pad) + fused dots ----------
__global__ void __launch_bounds__(256, 2)
hgemm40(const float* __restrict__ A,
        const float* __restrict__ a_s, const float* __restrict__ a_d,
        float* __restrict__ C, int M) {
    extern __shared__ __half sm[];
    __half* sBh = sm;
    __half* sAh = sBh + 128 * LDB3;
    int tid = threadIdx.x;
    int wid = tid >> 5, lane = tid & 31;
    int row0 = blockIdx.x * 128;

    #pragma unroll
    for (int it = 0; it < 3; it++) {
        int idx = tid + it * 256;
        int row = idx / 6, c = idx - row * 6;
        cp16(sBh + row * LDB3 + c * 8, g_B3h + row * 48 + c * 8);
    }
    asm volatile("cp.async.commit_group;\n");

    #pragma unroll
    for (int it = 0; it < 32; it++) {
        int idx = tid + it * 256;
        int c2 = idx & 63, r = idx >> 6;
        int gr = row0 + r;
        float2 v = make_float2(0.f, 0.f);
        if (gr < M) v = *(const float2*)(A + (size_t)gr * 128 + c2 * 2);
        *(__half2*)(sAh + r * LDAH + c2 * 2) = __floats2half2_rn(v.x, v.y);
    }
    asm volatile("cp.async.wait_group 0;\n");
    __syncthreads();

    wmma::fragment<wmma::accumulator, 16, 16, 16, float> acc[3];
    #pragma unroll
    for (int j = 0; j < 3; j++) wmma::fill_fragment(acc[j], 0.f);

    #pragma unroll
    for (int kk = 0; kk < 8; kk++) {
        wmma::fragment<wmma::matrix_a, 16, 16, 16, __half, wmma::row_major> ah;
        wmma::load_matrix_sync(ah, sAh + (wid * 16) * LDAH + kk * 16, LDAH);
        #pragma unroll
        for (int j = 0; j < 3; j++) {
            wmma::fragment<wmma::matrix_b, 16, 16, 16, __half, wmma::row_major> bh;
            wmma::load_matrix_sync(bh, sBh + kk * 16 * LDB3 + j * 16, LDB3);
            wmma::mma_sync(acc[j], ah, bh, acc[j]);
        }
    }

    __syncthreads();
    float* Cs = (float*)sm;   // 28.7KB <= 49.2KB
    #pragma unroll
    for (int j = 0; j < 3; j++)
        wmma::store_matrix_sync(Cs + (size_t)(wid * 16) * LDC3 + j * 16,
                                acc[j], LDC3, wmma::mem_row_major);
    __syncthreads();

    float as1v = a_s[lane], ad1v = a_d[lane];
    float as2v = (lane < 8) ? a_s[32 + lane] : 0.f;
    float ad2v = (lane < 8) ? a_d[32 + lane] : 0.f;
    #pragma unroll
    for (int rr = 0; rr < 16; rr++) {
        int r = wid * 16 + rr;
        int row = row0 + r;
        if (row >= M) break;
        float x1 = Cs[(size_t)r * LDC3 + lane];
        float x2 = (lane < 8) ? Cs[(size_t)r * LDC3 + 32 + lane] : 0.f;
        C[(size_t)row * 40 + lane] = x1;
        if (lane < 8) C[(size_t)row * 40 + 32 + lane] = x2;
        float ps = x1 * as1v + x2 * as2v;
        float pd = x1 * ad1v + x2 * ad2v;
        #pragma unroll
        for (int o = 16; o; o >>= 1) {
            ps += __shfl_xor_sync(0xffffffffu, ps, o);
            pd += __shfl_xor_sync(0xffffffffu, pd, o);
        }
        if (lane == 0) { g_es[row] = ps; g_ed[row] = pd; }
    }
}

// ------------------------- fused GAT agg (fp16 gather, 2x unroll) -----------
__global__ void agg128(const float* __restrict__ bias,
                       const float* __restrict__ gam, const float* __restrict__ bet,
                       const float* __restrict__ mean, const float* __restrict__ var,
                       const float* __restrict__ res, float* __restrict__ out, int n) {
    int node = blockIdx.x * 8 + (threadIdx.x >> 5);
    if (node >= n) return;
    int lane = threadIdx.x & 31;
    int head = lane >> 3, esub = lane & 7;
    float ed = g_ed[node * 4 + head];
    int s = g_off[node], e = g_off[node + 1];

    float m = -1e30f, den = 0.f;
    for (int base = s; base < e; base += 8) {
        int i = base + esub;
        bool val = i < e;
        int u = val ? g_csr[i] : 0;
        float ev = g_es[u * 4 + head] + ed;
        ev = ev > 0.f ? ev : 0.2f * ev;
        if (!val) ev = -1e30f;
        float gm = ev;
        gm = fmaxf(gm, __shfl_xor_sync(0xffffffffu, gm, 1));
        gm = fmaxf(gm, __shfl_xor_sync(0xffffffffu, gm, 2));
        gm = fmaxf(gm, __shfl_xor_sync(0xffffffffu, gm, 4));
        float nm = fmaxf(m, gm);
        float w = __expf(ev - nm);
        w += __shfl_xor_sync(0xffffffffu, w, 1);
        w += __shfl_xor_sync(0xffffffffu, w, 2);
        w += __shfl_xor_sync(0xffffffffu, w, 4);
        den = den * __expf(m - nm) + w;
        m = nm;
    }
    float rinv = 1.f / den;

    float4 acc = make_float4(0.f, 0.f, 0.f, 0.f);
    int i = s;
    for (; i + 1 < e; i += 2) {
        int u0 = g_csr[i];
        int u1 = g_csr[i + 1];
        float e0 = g_es[u0 * 4 + head] + ed;
        float e1 = g_es[u1 * 4 + head] + ed;
        e0 = e0 > 0.f ? e0 : 0.2f * e0;
        e1 = e1 > 0.f ? e1 : 0.2f * e1;
        float w0 = __expf(e0 - m);
        float w1 = __expf(e1 - m);
        uint2 p0 = *(const uint2*)(g_xwh + (size_t)u0 * 128 + lane * 4);
        uint2 p1 = *(const uint2*)(g_xwh + (size_t)u1 * 128 + lane * 4);
        float2 a0 = __half22float2(*(__half2*)&p0.x);
        float2 b0 = __half22float2(*(__half2*)&p0.y);
        float2 a1 = __half22float2(*(__half2*)&p1.x);
        float2 b1 = __half22float2(*(__half2*)&p1.y);
        acc.x += w0 * a0.x + w1 * a1.x;
        acc.y += w0 * a0.y + w1 * a1.y;
        acc.z += w0 * b0.x + w1 * b1.x;
        acc.w += w0 * b0.y + w1 * b1.y;
    }
    if (i < e) {
        int u0 = g_csr[i];
        float e0 = g_es[u0 * 4 + head] + ed;
        e0 = e0 > 0.f ? e0 : 0.2f * e0;
        float w0 = __expf(e0 - m);
        uint2 p0 = *(const uint2*)(g_xwh + (size_t)u0 * 128 + lane * 4);
        float2 a0 = __half22float2(*(__half2*)&p0.x);
        float2 b0 = __half22float2(*(__half2*)&p0.y);
        acc.x += w0 * a0.x; acc.y += w0 * a0.y;
        acc.z += w0 * b0.x; acc.w += w0 * b0.y;
    }

    int c = lane * 4;
    float4 b4 = *(const float4*)(bias + c);
    float4 g4 = *(const float4*)(gam + c);
    float4 e4 = *(const float4*)(bet + c);
    float4 m4 = *(const float4*)(mean + c);
    float4 v4 = *(const float4*)(var + c);
    float4 r4 = *(const float4*)(res + (size_t)node * 128 + c);
    float o0 = (acc.x * rinv + b4.x - m4.x) * rsqrtf(v4.x + GAT_EPS) * g4.x + e4.x + r4.x;
    float o1 = (acc.y * rinv + b4.y - m4.y) * rsqrtf(v4.y + GAT_EPS) * g4.y + e4.y + r4.y;
    float o2 = (acc.z * rinv + b4.z - m4.z) * rsqrtf(v4.z + GAT_EPS) * g4.z + e4.z + r4.z;
    float o3 = (acc.w * rinv + b4.w - m4.w) * rsqrtf(v4.w + GAT_EPS) * g4.w + e4.w + r4.w;
    float4 o = make_float4(o0 > 0.f ? o0 : expm1f(o0),
                           o1 > 0.f ? o1 : expm1f(o1),
                           o2 > 0.f ? o2 : expm1f(o2),
                           o3 > 0.f ? o3 : expm1f(o3));
    *(float4*)(out + (size_t)node * 128 + c) = o;
}

// ------------------------- layer-3 agg (fp32, two-pass) ---------------------
__global__ void agg40(const float* __restrict__ xw, const float* __restrict__ bias,
                      float* __restrict__ out, int n) {
    int node = blockIdx.x * 8 + (threadIdx.x >> 5);
    if (node >= n) return;
    int lane = threadIdx.x & 31;
    float ed = g_ed[node];
    int s = g_off[node], e = g_off[node + 1];

    float m = -1e30f, den = 0.f;
    for (int base = s; base < e; base += 32) {
        int i = base + lane;
        bool val = i < e;
        int u = val ? g_csr[i] : 0;
        float ev = g_es[u] + ed;
        ev = ev > 0.f ? ev : 0.2f * ev;
        if (!val) ev = -1e30f;
        float gm = ev;
        #pragma unroll
        for (int o = 16; o; o >>= 1) gm = fmaxf(gm, __shfl_xor_sync(0xffffffffu, gm, o));
        float nm = fmaxf(m, gm);
        float w = __expf(ev - nm);
        #pragma unroll
        for (int o = 16; o; o >>= 1) w += __shfl_xor_sync(0xffffffffu, w, o);
        den = den * __expf(m - nm) + w;
        m = nm;
    }
    float rinv = 1.f / den;

    float a1 = 0.f, a2 = 0.f;
    int u = g_csr[s];
    for (int i = s; i < e; i++) {
        int un = g_csr[i + 1];
        float ev = g_es[u] + ed;
        ev = ev > 0.f ? ev : 0.2f * ev;
        float w = __expf(ev - m);
        a1 += w * xw[(size_t)u * 40 + lane];
        if (lane < 8) a2 += w * xw[(size_t)u * 40 + 32 + lane];
        u = un;
    }
    out[(size_t)node * 40 + lane] = a1 * rinv + bias[lane];
    if (lane < 8) out[(size_t)node * 40 + 32 + lane] = a2 * rinv + bias[32 + lane];
}

// ------------------------- launch ------------------------------------------
extern "C" void kernel_launch(void* const* d_in, const int* in_sizes, int n_in,
                              void* d_out, int out_size) {
    const float* x    = (const float*)d_in[0];
    const int*   ei   = (const int*)  d_in[1];
    const float* W1   = (const float*)d_in[2];
    const float* as1  = (const float*)d_in[3];
    const float* ad1  = (const float*)d_in[4];
    const float* b1   = (const float*)d_in[5];
    const float* W2   = (const float*)d_in[6];
    const float* as2  = (const float*)d_in[7];
    const float* ad2  = (const float*)d_in[8];
    const float* b2   = (const float*)d_in[9];
    const float* W3   = (const float*)d_in[10];
    const float* as3  = (const float*)d_in[11];
    const float* ad3  = (const float*)d_in[12];
    const float* b3   = (const float*)d_in[13];
    const float* Wres = (const float*)d_in[14];
    const float* g1   = (const float*)d_in[15];
    const float* be1  = (const float*)d_in[16];
    const float* m1   = (const float*)d_in[17];
    const float* v1   = (const float*)d_in[18];
    const float* g2   = (const float*)d_in[19];
    const float* be2  = (const float*)d_in[20];
    const float* m2   = (const float*)d_in[21];
    const float* v2   = (const float*)d_in[22];

    int n = in_sizes[0] / 128;
    int E = in_sizes[1] / 2;
    const int* src = ei;
    const int* dst = ei + E;
    int tot = E + n;
    int nblk = (n + 1023) / 1024;

    float *p_aux, *p_h1, *p_h2, *p_xw3;
    cudaGetSymbolAddress((void**)&p_aux, g_aux);
    cudaGetSymbolAddress((void**)&p_h1,  g_h1);
    cudaGetSymbolAddress((void**)&p_h2,  g_h2);
    cudaGetSymbolAddress((void**)&p_xw3, g_xw3);

    cudaFuncSetAttribute(hgemm_dual, cudaFuncAttributeMaxDynamicSharedMemorySize, SM_DUAL);
    cudaFuncSetAttribute(hgemm128,   cudaFuncAttributeMaxDynamicSharedMemorySize, SM_SNGL);
    cudaFuncSetAttribute(hgemm40,    cudaFuncAttributeMaxDynamicSharedMemorySize, SM_40);

    int nb_gemm = (n + 127) / 128;
    int nb_warp = (n + 7) / 8;

    preB_zcnt <<<216, 256>>>(W1, Wres, W2, W3, n);                         // 1
    histo_kernel <<<(tot + 255) / 256, 256>>>(dst, E, n);                  // 2
    scan1_kernel <<<nblk, 256>>>(n);                                       // 3
    hgemm_dual <<<nb_gemm, 512, SM_DUAL>>>(x, p_aux, n, 0, 16384, as1, ad1); // 4 (profiled)
    scan23_kernel <<<(n + 255) / 256, 256>>>(nblk, n);                     // 5
    scatter_kernel <<<(tot + 255) / 256, 256>>>(src, dst, E, n);           // 6

    // ---- layer 1 aggregation ----
    agg128 <<<nb_warp, 256>>>(b1, g1, be1, m1, v1, p_aux, p_h1, n);        // 7

    // ---- layer 2 ----
    hgemm128 <<<nb_gemm, 512, SM_SNGL>>>(p_h1, n, 32768, as2, ad2);        // 8
    agg128 <<<nb_warp, 256>>>(b2, g2, be2, m2, v2, p_h1, p_h2, n);         // 9

    // ---- layer 3 ----
    hgemm40 <<<nb_gemm, 256, SM_40>>>(p_h2, as3, ad3, p_xw3, n);           // 10
    agg40  <<<nb_warp, 256>>>(p_xw3, b3, (float*)d_out, n);                // 11
}

// round 15
// speedup vs baseline: 1.7331x; 1.0130x over previous
#include <cuda_runtime.h>
#include <cuda_fp16.h>
#include <mma.h>
using namespace nvcuda;

// Problem constants
#define MAXN 50000
#define MAXE 400000
#define MAXTOT (MAXN + MAXE)
#define GAT_EPS 1e-5f

// ------------------------- scratch (device globals) ------------------------
__device__ float g_aux [MAXN * 128];
__device__ float g_h1  [MAXN * 128];
__device__ float g_h2  [MAXN * 128];
__device__ float g_xw3 [MAXN * 40];
__device__ float g_es  [MAXN * 4];
__device__ float g_ed  [MAXN * 4];
__device__ int   g_cnt [MAXN];
__device__ int   g_off [MAXN + 1];
__device__ int   g_cur [MAXN];
__device__ int   g_csr [MAXTOT + 8];
__device__ int   g_bsum[64];
__device__ __align__(16) __half g_Bh[3 * 16384];
__device__ __align__(16) __half g_B3h[128 * 48];
__device__ __align__(16) __half g_xwh[MAXN * 128];   // fp16 xw (gather operand)
__device__ __align__(16) __half g_hh [MAXN * 128];   // fp16 h (next-layer A operand)

// ------------------------- preB (hi planes) ---------------------------------
__global__ void preB(const float* __restrict__ W1, const float* __restrict__ Wres,
                     const float* __restrict__ W2, const float* __restrict__ W3) {
    int i = blockIdx.x * blockDim.x + threadIdx.x;
    if (i < 3 * 16384) {
        const float* W = (i < 16384) ? W1 : (i < 32768 ? Wres : W2);
        g_Bh[i] = __float2half_rn(W[i & 16383]);
    } else if (i < 3 * 16384 + 128 * 48) {
        int j = i - 3 * 16384;
        int k = j / 48, nn = j - k * 48;
        g_B3h[j] = (nn < 40) ? __float2half_rn(W3[k * 40 + nn]) : __half(0);
    }
}

__global__ void histo_kernel(const int* __restrict__ dst, int E, int n) {
    int i = blockIdx.x * blockDim.x + threadIdx.x;
    if (i >= E + n) return;
    int dd = (i < E) ? dst[i] : (i - E);
    atomicAdd(&g_cnt[dd], 1);
}

// reads counts, resets them to 0 for the next graph replay
__global__ void scan1_kernel(int n) {
    __shared__ int wsum[8];
    int tid = threadIdx.x;
    int base = blockIdx.x * 1024 + tid * 4;
    int c0 = 0, c1 = 0, c2 = 0, c3 = 0;
    if (base + 0 < n) { c0 = g_cnt[base + 0]; g_cnt[base + 0] = 0; }
    if (base + 1 < n) { c1 = g_cnt[base + 1]; g_cnt[base + 1] = 0; }
    if (base + 2 < n) { c2 = g_cnt[base + 2]; g_cnt[base + 2] = 0; }
    if (base + 3 < n) { c3 = g_cnt[base + 3]; g_cnt[base + 3] = 0; }
    int t = c0 + c1 + c2 + c3;
    int lane = tid & 31, wid = tid >> 5;
    int incl = t;
    #pragma unroll
    for (int o = 1; o < 32; o <<= 1) {
        int v = __shfl_up_sync(0xffffffffu, incl, o);
        if (lane >= o) incl += v;
    }
    if (lane == 31) wsum[wid] = incl;
    __syncthreads();
    if (tid == 0) {
        int r = 0;
        #pragma unroll
        for (int k = 0; k < 8; k++) { int v = wsum[k]; wsum[k] = r; r += v; }
        g_bsum[blockIdx.x] = r;
    }
    __syncthreads();
    int run = wsum[wid] + incl - t;
    if (base + 0 < n) g_off[base + 0] = run; run += c0;
    if (base + 1 < n) g_off[base + 1] = run; run += c1;
    if (base + 2 < n) g_off[base + 2] = run; run += c2;
    if (base + 3 < n) g_off[base + 3] = run;
}

__global__ void scan23_kernel(int nb, int n) {
    __shared__ int sboff[64];
    __shared__ int sgrand;
    int tid = threadIdx.x;
    if (tid < 32) {
        int lane = tid;
        int v0 = (lane < nb) ? g_bsum[lane] : 0;
        int v1 = (32 + lane < nb) ? g_bsum[32 + lane] : 0;
        int i0 = v0;
        #pragma unroll
        for (int o = 1; o < 32; o <<= 1) {
            int q = __shfl_up_sync(0xffffffffu, i0, o);
            if (lane >= o) i0 += q;
        }
        int tot0 = __shfl_sync(0xffffffffu, i0, 31);
        int i1 = v1;
        #pragma unroll
        for (int o = 1; o < 32; o <<= 1) {
            int q = __shfl_up_sync(0xffffffffu, i1, o);
            if (lane >= o) i1 += q;
        }
        i1 += tot0;
        sboff[lane] = i0 - v0;
        sboff[32 + lane] = i1 - v1;
        if (lane == 31) sgrand = i1;
    }
    __syncthreads();
    int i = blockIdx.x * blockDim.x + tid;
    if (i < n) {
        int o = g_off[i] + sboff[i >> 10];
        g_off[i] = o;
        g_cur[i] = o;
    }
    if (blockIdx.x == 0 && tid == 0) g_off[n] = sgrand;
}

__global__ void scatter_kernel(const int* __restrict__ src, const int* __restrict__ dst,
                               int E, int n) {
    int i = blockIdx.x * blockDim.x + threadIdx.x;
    if (i >= E + n) return;
    int ss, dd;
    if (i < E) { ss = src[i]; dd = dst[i]; }
    else       { ss = dd = i - E; }
    int p = atomicAdd(&g_cur[dd], 1);
    g_csr[p] = ss;
}

// ------------------------- GEMM helpers -------------------------------------
#define LDAH 136
#define LDBH 272
#define LDBS 136
#define LDC  132
#define LDB3 56
#define LDC3 56
#define SM_DUAL ((128 * LDBH + 128 * LDAH) * 2)   // 104448 B
#define SM_SNGL ((128 * LDBS + 128 * LDAH) * 2)   // 69632 B
#define SM_40   ((128 * LDB3 + 128 * LDAH) * 2)   // 49152 B

__device__ __forceinline__ void cp16(__half* dst, const __half* src) {
    unsigned d = (unsigned)__cvta_generic_to_shared(dst);
    asm volatile("cp.async.cg.shared.global [%0], [%1], 16;\n" :: "r"(d), "l"(src));
}

__device__ __forceinline__ void store_xwh(int row, int lane, float4 xv) {
    __half2 ha = __floats2half2_rn(xv.x, xv.y);
    __half2 hb = __floats2half2_rn(xv.z, xv.w);
    uint2 p = make_uint2(*(unsigned*)&ha, *(unsigned*)&hb);
    *(uint2*)(g_xwh + (size_t)row * 128 + lane * 4) = p;
}

__device__ __forceinline__ void dots_epilogue(const float* Cs, int row0, int M,
                                              int wid, int lane,
                                              const float* a_s, const float* a_d) {
    float4 asv = *(const float4*)(a_s + lane * 4);
    float4 adv = *(const float4*)(a_d + lane * 4);
    #pragma unroll
    for (int rr = 0; rr < 8; rr++) {
        int r = wid * 8 + rr;
        int row = row0 + r;
        if (row >= M) break;
        float4 xv = *(const float4*)(Cs + (size_t)r * LDC + lane * 4);
        store_xwh(row, lane, xv);
        float ps = xv.x * asv.x + xv.y * asv.y + xv.z * asv.z + xv.w * asv.w;
        float pd = xv.x * adv.x + xv.y * adv.y + xv.z * adv.z + xv.w * adv.w;
        ps += __shfl_xor_sync(0xffffffffu, ps, 1);
        ps += __shfl_xor_sync(0xffffffffu, ps, 2);
        ps += __shfl_xor_sync(0xffffffffu, ps, 4);
        pd += __shfl_xor_sync(0xffffffffu, pd, 1);
        pd += __shfl_xor_sync(0xffffffffu, pd, 2);
        pd += __shfl_xor_sync(0xffffffffu, pd, 4);
        if ((lane & 7) == 0) {
            int h = lane >> 3;
            g_es[row * 4 + h] = ps;
            g_ed[row * 4 + h] = pd;
        }
    }
}

// ------------------------- dual WMMA GEMM (layer 1), A fp32->hi -------------
__global__ void __launch_bounds__(512, 1)
hgemm_dual(const float* __restrict__ A, float* __restrict__ C2,
           int M, int boff1, int boff2,
           const float* __restrict__ a_s, const float* __restrict__ a_d) {
    extern __shared__ __half sm[];
    __half* sBh = sm;
    __half* sAh = sBh + 128 * LDBH;
    int tid = threadIdx.x;
    int wid = tid >> 5, lane = tid & 31;
    int wm = wid & 3, wn = wid >> 2;
    int mi = wn >> 1, nsub = wn & 1;
    int row0 = blockIdx.x * 128;

    #pragma unroll
    for (int it = 0; it < 8; it++) {
        int idx = tid + it * 512;
        int c4 = idx & 15, row = (idx >> 4) & 127, mat = idx >> 11;
        const __half* src = g_Bh + (mat ? boff2 : boff1) + row * 128 + c4 * 8;
        __half* dst = sBh + row * LDBH + mat * 128 + c4 * 8;
        cp16(dst, src);
    }
    asm volatile("cp.async.commit_group;\n");

    #pragma unroll
    for (int it = 0; it < 16; it++) {
        int idx = tid + it * 512;
        int c2 = idx & 63, r = idx >> 6;
        int gr = row0 + r;
        float2 v = make_float2(0.f, 0.f);
        if (gr < M) v = *(const float2*)(A + (size_t)gr * 128 + c2 * 2);
        *(__half2*)(sAh + r * LDAH + c2 * 2) = __floats2half2_rn(v.x, v.y);
    }
    asm volatile("cp.async.wait_group 0;\n");
    __syncthreads();

    wmma::fragment<wmma::accumulator, 16, 16, 16, float> acc[2][4];
    #pragma unroll
    for (int i = 0; i < 2; i++)
        #pragma unroll
        for (int j = 0; j < 4; j++)
            wmma::fill_fragment(acc[i][j], 0.f);

    #pragma unroll
    for (int kk = 0; kk < 8; kk++) {
        wmma::fragment<wmma::matrix_a, 16, 16, 16, __half, wmma::row_major> ah[2];
        #pragma unroll
        for (int i = 0; i < 2; i++)
            wmma::load_matrix_sync(ah[i], sAh + (wm * 32 + i * 16) * LDAH + kk * 16, LDAH);
        #pragma unroll
        for (int j = 0; j < 4; j++) {
            wmma::fragment<wmma::matrix_b, 16, 16, 16, __half, wmma::row_major> bh;
            wmma::load_matrix_sync(bh, sBh + kk * 16 * LDBH + mi * 128 + nsub * 64 + j * 16, LDBH);
            #pragma unroll
            for (int i = 0; i < 2; i++)
                wmma::mma_sync(acc[i][j], ah[i], bh, acc[i][j]);
        }
    }

    __syncthreads();
    float* Cs = (float*)sm;
    #pragma unroll
    for (int i = 0; i < 2; i++) {
        int r = wm * 32 + i * 16;
        int gr = row0 + r;
        if (mi == 0) {
            #pragma unroll
            for (int j = 0; j < 4; j++)
                wmma::store_matrix_sync(Cs + (size_t)r * LDC + nsub * 64 + j * 16,
                                        acc[i][j], LDC, wmma::mem_row_major);
        } else if (gr < M) {
            #pragma unroll
            for (int j = 0; j < 4; j++)
                wmma::store_matrix_sync(C2 + (size_t)gr * 128 + nsub * 64 + j * 16,
                                        acc[i][j], 128, wmma::mem_row_major);
        }
    }
    __syncthreads();
    dots_epilogue(Cs, row0, M, wid, lane, a_s, a_d);
}

// ------------------------- single WMMA GEMM (layer 2), A fp16 direct --------
__global__ void __launch_bounds__(512, 2)
hgemm128(int M, int boff,
         const float* __restrict__ a_s, const float* __restrict__ a_d) {
    extern __shared__ __half sm[];
    __half* sBh = sm;
    __half* sAh = sBh + 128 * LDBS;
    int tid = threadIdx.x;
    int wid = tid >> 5, lane = tid & 31;
    int wm = wid & 3, wn = wid >> 2;
    int row0 = blockIdx.x * 128;

    // B: 2048 chunks; A (fp16 mirror): 2048 chunks — one async wave
    #pragma unroll
    for (int it = 0; it < 4; it++) {
        int idx = tid + it * 512;
        int c4 = idx & 15, row = idx >> 4;
        cp16(sBh + row * LDBS + c4 * 8, g_Bh + boff + row * 128 + c4 * 8);
    }
    #pragma unroll
    for (int it = 0; it < 4; it++) {
        int idx = tid + it * 512;
        int c4 = idx & 15, r = idx >> 4;
        cp16(sAh + r * LDAH + c4 * 8, g_hh + (size_t)(row0 + r) * 128 + c4 * 8);
    }
    asm volatile("cp.async.commit_group;\n");
    asm volatile("cp.async.wait_group 0;\n");
    __syncthreads();

    wmma::fragment<wmma::accumulator, 16, 16, 16, float> acc[2][2];
    #pragma unroll
    for (int i = 0; i < 2; i++)
        #pragma unroll
        for (int j = 0; j < 2; j++)
            wmma::fill_fragment(acc[i][j], 0.f);

    #pragma unroll
    for (int kk = 0; kk < 8; kk++) {
        wmma::fragment<wmma::matrix_a, 16, 16, 16, __half, wmma::row_major> ah[2];
        #pragma unroll
        for (int i = 0; i < 2; i++)
            wmma::load_matrix_sync(ah[i], sAh + (wm * 32 + i * 16) * LDAH + kk * 16, LDAH);
        #pragma unroll
        for (int j = 0; j < 2; j++) {
            wmma::fragment<wmma::matrix_b, 16, 16, 16, __half, wmma::row_major> bh;
            wmma::load_matrix_sync(bh, sBh + kk * 16 * LDBS + wn * 32 + j * 16, LDBS);
            #pragma unroll
            for (int i = 0; i < 2; i++)
                wmma::mma_sync(acc[i][j], ah[i], bh, acc[i][j]);
        }
    }

    __syncthreads();
    float* Cs = (float*)sm;
    #pragma unroll
    for (int i = 0; i < 2; i++) {
        int r = wm * 32 + i * 16;
        #pragma unroll
        for (int j = 0; j < 2; j++)
            wmma::store_matrix_sync(Cs + (size_t)r * LDC + wn * 32 + j * 16,
                                    acc[i][j], LDC, wmma::mem_row_major);
    }
    __syncthreads();
    dots_epilogue(Cs, row0, M, wid, lane, a_s, a_d);
}

// ------------------------- layer-3 WMMA GEMM, A fp16 direct -----------------
__global__ void __launch_bounds__(256, 2)
hgemm40(const float* __restrict__ a_s, const float* __restrict__ a_d,
        float* __restrict__ C, int M) {
    extern __shared__ __half sm[];
    __half* sBh = sm;
    __half* sAh = sBh + 128 * LDB3;
    int tid = threadIdx.x;
    int wid = tid >> 5, lane = tid & 31;
    int row0 = blockIdx.x * 128;

    #pragma unroll
    for (int it = 0; it < 3; it++) {
        int idx = tid + it * 256;
        int row = idx / 6, c = idx - row * 6;
        cp16(sBh + row * LDB3 + c * 8, g_B3h + row * 48 + c * 8);
    }
    #pragma unroll
    for (int it = 0; it < 8; it++) {
        int idx = tid + it * 256;
        int c4 = idx & 15, r = idx >> 4;
        cp16(sAh + r * LDAH + c4 * 8, g_hh + (size_t)(row0 + r) * 128 + c4 * 8);
    }
    asm volatile("cp.async.commit_group;\n");
    asm volatile("cp.async.wait_group 0;\n");
    __syncthreads();

    wmma::fragment<wmma::accumulator, 16, 16, 16, float> acc[3];
    #pragma unroll
    for (int j = 0; j < 3; j++) wmma::fill_fragment(acc[j], 0.f);

    #pragma unroll
    for (int kk = 0; kk < 8; kk++) {
        wmma::fragment<wmma::matrix_a, 16, 16, 16, __half, wmma::row_major> ah;
        wmma::load_matrix_sync(ah, sAh + (wid * 16) * LDAH + kk * 16, LDAH);
        #pragma unroll
        for (int j = 0; j < 3; j++) {
            wmma::fragment<wmma::matrix_b, 16, 16, 16, __half, wmma::row_major> bh;
            wmma::load_matrix_sync(bh, sBh + kk * 16 * LDB3 + j * 16, LDB3);
            wmma::mma_sync(acc[j], ah, bh, acc[j]);
        }
    }

    __syncthreads();
    float* Cs = (float*)sm;
    #pragma unroll
    for (int j = 0; j < 3; j++)
        wmma::store_matrix_sync(Cs + (size_t)(wid * 16) * LDC3 + j * 16,
                                acc[j], LDC3, wmma::mem_row_major);
    __syncthreads();

    float as1v = a_s[lane], ad1v = a_d[lane];
    float as2v = (lane < 8) ? a_s[32 + lane] : 0.f;
    float ad2v = (lane < 8) ? a_d[32 + lane] : 0.f;
    #pragma unroll
    for (int rr = 0; rr < 16; rr++) {
        int r = wid * 16 + rr;
        int row = row0 + r;
        if (row >= M) break;
        float x1 = Cs[(size_t)r * LDC3 + lane];
        float x2 = (lane < 8) ? Cs[(size_t)r * LDC3 + 32 + lane] : 0.f;
        C[(size_t)row * 40 + lane] = x1;
        if (lane < 8) C[(size_t)row * 40 + 32 + lane] = x2;
        float ps = x1 * as1v + x2 * as2v;
        float pd = x1 * ad1v + x2 * ad2v;
        #pragma unroll
        for (int o = 16; o; o >>= 1) {
            ps += __shfl_xor_sync(0xffffffffu, ps, o);
            pd += __shfl_xor_sync(0xffffffffu, pd, o);
        }
        if (lane == 0) { g_es[row] = ps; g_ed[row] = pd; }
    }
}

// ------------------------- fused GAT agg (fp16 gather + fp16 h mirror) ------
__global__ void agg128(const float* __restrict__ bias,
                       const float* __restrict__ gam, const float* __restrict__ bet,
                       const float* __restrict__ mean, const float* __restrict__ var,
                       const float* __restrict__ res, float* __restrict__ out, int n) {
    int node = blockIdx.x * 8 + (threadIdx.x >> 5);
    if (node >= n) return;
    int lane = threadIdx.x & 31;
    int head = lane >> 3, esub = lane & 7;
    float ed = g_ed[node * 4 + head];
    int s = g_off[node], e = g_off[node + 1];

    float m = -1e30f, den = 0.f;
    for (int base = s; base < e; base += 8) {
        int i = base + esub;
        bool val = i < e;
        int u = val ? g_csr[i] : 0;
        float ev = g_es[u * 4 + head] + ed;
        ev = ev > 0.f ? ev : 0.2f * ev;
        if (!val) ev = -1e30f;
        float gm = ev;
        gm = fmaxf(gm, __shfl_xor_sync(0xffffffffu, gm, 1));
        gm = fmaxf(gm, __shfl_xor_sync(0xffffffffu, gm, 2));
        gm = fmaxf(gm, __shfl_xor_sync(0xffffffffu, gm, 4));
        float nm = fmaxf(m, gm);
        float w = __expf(ev - nm);
        w += __shfl_xor_sync(0xffffffffu, w, 1);
        w += __shfl_xor_sync(0xffffffffu, w, 2);
        w += __shfl_xor_sync(0xffffffffu, w, 4);
        den = den * __expf(m - nm) + w;
        m = nm;
    }
    float rinv = 1.f / den;

    float4 acc = make_float4(0.f, 0.f, 0.f, 0.f);
    int i = s;
    for (; i + 1 < e; i += 2) {
        int u0 = g_csr[i];
        int u1 = g_csr[i + 1];
        float e0 = g_es[u0 * 4 + head] + ed;
        float e1 = g_es[u1 * 4 + head] + ed;
        e0 = e0 > 0.f ? e0 : 0.2f * e0;
        e1 = e1 > 0.f ? e1 : 0.2f * e1;
        float w0 = __expf(e0 - m);
        float w1 = __expf(e1 - m);
        uint2 p0 = *(const uint2*)(g_xwh + (size_t)u0 * 128 + lane * 4);
        uint2 p1 = *(const uint2*)(g_xwh + (size_t)u1 * 128 + lane * 4);
        float2 a0 = __half22float2(*(__half2*)&p0.x);
        float2 b0 = __half22float2(*(__half2*)&p0.y);
        float2 a1 = __half22float2(*(__half2*)&p1.x);
        float2 b1 = __half22float2(*(__half2*)&p1.y);
        acc.x += w0 * a0.x + w1 * a1.x;
        acc.y += w0 * a0.y + w1 * a1.y;
        acc.z += w0 * b0.x + w1 * b1.x;
        acc.w += w0 * b0.y + w1 * b1.y;
    }
    if (i < e) {
        int u0 = g_csr[i];
        float e0 = g_es[u0 * 4 + head] + ed;
        e0 = e0 > 0.f ? e0 : 0.2f * e0;
        float w0 = __expf(e0 - m);
        uint2 p0 = *(const uint2*)(g_xwh + (size_t)u0 * 128 + lane * 4);
        float2 a0 = __half22float2(*(__half2*)&p0.x);
        float2 b0 = __half22float2(*(__half2*)&p0.y);
        acc.x += w0 * a0.x; acc.y += w0 * a0.y;
        acc.z += w0 * b0.x; acc.w += w0 * b0.y;
    }

    int c = lane * 4;
    float4 b4 = *(const float4*)(bias + c);
    float4 g4 = *(const float4*)(gam + c);
    float4 e4 = *(const float4*)(bet + c);
    float4 m4 = *(const float4*)(mean + c);
    float4 v4 = *(const float4*)(var + c);
    float4 r4 = *(const float4*)(res + (size_t)node * 128 + c);
    float o0 = (acc.x * rinv + b4.x - m4.x) * rsqrtf(v4.x + GAT_EPS) * g4.x + e4.x + r4.x;
    float o1 = (acc.y * rinv + b4.y - m4.y) * rsqrtf(v4.y + GAT_EPS) * g4.y + e4.y + r4.y;
    float o2 = (acc.z * rinv + b4.z - m4.z) * rsqrtf(v4.z + GAT_EPS) * g4.z + e4.z + r4.z;
    float o3 = (acc.w * rinv + b4.w - m4.w) * rsqrtf(v4.w + GAT_EPS) * g4.w + e4.w + r4.w;
    float4 o = make_float4(o0 > 0.f ? o0 : expm1f(o0),
                           o1 > 0.f ? o1 : expm1f(o1),
                           o2 > 0.f ? o2 : expm1f(o2),
                           o3 > 0.f ? o3 : expm1f(o3));
    *(float4*)(out + (size_t)node * 128 + c) = o;
    // fp16 mirror for the next layer's GEMM A operand (same rounding as before)
    __half2 ha = __floats2half2_rn(o.x, o.y);
    __half2 hb = __floats2half2_rn(o.z, o.w);
    uint2 ph = make_uint2(*(unsigned*)&ha, *(unsigned*)&hb);
    *(uint2*)(g_hh + (size_t)node * 128 + c) = ph;
}

// ------------------------- layer-3 agg (fp32, two-pass) ---------------------
__global__ void agg40(const float* __restrict__ xw, const float* __restrict__ bias,
                      float* __restrict__ out, int n) {
    int node = blockIdx.x * 8 + (threadIdx.x >> 5);
    if (node >= n) return;
    int lane = threadIdx.x & 31;
    float ed = g_ed[node];
    int s = g_off[node], e = g_off[node + 1];

    float m = -1e30f, den = 0.f;
    for (int base = s; base < e; base += 32) {
        int i = base + lane;
        bool val = i < e;
        int u = val ? g_csr[i] : 0;
        float ev = g_es[u] + ed;
        ev = ev > 0.f ? ev : 0.2f * ev;
        if (!val) ev = -1e30f;
        float gm = ev;
        #pragma unroll
        for (int o = 16; o; o >>= 1) gm = fmaxf(gm, __shfl_xor_sync(0xffffffffu, gm, o));
        float nm = fmaxf(m, gm);
        float w = __expf(ev - nm);
        #pragma unroll
        for (int o = 16; o; o >>= 1) w += __shfl_xor_sync(0xffffffffu, w, o);
        den = den * __expf(m - nm) + w;
        m = nm;
    }
    float rinv = 1.f / den;

    float a1 = 0.f, a2 = 0.f;
    int u = g_csr[s];
    for (int i = s; i < e; i++) {
        int un = g_csr[i + 1];
        float ev = g_es[u] + ed;
        ev = ev > 0.f ? ev : 0.2f * ev;
        float w = __expf(ev - m);
        a1 += w * xw[(size_t)u * 40 + lane];
        if (lane < 8) a2 += w * xw[(size_t)u * 40 + 32 + lane];
        u = un;
    }
    out[(size_t)node * 40 + lane] = a1 * rinv + bias[lane];
    if (lane < 8) out[(size_t)node * 40 + 32 + lane] = a2 * rinv + bias[32 + lane];
}

// ------------------------- launch ------------------------------------------
extern "C" void kernel_launch(void* const* d_in, const int* in_sizes, int n_in,
                              void* d_out, int out_size) {
    const float* x    = (const float*)d_in[0];
    const int*   ei   = (const int*)  d_in[1];
    const float* W1   = (const float*)d_in[2];
    const float* as1  = (const float*)d_in[3];
    const float* ad1  = (const float*)d_in[4];
    const float* b1   = (const float*)d_in[5];
    const float* W2   = (const float*)d_in[6];
    const float* as2  = (const float*)d_in[7];
    const float* ad2  = (const float*)d_in[8];
    const float* b2   = (const float*)d_in[9];
    const float* W3   = (const float*)d_in[10];
    const float* as3  = (const float*)d_in[11];
    const float* ad3  = (const float*)d_in[12];
    const float* b3   = (const float*)d_in[13];
    const float* Wres = (const float*)d_in[14];
    const float* g1   = (const float*)d_in[15];
    const float* be1  = (const float*)d_in[16];
    const float* m1   = (const float*)d_in[17];
    const float* v1   = (const float*)d_in[18];
    const float* g2   = (const float*)d_in[19];
    const float* be2  = (const float*)d_in[20];
    const float* m2   = (const float*)d_in[21];
    const float* v2   = (const float*)d_in[22];

    int n = in_sizes[0] / 128;
    int E = in_sizes[1] / 2;
    const int* src = ei;
    const int* dst = ei + E;
    int tot = E + n;
    int nblk = (n + 1023) / 1024;

    float *p_aux, *p_h1, *p_h2, *p_xw3;
    cudaGetSymbolAddress((void**)&p_aux, g_aux);
    cudaGetSymbolAddress((void**)&p_h1,  g_h1);
    cudaGetSymbolAddress((void**)&p_h2,  g_h2);
    cudaGetSymbolAddress((void**)&p_xw3, g_xw3);

    cudaFuncSetAttribute(hgemm_dual, cudaFuncAttributeMaxDynamicSharedMemorySize, SM_DUAL);
    cudaFuncSetAttribute(hgemm128,   cudaFuncAttributeMaxDynamicSharedMemorySize, SM_SNGL);
    cudaFuncSetAttribute(hgemm40,    cudaFuncAttributeMaxDynamicSharedMemorySize, SM_40);

    int nb_gemm = (n + 127) / 128;
    int nb_warp = (n + 7) / 8;

    preB <<<216, 256>>>(W1, Wres, W2, W3);                                 // 1
    histo_kernel <<<(tot + 255) / 256, 256>>>(dst, E, n);                  // 2
    scan1_kernel <<<nblk, 256>>>(n);                                       // 3
    hgemm_dual <<<nb_gemm, 512, SM_DUAL>>>(x, p_aux, n, 0, 16384, as1, ad1); // 4 (profiled)
    scan23_kernel <<<(n + 255) / 256, 256>>>(nblk, n);                     // 5
    scatter_kernel <<<(tot + 255) / 256, 256>>>(src, dst, E, n);           // 6

    // ---- layer 1 aggregation (also emits fp16 h1 mirror) ----
    agg128 <<<nb_warp, 256>>>(b1, g1, be1, m1, v1, p_aux, p_h1, n);        // 7

    // ---- layer 2 ----
    hgemm128 <<<nb_gemm, 512, SM_SNGL>>>(n, 32768, as2, ad2);              // 8
    agg128 <<<nb_warp, 256>>>(b2, g2, be2, m2, v2, p_h1, p_h2, n);         // 9

    // ---- layer 3 ----
    hgemm40 <<<nb_gemm, 256, SM_40>>>(as3, ad3, p_xw3, n);                 // 10
    agg40  <<<nb_warp, 256>>>(p_xw3, b3, (float*)d_out, n);                // 11
}

// round 16
// speedup vs baseline: 1.7485x; 1.0088x over previous
#include <cuda_runtime.h>
#include <cuda_fp16.h>
#include <mma.h>
using namespace nvcuda;

// Problem constants
#define MAXN 50000
#define MAXE 400000
#define MAXTOT (MAXN + MAXE)
#define GAT_EPS 1e-5f

// ------------------------- scratch (device globals) ------------------------
__device__ float g_aux [MAXN * 128];
__device__ float g_h1  [MAXN * 128];
__device__ float g_h2  [MAXN * 128];
__device__ float g_xw3 [MAXN * 40];
__device__ float g_es  [MAXN * 4];
__device__ float g_ed  [MAXN * 4];
__device__ int   g_cnt [MAXN];
__device__ int   g_off [MAXN + 1];
__device__ int   g_cur [MAXN];
__device__ int   g_csr [MAXTOT + 8];
__device__ int   g_bsum[64];
__device__ __align__(16) __half g_Bh[3 * 16384];
__device__ __align__(16) __half g_B3h[128 * 48];
__device__ __align__(16) __half g_xwh[MAXN * 128];   // fp16 xw (gather operand)
__device__ __align__(16) __half g_hh [MAXN * 128];   // fp16 h (next-layer A operand)

// ------------------------- preB + histo (fused) ------------------------------
__global__ void preB_histo(const float* __restrict__ W1, const float* __restrict__ Wres,
                           const float* __restrict__ W2, const float* __restrict__ W3,
                           const int* __restrict__ dst, int E, int n) {
    int i = blockIdx.x * blockDim.x + threadIdx.x;
    if (i < 3 * 16384) {
        const float* W = (i < 16384) ? W1 : (i < 32768 ? Wres : W2);
        g_Bh[i] = __float2half_rn(W[i & 16383]);
    } else if (i < 3 * 16384 + 128 * 48) {
        int j = i - 3 * 16384;
        int k = j / 48, nn = j - k * 48;
        g_B3h[j] = (nn < 40) ? __float2half_rn(W3[k * 40 + nn]) : __half(0);
    }
    if (i < E + n) {
        int dd = (i < E) ? dst[i] : (i - E);
        atomicAdd(&g_cnt[dd], 1);   // g_cnt zeroed at init / reset by scan1
    }
}

// reads counts, resets them to 0 for the next graph replay
__global__ void scan1_kernel(int n) {
    __shared__ int wsum[8];
    int tid = threadIdx.x;
    int base = blockIdx.x * 1024 + tid * 4;
    int c0 = 0, c1 = 0, c2 = 0, c3 = 0;
    if (base + 0 < n) { c0 = g_cnt[base + 0]; g_cnt[base + 0] = 0; }
    if (base + 1 < n) { c1 = g_cnt[base + 1]; g_cnt[base + 1] = 0; }
    if (base + 2 < n) { c2 = g_cnt[base + 2]; g_cnt[base + 2] = 0; }
    if (base + 3 < n) { c3 = g_cnt[base + 3]; g_cnt[base + 3] = 0; }
    int t = c0 + c1 + c2 + c3;
    int lane = tid & 31, wid = tid >> 5;
    int incl = t;
    #pragma unroll
    for (int o = 1; o < 32; o <<= 1) {
        int v = __shfl_up_sync(0xffffffffu, incl, o);
        if (lane >= o) incl += v;
    }
    if (lane == 31) wsum[wid] = incl;
    __syncthreads();
    if (tid == 0) {
        int r = 0;
        #pragma unroll
        for (int k = 0; k < 8; k++) { int v = wsum[k]; wsum[k] = r; r += v; }
        g_bsum[blockIdx.x] = r;
    }
    __syncthreads();
    int run = wsum[wid] + incl - t;
    if (base + 0 < n) g_off[base + 0] = run; run += c0;
    if (base + 1 < n) g_off[base + 1] = run; run += c1;
    if (base + 2 < n) g_off[base + 2] = run; run += c2;
    if (base + 3 < n) g_off[base + 3] = run;
}

__global__ void scan23_kernel(int nb, int n) {
    __shared__ int sboff[64];
    __shared__ int sgrand;
    int tid = threadIdx.x;
    if (tid < 32) {
        int lane = tid;
        int v0 = (lane < nb) ? g_bsum[lane] : 0;
        int v1 = (32 + lane < nb) ? g_bsum[32 + lane] : 0;
        int i0 = v0;
        #pragma unroll
        for (int o = 1; o < 32; o <<= 1) {
            int q = __shfl_up_sync(0xffffffffu, i0, o);
            if (lane >= o) i0 += q;
        }
        int tot0 = __shfl_sync(0xffffffffu, i0, 31);
        int i1 = v1;
        #pragma unroll
        for (int o = 1; o < 32; o <<= 1) {
            int q = __shfl_up_sync(0xffffffffu, i1, o);
            if (lane >= o) i1 += q;
        }
        i1 += tot0;
        sboff[lane] = i0 - v0;
        sboff[32 + lane] = i1 - v1;
        if (lane == 31) sgrand = i1;
    }
    __syncthreads();
    int i = blockIdx.x * blockDim.x + tid;
    if (i < n) {
        int o = g_off[i] + sboff[i >> 10];
        g_off[i] = o;
        g_cur[i] = o;
    }
    if (blockIdx.x == 0 && tid == 0) g_off[n] = sgrand;
}

__global__ void scatter_kernel(const int* __restrict__ src, const int* __restrict__ dst,
                               int E, int n) {
    int i = blockIdx.x * blockDim.x + threadIdx.x;
    if (i >= E + n) return;
    int ss, dd;
    if (i < E) { ss = src[i]; dd = dst[i]; }
    else       { ss = dd = i - E; }
    int p = atomicAdd(&g_cur[dd], 1);
    g_csr[p] = ss;
}

// ------------------------- GEMM helpers -------------------------------------
#define LDAH 136
#define LDBS 136
#define LDC  132
#define LDB3 56
#define LDC3 56
#define SM_SNGL ((128 * LDBS + 128 * LDAH) * 2)   // 69632 B
#define SM_40   ((128 * LDB3 + 128 * LDAH) * 2)   // 49152 B

__device__ __forceinline__ void cp16(__half* dst, const __half* src) {
    unsigned d = (unsigned)__cvta_generic_to_shared(dst);
    asm volatile("cp.async.cg.shared.global [%0], [%1], 16;\n" :: "r"(d), "l"(src));
}

__device__ __forceinline__ void store_xwh(int row, int lane, float4 xv) {
    __half2 ha = __floats2half2_rn(xv.x, xv.y);
    __half2 hb = __floats2half2_rn(xv.z, xv.w);
    uint2 p = make_uint2(*(unsigned*)&ha, *(unsigned*)&hb);
    *(uint2*)(g_xwh + (size_t)row * 128 + lane * 4) = p;
}

__device__ __forceinline__ void dots_epilogue(const float* Cs, int row0, int M,
                                              int wid, int lane,
                                              const float* a_s, const float* a_d) {
    float4 asv = *(const float4*)(a_s + lane * 4);
    float4 adv = *(const float4*)(a_d + lane * 4);
    #pragma unroll
    for (int rr = 0; rr < 8; rr++) {
        int r = wid * 8 + rr;
        int row = row0 + r;
        if (row >= M) break;
        float4 xv = *(const float4*)(Cs + (size_t)r * LDC + lane * 4);
        store_xwh(row, lane, xv);
        float ps = xv.x * asv.x + xv.y * asv.y + xv.z * asv.z + xv.w * asv.w;
        float pd = xv.x * adv.x + xv.y * adv.y + xv.z * adv.z + xv.w * adv.w;
        ps += __shfl_xor_sync(0xffffffffu, ps, 1);
        ps += __shfl_xor_sync(0xffffffffu, ps, 2);
        ps += __shfl_xor_sync(0xffffffffu, ps, 4);
        pd += __shfl_xor_sync(0xffffffffu, pd, 1);
        pd += __shfl_xor_sync(0xffffffffu, pd, 2);
        pd += __shfl_xor_sync(0xffffffffu, pd, 4);
        if ((lane & 7) == 0) {
            int h = lane >> 3;
            g_es[row * 4 + h] = ps;
            g_ed[row * 4 + h] = pd;
        }
    }
}

// ------------------------- GEMM (layer 1): fp32 A, 128 cols ------------------
// a_s != null -> dots + fp16 mirror (xw path); Cout != null -> fp32 output (aux).
__global__ void __launch_bounds__(512, 2)
hgemm128x(const float* __restrict__ A, int boff, float* __restrict__ Cout,
          const float* __restrict__ a_s, const float* __restrict__ a_d, int M) {
    extern __shared__ __half sm[];
    __half* sBh = sm;
    __half* sAh = sBh + 128 * LDBS;
    int tid = threadIdx.x;
    int wid = tid >> 5, lane = tid & 31;
    int wm = wid & 3, wn = wid >> 2;
    int row0 = blockIdx.x * 128;

    #pragma unroll
    for (int it = 0; it < 4; it++) {
        int idx = tid + it * 512;
        int c4 = idx & 15, row = idx >> 4;
        cp16(sBh + row * LDBS + c4 * 8, g_Bh + boff + row * 128 + c4 * 8);
    }
    asm volatile("cp.async.commit_group;\n");

    #pragma unroll
    for (int it = 0; it < 16; it++) {
        int idx = tid + it * 512;
        int c2 = idx & 63, r = idx >> 6;
        int gr = row0 + r;
        float2 v = make_float2(0.f, 0.f);
        if (gr < M) v = *(const float2*)(A + (size_t)gr * 128 + c2 * 2);
        *(__half2*)(sAh + r * LDAH + c2 * 2) = __floats2half2_rn(v.x, v.y);
    }
    asm volatile("cp.async.wait_group 0;\n");
    __syncthreads();

    wmma::fragment<wmma::accumulator, 16, 16, 16, float> acc[2][2];
    #pragma unroll
    for (int i = 0; i < 2; i++)
        #pragma unroll
        for (int j = 0; j < 2; j++)
            wmma::fill_fragment(acc[i][j], 0.f);

    #pragma unroll
    for (int kk = 0; kk < 8; kk++) {
        wmma::fragment<wmma::matrix_a, 16, 16, 16, __half, wmma::row_major> ah[2];
        #pragma unroll
        for (int i = 0; i < 2; i++)
            wmma::load_matrix_sync(ah[i], sAh + (wm * 32 + i * 16) * LDAH + kk * 16, LDAH);
        #pragma unroll
        for (int j = 0; j < 2; j++) {
            wmma::fragment<wmma::matrix_b, 16, 16, 16, __half, wmma::row_major> bh;
            wmma::load_matrix_sync(bh, sBh + kk * 16 * LDBS + wn * 32 + j * 16, LDBS);
            #pragma unroll
            for (int i = 0; i < 2; i++)
                wmma::mma_sync(acc[i][j], ah[i], bh, acc[i][j]);
        }
    }

    __syncthreads();
    float* Cs = (float*)sm;   // 128 x LDC fp32 = 67.6KB <= 69.6KB
    #pragma unroll
    for (int i = 0; i < 2; i++) {
        int r = wm * 32 + i * 16;
        #pragma unroll
        for (int j = 0; j < 2; j++)
            wmma::store_matrix_sync(Cs + (size_t)r * LDC + wn * 32 + j * 16,
                                    acc[i][j], LDC, wmma::mem_row_major);
    }
    __syncthreads();
    if (a_s) dots_epilogue(Cs, row0, M, wid, lane, a_s, a_d);
    if (Cout) {
        #pragma unroll
        for (int it = 0; it < 8; it++) {
            int idx = tid + it * 512;           // 4096 float4
            int r = idx >> 5, c4 = idx & 31;
            int gr = row0 + r;
            if (gr < M)
                *(float4*)(Cout + (size_t)gr * 128 + c4 * 4) =
                    *(const float4*)(Cs + (size_t)r * LDC + c4 * 4);
        }
    }
}

// ------------------------- GEMM (layer 2): fp16 A direct --------------------
__global__ void __launch_bounds__(512, 2)
hgemm128(int M, int boff,
         const float* __restrict__ a_s, const float* __restrict__ a_d) {
    extern __shared__ __half sm[];
    __half* sBh = sm;
    __half* sAh = sBh + 128 * LDBS;
    int tid = threadIdx.x;
    int wid = tid >> 5, lane = tid & 31;
    int wm = wid & 3, wn = wid >> 2;
    int row0 = blockIdx.x * 128;

    #pragma unroll
    for (int it = 0; it < 4; it++) {
        int idx = tid + it * 512;
        int c4 = idx & 15, row = idx >> 4;
        cp16(sBh + row * LDBS + c4 * 8, g_Bh + boff + row * 128 + c4 * 8);
    }
    #pragma unroll
    for (int it = 0; it < 4; it++) {
        int idx = tid + it * 512;
        int c4 = idx & 15, r = idx >> 4;
        cp16(sAh + r * LDAH + c4 * 8, g_hh + (size_t)(row0 + r) * 128 + c4 * 8);
    }
    asm volatile("cp.async.commit_group;\n");
    asm volatile("cp.async.wait_group 0;\n");
    __syncthreads();

    wmma::fragment<wmma::accumulator, 16, 16, 16, float> acc[2][2];
    #pragma unroll
    for (int i = 0; i < 2; i++)
        #pragma unroll
        for (int j = 0; j < 2; j++)
            wmma::fill_fragment(acc[i][j], 0.f);

    #pragma unroll
    for (int kk = 0; kk < 8; kk++) {
        wmma::fragment<wmma::matrix_a, 16, 16, 16, __half, wmma::row_major> ah[2];
        #pragma unroll
        for (int i = 0; i < 2; i++)
            wmma::load_matrix_sync(ah[i], sAh + (wm * 32 + i * 16) * LDAH + kk * 16, LDAH);
        #pragma unroll
        for (int j = 0; j < 2; j++) {
            wmma::fragment<wmma::matrix_b, 16, 16, 16, __half, wmma::row_major> bh;
            wmma::load_matrix_sync(bh, sBh + kk * 16 * LDBS + wn * 32 + j * 16, LDBS);
            #pragma unroll
            for (int i = 0; i < 2; i++)
                wmma::mma_sync(acc[i][j], ah[i], bh, acc[i][j]);
        }
    }

    __syncthreads();
    float* Cs = (float*)sm;
    #pragma unroll
    for (int i = 0; i < 2; i++) {
        int r = wm * 32 + i * 16;
        #pragma unroll
        for (int j = 0; j < 2; j++)
            wmma::store_matrix_sync(Cs + (size_t)r * LDC + wn * 32 + j * 16,
                                    acc[i][j], LDC, wmma::mem_row_major);
    }
    __syncthreads();
    dots_epilogue(Cs, row0, M, wid, lane, a_s, a_d);
}

// ------------------------- layer-3 WMMA GEMM, A fp16 direct -----------------
__global__ void __launch_bounds__(256, 2)
hgemm40(const float* __restrict__ a_s, const float* __restrict__ a_d,
        float* __restrict__ C, int M) {
    extern __shared__ __half sm[];
    __half* sBh = sm;
    __half* sAh = sBh + 128 * LDB3;
    int tid = threadIdx.x;
    int wid = tid >> 5, lane = tid & 31;
    int row0 = blockIdx.x * 128;

    #pragma unroll
    for (int it = 0; it < 3; it++) {
        int idx = tid + it * 256;
        int row = idx / 6, c = idx - row * 6;
        cp16(sBh + row * LDB3 + c * 8, g_B3h + row * 48 + c * 8);
    }
    #pragma unroll
    for (int it = 0; it < 8; it++) {
        int idx = tid + it * 256;
        int c4 = idx & 15, r = idx >> 4;
        cp16(sAh + r * LDAH + c4 * 8, g_hh + (size_t)(row0 + r) * 128 + c4 * 8);
    }
    asm volatile("cp.async.commit_group;\n");
    asm volatile("cp.async.wait_group 0;\n");
    __syncthreads();

    wmma::fragment<wmma::accumulator, 16, 16, 16, float> acc[3];
    #pragma unroll
    for (int j = 0; j < 3; j++) wmma::fill_fragment(acc[j], 0.f);

    #pragma unroll
    for (int kk = 0; kk < 8; kk++) {
        wmma::fragment<wmma::matrix_a, 16, 16, 16, __half, wmma::row_major> ah;
        wmma::load_matrix_sync(ah, sAh + (wid * 16) * LDAH + kk * 16, LDAH);
        #pragma unroll
        for (int j = 0; j < 3; j++) {
            wmma::fragment<wmma::matrix_b, 16, 16, 16, __half, wmma::row_major> bh;
            wmma::load_matrix_sync(bh, sBh + kk * 16 * LDB3 + j * 16, LDB3);
            wmma::mma_sync(acc[j], ah, bh, acc[j]);
        }
    }

    __syncthreads();
    float* Cs = (float*)sm;
    #pragma unroll
    for (int j = 0; j < 3; j++)
        wmma::store_matrix_sync(Cs + (size_t)(wid * 16) * LDC3 + j * 16,
                                acc[j], LDC3, wmma::mem_row_major);
    __syncthreads();

    float as1v = a_s[lane], ad1v = a_d[lane];
    float as2v = (lane < 8) ? a_s[32 + lane] : 0.f;
    float ad2v = (lane < 8) ? a_d[32 + lane] : 0.f;
    #pragma unroll
    for (int rr = 0; rr < 16; rr++) {
        int r = wid * 16 + rr;
        int row = row0 + r;
        if (row >= M) break;
        float x1 = Cs[(size_t)r * LDC3 + lane];
        float x2 = (lane < 8) ? Cs[(size_t)r * LDC3 + 32 + lane] : 0.f;
        C[(size_t)row * 40 + lane] = x1;
        if (lane < 8) C[(size_t)row * 40 + 32 + lane] = x2;
        float ps = x1 * as1v + x2 * as2v;
        float pd = x1 * ad1v + x2 * ad2v;
        #pragma unroll
        for (int o = 16; o; o >>= 1) {
            ps += __shfl_xor_sync(0xffffffffu, ps, o);
            pd += __shfl_xor_sync(0xffffffffu, pd, o);
        }
        if (lane == 0) { g_es[row] = ps; g_ed[row] = pd; }
    }
}

// ------------------------- fused GAT agg (fp16 gather, 4x unroll) -----------
__global__ void agg128(const float* __restrict__ bias,
                       const float* __restrict__ gam, const float* __restrict__ bet,
                       const float* __restrict__ mean, const float* __restrict__ var,
                       const float* __restrict__ res, float* __restrict__ out, int n) {
    int node = blockIdx.x * 8 + (threadIdx.x >> 5);
    if (node >= n) return;
    int lane = threadIdx.x & 31;
    int head = lane >> 3, esub = lane & 7;
    float ed = g_ed[node * 4 + head];
    int s = g_off[node], e = g_off[node + 1];

    float m = -1e30f, den = 0.f;
    for (int base = s; base < e; base += 8) {
        int i = base + esub;
        bool val = i < e;
        int u = val ? g_csr[i] : 0;
        float ev = g_es[u * 4 + head] + ed;
        ev = ev > 0.f ? ev : 0.2f * ev;
        if (!val) ev = -1e30f;
        float gm = ev;
        gm = fmaxf(gm, __shfl_xor_sync(0xffffffffu, gm, 1));
        gm = fmaxf(gm, __shfl_xor_sync(0xffffffffu, gm, 2));
        gm = fmaxf(gm, __shfl_xor_sync(0xffffffffu, gm, 4));
        float nm = fmaxf(m, gm);
        float w = __expf(ev - nm);
        w += __shfl_xor_sync(0xffffffffu, w, 1);
        w += __shfl_xor_sync(0xffffffffu, w, 2);
        w += __shfl_xor_sync(0xffffffffu, w, 4);
        den = den * __expf(m - nm) + w;
        m = nm;
    }
    float rinv = 1.f / den;

    float4 acc = make_float4(0.f, 0.f, 0.f, 0.f);
    int i = s;
    for (; i + 3 < e; i += 4) {
        int u0 = g_csr[i], u1 = g_csr[i + 1], u2 = g_csr[i + 2], u3 = g_csr[i + 3];
        float e0 = g_es[u0 * 4 + head] + ed;
        float e1 = g_es[u1 * 4 + head] + ed;
        float e2 = g_es[u2 * 4 + head] + ed;
        float e3 = g_es[u3 * 4 + head] + ed;
        e0 = e0 > 0.f ? e0 : 0.2f * e0;
        e1 = e1 > 0.f ? e1 : 0.2f * e1;
        e2 = e2 > 0.f ? e2 : 0.2f * e2;
        e3 = e3 > 0.f ? e3 : 0.2f * e3;
        float w0 = __expf(e0 - m), w1 = __expf(e1 - m);
        float w2 = __expf(e2 - m), w3 = __expf(e3 - m);
        uint2 p0 = *(const uint2*)(g_xwh + (size_t)u0 * 128 + lane * 4);
        uint2 p1 = *(const uint2*)(g_xwh + (size_t)u1 * 128 + lane * 4);
        uint2 p2 = *(const uint2*)(g_xwh + (size_t)u2 * 128 + lane * 4);
        uint2 p3 = *(const uint2*)(g_xwh + (size_t)u3 * 128 + lane * 4);
        float2 a0 = __half22float2(*(__half2*)&p0.x), b0 = __half22float2(*(__half2*)&p0.y);
        float2 a1 = __half22float2(*(__half2*)&p1.x), b1 = __half22float2(*(__half2*)&p1.y);
        float2 a2 = __half22float2(*(__half2*)&p2.x), b2 = __half22float2(*(__half2*)&p2.y);
        float2 a3 = __half22float2(*(__half2*)&p3.x), b3 = __half22float2(*(__half2*)&p3.y);
        acc.x += w0 * a0.x + w1 * a1.x + w2 * a2.x + w3 * a3.x;
        acc.y += w0 * a0.y + w1 * a1.y + w2 * a2.y + w3 * a3.y;
        acc.z += w0 * b0.x + w1 * b1.x + w2 * b2.x + w3 * b3.x;
        acc.w += w0 * b0.y + w1 * b1.y + w2 * b2.y + w3 * b3.y;
    }
    for (; i < e; i++) {
        int u0 = g_csr[i];
        float e0 = g_es[u0 * 4 + head] + ed;
        e0 = e0 > 0.f ? e0 : 0.2f * e0;
        float w0 = __expf(e0 - m);
        uint2 p0 = *(const uint2*)(g_xwh + (size_t)u0 * 128 + lane * 4);
        float2 a0 = __half22float2(*(__half2*)&p0.x);
        float2 b0 = __half22float2(*(__half2*)&p0.y);
        acc.x += w0 * a0.x; acc.y += w0 * a0.y;
        acc.z += w0 * b0.x; acc.w += w0 * b0.y;
    }

    int c = lane * 4;
    float4 b4 = *(const float4*)(bias + c);
    float4 g4 = *(const float4*)(gam + c);
    float4 e4 = *(const float4*)(bet + c);
    float4 m4 = *(const float4*)(mean + c);
    float4 v4 = *(const float4*)(var + c);
    float4 r4 = *(const float4*)(res + (size_t)node * 128 + c);
    float o0 = (acc.x * rinv + b4.x - m4.x) * rsqrtf(v4.x + GAT_EPS) * g4.x + e4.x + r4.x;
    float o1 = (acc.y * rinv + b4.y - m4.y) * rsqrtf(v4.y + GAT_EPS) * g4.y + e4.y + r4.y;
    float o2 = (acc.z * rinv + b4.z - m4.z) * rsqrtf(v4.z + GAT_EPS) * g4.z + e4.z + r4.z;
    float o3 = (acc.w * rinv + b4.w - m4.w) * rsqrtf(v4.w + GAT_EPS) * g4.w + e4.w + r4.w;
    float4 o = make_float4(o0 > 0.f ? o0 : expm1f(o0),
                           o1 > 0.f ? o1 : expm1f(o1),
                           o2 > 0.f ? o2 : expm1f(o2),
                           o3 > 0.f ? o3 : expm1f(o3));
    *(float4*)(out + (size_t)node * 128 + c) = o;
    __half2 ha = __floats2half2_rn(o.x, o.y);
    __half2 hb = __floats2half2_rn(o.z, o.w);
    uint2 ph = make_uint2(*(unsigned*)&ha, *(unsigned*)&hb);
    *(uint2*)(g_hh + (size_t)node * 128 + c) = ph;
}

// ------------------------- layer-3 agg (fp32, two-pass) ---------------------
__global__ void agg40(const float* __restrict__ xw, const float* __restrict__ bias,
                      float* __restrict__ out, int n) {
    int node = blockIdx.x * 8 + (threadIdx.x >> 5);
    if (node >= n) return;
    int lane = threadIdx.x & 31;
    float ed = g_ed[node];
    int s = g_off[node], e = g_off[node + 1];

    float m = -1e30f, den = 0.f;
    for (int base = s; base < e; base += 32) {
        int i = base + lane;
        bool val = i < e;
        int u = val ? g_csr[i] : 0;
        float ev = g_es[u] + ed;
        ev = ev > 0.f ? ev : 0.2f * ev;
        if (!val) ev = -1e30f;
        float gm = ev;
        #pragma unroll
        for (int o = 16; o; o >>= 1) gm = fmaxf(gm, __shfl_xor_sync(0xffffffffu, gm, o));
        float nm = fmaxf(m, gm);
        float w = __expf(ev - nm);
        #pragma unroll
        for (int o = 16; o; o >>= 1) w += __shfl_xor_sync(0xffffffffu, w, o);
        den = den * __expf(m - nm) + w;
        m = nm;
    }
    float rinv = 1.f / den;

    float a1 = 0.f, a2 = 0.f;
    int u = g_csr[s];
    for (int i = s; i < e; i++) {
        int un = g_csr[i + 1];
        float ev = g_es[u] + ed;
        ev = ev > 0.f ? ev : 0.2f * ev;
        float w = __expf(ev - m);
        a1 += w * xw[(size_t)u * 40 + lane];
        if (lane < 8) a2 += w * xw[(size_t)u * 40 + 32 + lane];
        u = un;
    }
    out[(size_t)node * 40 + lane] = a1 * rinv + bias[lane];
    if (lane < 8) out[(size_t)node * 40 + 32 + lane] = a2 * rinv + bias[32 + lane];
}

// ------------------------- launch ------------------------------------------
extern "C" void kernel_launch(void* const* d_in, const int* in_sizes, int n_in,
                              void* d_out, int out_size) {
    const float* x    = (const float*)d_in[0];
    const int*   ei   = (const int*)  d_in[1];
    const float* W1   = (const float*)d_in[2];
    const float* as1  = (const float*)d_in[3];
    const float* ad1  = (const float*)d_in[4];
    const float* b1   = (const float*)d_in[5];
    const float* W2   = (const float*)d_in[6];
    const float* as2  = (const float*)d_in[7];
    const float* ad2  = (const float*)d_in[8];
    const float* b2   = (const float*)d_in[9];
    const float* W3   = (const float*)d_in[10];
    const float* as3  = (const float*)d_in[11];
    const float* ad3  = (const float*)d_in[12];
    const float* b3   = (const float*)d_in[13];
    const float* Wres = (const float*)d_in[14];
    const float* g1   = (const float*)d_in[15];
    const float* be1  = (const float*)d_in[16];
    const float* m1   = (const float*)d_in[17];
    const float* v1   = (const float*)d_in[18];
    const float* g2   = (const float*)d_in[19];
    const float* be2  = (const float*)d_in[20];
    const float* m2   = (const float*)d_in[21];
    const float* v2   = (const float*)d_in[22];

    int n = in_sizes[0] / 128;
    int E = in_sizes[1] / 2;
    const int* src = ei;
    const int* dst = ei + E;
    int tot = E + n;
    int nblk = (n + 1023) / 1024;

    float *p_aux, *p_h1, *p_h2, *p_xw3;
    cudaGetSymbolAddress((void**)&p_aux, g_aux);
    cudaGetSymbolAddress((void**)&p_h1,  g_h1);
    cudaGetSymbolAddress((void**)&p_h2,  g_h2);
    cudaGetSymbolAddress((void**)&p_xw3, g_xw3);

    cudaFuncSetAttribute(hgemm128x, cudaFuncAttributeMaxDynamicSharedMemorySize, SM_SNGL);
    cudaFuncSetAttribute(hgemm128,  cudaFuncAttributeMaxDynamicSharedMemorySize, SM_SNGL);
    cudaFuncSetAttribute(hgemm40,   cudaFuncAttributeMaxDynamicSharedMemorySize, SM_40);

    int nb_gemm = (n + 127) / 128;
    int nb_warp = (n + 7) / 8;
    int nb_pre  = (tot + 255) / 256;   // covers weights (55296) too

    preB_histo <<<nb_pre, 256>>>(W1, Wres, W2, W3, dst, E, n);             // 1
    scan1_kernel <<<nblk, 256>>>(n);                                       // 2
    hgemm128x <<<nb_gemm, 512, SM_SNGL>>>(x, 0, nullptr, as1, ad1, n);     // 3 (xw + dots)
    hgemm128x <<<nb_gemm, 512, SM_SNGL>>>(x, 16384, p_aux, nullptr, nullptr, n); // 4 (aux, profiled)
    scan23_kernel <<<(n + 255) / 256, 256>>>(nblk, n);                     // 5
    scatter_kernel <<<(tot + 255) / 256, 256>>>(src, dst, E, n);           // 6

    // ---- layer 1 aggregation (emits fp16 h1 mirror) ----
    agg128 <<<nb_warp, 256>>>(b1, g1, be1, m1, v1, p_aux, p_h1, n);        // 7

    // ---- layer 2 ----
    hgemm128 <<<nb_gemm, 512, SM_SNGL>>>(n, 32768, as2, ad2);              // 8
    agg128 <<<nb_warp, 256>>>(b2, g2, be2, m2, v2, p_h1, p_h2, n);         // 9

    // ---- layer 3 ----
    hgemm40 <<<nb_gemm, 256, SM_40>>>(as3, ad3, p_xw3, n);                 // 10
    agg40  <<<nb_warp, 256>>>(p_xw3, b3, (float*)d_out, n);                // 11
}

// round 17
// speedup vs baseline: 1.7751x; 1.0152x over previous
#include <cuda_runtime.h>
#include <cuda_fp16.h>
#include <mma.h>
using namespace nvcuda;

// Problem constants
#define MAXN 50000
#define MAXE 400000
#define MAXTOT (MAXN + MAXE)
#define GAT_EPS 1e-5f

// ------------------------- scratch (device globals) ------------------------
__device__ float g_aux [MAXN * 128];
__device__ float g_h1  [MAXN * 128];
__device__ float g_h2  [MAXN * 128];
__device__ float g_xw3 [MAXN * 40];
__device__ float g_es  [MAXN * 4];
__device__ float g_ed  [MAXN * 4];
__device__ int   g_cnt [MAXN];
__device__ int   g_off [MAXN + 1];
__device__ int   g_cur [MAXN];
__device__ int   g_csr [MAXTOT + 8];
__device__ int   g_bsum[64];
__device__ __align__(16) __half g_Bh[3 * 16384];
__device__ __align__(16) __half g_B3h[128 * 48];
__device__ __align__(16) __half g_xwh[MAXN * 128];   // fp16 xw (gather operand)
__device__ __align__(16) __half g_hh [MAXN * 128];   // fp16 h (next-layer A operand)

// ------------------------- preB + histo (fused) ------------------------------
__global__ void preB_histo(const float* __restrict__ W1, const float* __restrict__ Wres,
                           const float* __restrict__ W2, const float* __restrict__ W3,
                           const int* __restrict__ dst, int E, int n) {
    int i = blockIdx.x * blockDim.x + threadIdx.x;
    if (i < 3 * 16384) {
        const float* W = (i < 16384) ? W1 : (i < 32768 ? Wres : W2);
        g_Bh[i] = __float2half_rn(W[i & 16383]);
    } else if (i < 3 * 16384 + 128 * 48) {
        int j = i - 3 * 16384;
        int k = j / 48, nn = j - k * 48;
        g_B3h[j] = (nn < 40) ? __float2half_rn(W3[k * 40 + nn]) : __half(0);
    }
    if (i < E + n) {
        int dd = (i < E) ? dst[i] : (i - E);
        atomicAdd(&g_cnt[dd], 1);   // g_cnt zeroed at init / reset by scan1
    }
}

// reads counts, resets them to 0 for the next graph replay
__global__ void scan1_kernel(int n) {
    __shared__ int wsum[8];
    int tid = threadIdx.x;
    int base = blockIdx.x * 1024 + tid * 4;
    int c0 = 0, c1 = 0, c2 = 0, c3 = 0;
    if (base + 0 < n) { c0 = g_cnt[base + 0]; g_cnt[base + 0] = 0; }
    if (base + 1 < n) { c1 = g_cnt[base + 1]; g_cnt[base + 1] = 0; }
    if (base + 2 < n) { c2 = g_cnt[base + 2]; g_cnt[base + 2] = 0; }
    if (base + 3 < n) { c3 = g_cnt[base + 3]; g_cnt[base + 3] = 0; }
    int t = c0 + c1 + c2 + c3;
    int lane = tid & 31, wid = tid >> 5;
    int incl = t;
    #pragma unroll
    for (int o = 1; o < 32; o <<= 1) {
        int v = __shfl_up_sync(0xffffffffu, incl, o);
        if (lane >= o) incl += v;
    }
    if (lane == 31) wsum[wid] = incl;
    __syncthreads();
    if (tid == 0) {
        int r = 0;
        #pragma unroll
        for (int k = 0; k < 8; k++) { int v = wsum[k]; wsum[k] = r; r += v; }
        g_bsum[blockIdx.x] = r;
    }
    __syncthreads();
    int run = wsum[wid] + incl - t;
    if (base + 0 < n) g_off[base + 0] = run; run += c0;
    if (base + 1 < n) g_off[base + 1] = run; run += c1;
    if (base + 2 < n) g_off[base + 2] = run; run += c2;
    if (base + 3 < n) g_off[base + 3] = run;
}

__global__ void scan23_kernel(int nb, int n) {
    __shared__ int sboff[64];
    __shared__ int sgrand;
    int tid = threadIdx.x;
    if (tid < 32) {
        int lane = tid;
        int v0 = (lane < nb) ? g_bsum[lane] : 0;
        int v1 = (32 + lane < nb) ? g_bsum[32 + lane] : 0;
        int i0 = v0;
        #pragma unroll
        for (int o = 1; o < 32; o <<= 1) {
            int q = __shfl_up_sync(0xffffffffu, i0, o);
            if (lane >= o) i0 += q;
        }
        int tot0 = __shfl_sync(0xffffffffu, i0, 31);
        int i1 = v1;
        #pragma unroll
        for (int o = 1; o < 32; o <<= 1) {
            int q = __shfl_up_sync(0xffffffffu, i1, o);
            if (lane >= o) i1 += q;
        }
        i1 += tot0;
        sboff[lane] = i0 - v0;
        sboff[32 + lane] = i1 - v1;
        if (lane == 31) sgrand = i1;
    }
    __syncthreads();
    int i = blockIdx.x * blockDim.x + tid;
    if (i < n) {
        int o = g_off[i] + sboff[i >> 10];
        g_off[i] = o;
        g_cur[i] = o;
    }
    if (blockIdx.x == 0 && tid == 0) g_off[n] = sgrand;
}

__global__ void scatter_kernel(const int* __restrict__ src, const int* __restrict__ dst,
                               int E, int n) {
    int i = blockIdx.x * blockDim.x + threadIdx.x;
    if (i >= E + n) return;
    int ss, dd;
    if (i < E) { ss = src[i]; dd = dst[i]; }
    else       { ss = dd = i - E; }
    int p = atomicAdd(&g_cur[dd], 1);
    g_csr[p] = ss;
}

// ------------------------- GEMM helpers -------------------------------------
#define LDAH 136
#define LDBS 136
#define LDC  132
#define LDB3 56
#define LDC3 56
#define SM_SNGL ((128 * LDBS + 128 * LDAH) * 2)   // 69632 B
#define SM_40   ((128 * LDB3 + 128 * LDAH) * 2)   // 49152 B

__device__ __forceinline__ void cp16(__half* dst, const __half* src) {
    unsigned d = (unsigned)__cvta_generic_to_shared(dst);
    asm volatile("cp.async.cg.shared.global [%0], [%1], 16;\n" :: "r"(d), "l"(src));
}

__device__ __forceinline__ void store_xwh(int row, int lane, float4 xv) {
    __half2 ha = __floats2half2_rn(xv.x, xv.y);
    __half2 hb = __floats2half2_rn(xv.z, xv.w);
    uint2 p = make_uint2(*(unsigned*)&ha, *(unsigned*)&hb);
    *(uint2*)(g_xwh + (size_t)row * 128 + lane * 4) = p;
}

__device__ __forceinline__ void dots_epilogue(const float* Cs, int row0, int M,
                                              int wid, int lane,
                                              const float* a_s, const float* a_d) {
    float4 asv = *(const float4*)(a_s + lane * 4);
    float4 adv = *(const float4*)(a_d + lane * 4);
    #pragma unroll
    for (int rr = 0; rr < 8; rr++) {
        int r = wid * 8 + rr;
        int row = row0 + r;
        if (row >= M) break;
        float4 xv = *(const float4*)(Cs + (size_t)r * LDC + lane * 4);
        store_xwh(row, lane, xv);
        float ps = xv.x * asv.x + xv.y * asv.y + xv.z * asv.z + xv.w * asv.w;
        float pd = xv.x * adv.x + xv.y * adv.y + xv.z * adv.z + xv.w * adv.w;
        ps += __shfl_xor_sync(0xffffffffu, ps, 1);
        ps += __shfl_xor_sync(0xffffffffu, ps, 2);
        ps += __shfl_xor_sync(0xffffffffu, ps, 4);
        pd += __shfl_xor_sync(0xffffffffu, pd, 1);
        pd += __shfl_xor_sync(0xffffffffu, pd, 2);
        pd += __shfl_xor_sync(0xffffffffu, pd, 4);
        if ((lane & 7) == 0) {
            int h = lane >> 3;
            g_es[row * 4 + h] = ps;
            g_ed[row * 4 + h] = pd;
        }
    }
}

// ------------------------- layer-1 GEMM: both W1 and Wres in one grid -------
// blocks [0, nb): xw path (B = W1, dots + fp16 mirror)
// blocks [nb, 2nb): aux path (B = Wres, fp32 out)
__global__ void __launch_bounds__(512, 2)
hgemm_l1(const float* __restrict__ A, float* __restrict__ Cout,
         const float* __restrict__ a_s, const float* __restrict__ a_d,
         int M, int nb) {
    extern __shared__ __half sm[];
    __half* sBh = sm;
    __half* sAh = sBh + 128 * LDBS;
    int tid = threadIdx.x;
    int wid = tid >> 5, lane = tid & 31;
    int wm = wid & 3, wn = wid >> 2;
    int xwrole = blockIdx.x < nb;
    int row0 = (xwrole ? blockIdx.x : blockIdx.x - nb) * 128;
    int boff = xwrole ? 0 : 16384;

    #pragma unroll
    for (int it = 0; it < 4; it++) {
        int idx = tid + it * 512;
        int c4 = idx & 15, row = idx >> 4;
        cp16(sBh + row * LDBS + c4 * 8, g_Bh + boff + row * 128 + c4 * 8);
    }
    asm volatile("cp.async.commit_group;\n");

    #pragma unroll
    for (int it = 0; it < 16; it++) {
        int idx = tid + it * 512;
        int c2 = idx & 63, r = idx >> 6;
        int gr = row0 + r;
        float2 v = make_float2(0.f, 0.f);
        if (gr < M) v = *(const float2*)(A + (size_t)gr * 128 + c2 * 2);
        *(__half2*)(sAh + r * LDAH + c2 * 2) = __floats2half2_rn(v.x, v.y);
    }
    asm volatile("cp.async.wait_group 0;\n");
    __syncthreads();

    wmma::fragment<wmma::accumulator, 16, 16, 16, float> acc[2][2];
    #pragma unroll
    for (int i = 0; i < 2; i++)
        #pragma unroll
        for (int j = 0; j < 2; j++)
            wmma::fill_fragment(acc[i][j], 0.f);

    #pragma unroll
    for (int kk = 0; kk < 8; kk++) {
        wmma::fragment<wmma::matrix_a, 16, 16, 16, __half, wmma::row_major> ah[2];
        #pragma unroll
        for (int i = 0; i < 2; i++)
            wmma::load_matrix_sync(ah[i], sAh + (wm * 32 + i * 16) * LDAH + kk * 16, LDAH);
        #pragma unroll
        for (int j = 0; j < 2; j++) {
            wmma::fragment<wmma::matrix_b, 16, 16, 16, __half, wmma::row_major> bh;
            wmma::load_matrix_sync(bh, sBh + kk * 16 * LDBS + wn * 32 + j * 16, LDBS);
            #pragma unroll
            for (int i = 0; i < 2; i++)
                wmma::mma_sync(acc[i][j], ah[i], bh, acc[i][j]);
        }
    }

    __syncthreads();
    float* Cs = (float*)sm;   // 128 x LDC fp32 = 67.6KB <= 69.6KB
    #pragma unroll
    for (int i = 0; i < 2; i++) {
        int r = wm * 32 + i * 16;
        #pragma unroll
        for (int j = 0; j < 2; j++)
            wmma::store_matrix_sync(Cs + (size_t)r * LDC + wn * 32 + j * 16,
                                    acc[i][j], LDC, wmma::mem_row_major);
    }
    __syncthreads();
    if (xwrole) {
        dots_epilogue(Cs, row0, M, wid, lane, a_s, a_d);
    } else {
        #pragma unroll
        for (int it = 0; it < 8; it++) {
            int idx = tid + it * 512;           // 4096 float4
            int r = idx >> 5, c4 = idx & 31;
            int gr = row0 + r;
            if (gr < M)
                *(float4*)(Cout + (size_t)gr * 128 + c4 * 4) =
                    *(const float4*)(Cs + (size_t)r * LDC + c4 * 4);
        }
    }
}

// ------------------------- GEMM (layer 2): fp16 A direct --------------------
__global__ void __launch_bounds__(512, 2)
hgemm128(int M, int boff,
         const float* __restrict__ a_s, const float* __restrict__ a_d) {
    extern __shared__ __half sm[];
    __half* sBh = sm;
    __half* sAh = sBh + 128 * LDBS;
    int tid = threadIdx.x;
    int wid = tid >> 5, lane = tid & 31;
    int wm = wid & 3, wn = wid >> 2;
    int row0 = blockIdx.x * 128;

    #pragma unroll
    for (int it = 0; it < 4; it++) {
        int idx = tid + it * 512;
        int c4 = idx & 15, row = idx >> 4;
        cp16(sBh + row * LDBS + c4 * 8, g_Bh + boff + row * 128 + c4 * 8);
    }
    #pragma unroll
    for (int it = 0; it < 4; it++) {
        int idx = tid + it * 512;
        int c4 = idx & 15, r = idx >> 4;
        cp16(sAh + r * LDAH + c4 * 8, g_hh + (size_t)(row0 + r) * 128 + c4 * 8);
    }
    asm volatile("cp.async.commit_group;\n");
    asm volatile("cp.async.wait_group 0;\n");
    __syncthreads();

    wmma::fragment<wmma::accumulator, 16, 16, 16, float> acc[2][2];
    #pragma unroll
    for (int i = 0; i < 2; i++)
        #pragma unroll
        for (int j = 0; j < 2; j++)
            wmma::fill_fragment(acc[i][j], 0.f);

    #pragma unroll
    for (int kk = 0; kk < 8; kk++) {
        wmma::fragment<wmma::matrix_a, 16, 16, 16, __half, wmma::row_major> ah[2];
        #pragma unroll
        for (int i = 0; i < 2; i++)
            wmma::load_matrix_sync(ah[i], sAh + (wm * 32 + i * 16) * LDAH + kk * 16, LDAH);
        #pragma unroll
        for (int j = 0; j < 2; j++) {
            wmma::fragment<wmma::matrix_b, 16, 16, 16, __half, wmma::row_major> bh;
            wmma::load_matrix_sync(bh, sBh + kk * 16 * LDBS + wn * 32 + j * 16, LDBS);
            #pragma unroll
            for (int i = 0; i < 2; i++)
                wmma::mma_sync(acc[i][j], ah[i], bh, acc[i][j]);
        }
    }

    __syncthreads();
    float* Cs = (float*)sm;
    #pragma unroll
    for (int i = 0; i < 2; i++) {
        int r = wm * 32 + i * 16;
        #pragma unroll
        for (int j = 0; j < 2; j++)
            wmma::store_matrix_sync(Cs + (size_t)r * LDC + wn * 32 + j * 16,
                                    acc[i][j], LDC, wmma::mem_row_major);
    }
    __syncthreads();
    dots_epilogue(Cs, row0, M, wid, lane, a_s, a_d);
}

// ------------------------- layer-3 WMMA GEMM, A fp16 direct -----------------
__global__ void __launch_bounds__(256, 2)
hgemm40(const float* __restrict__ a_s, const float* __restrict__ a_d,
        float* __restrict__ C, int M) {
    extern __shared__ __half sm[];
    __half* sBh = sm;
    __half* sAh = sBh + 128 * LDB3;
    int tid = threadIdx.x;
    int wid = tid >> 5, lane = tid & 31;
    int row0 = blockIdx.x * 128;

    #pragma unroll
    for (int it = 0; it < 3; it++) {
        int idx = tid + it * 256;
        int row = idx / 6, c = idx - row * 6;
        cp16(sBh + row * LDB3 + c * 8, g_B3h + row * 48 + c * 8);
    }
    #pragma unroll
    for (int it = 0; it < 8; it++) {
        int idx = tid + it * 256;
        int c4 = idx & 15, r = idx >> 4;
        cp16(sAh + r * LDAH + c4 * 8, g_hh + (size_t)(row0 + r) * 128 + c4 * 8);
    }
    asm volatile("cp.async.commit_group;\n");
    asm volatile("cp.async.wait_group 0;\n");
    __syncthreads();

    wmma::fragment<wmma::accumulator, 16, 16, 16, float> acc[3];
    #pragma unroll
    for (int j = 0; j < 3; j++) wmma::fill_fragment(acc[j], 0.f);

    #pragma unroll
    for (int kk = 0; kk < 8; kk++) {
        wmma::fragment<wmma::matrix_a, 16, 16, 16, __half, wmma::row_major> ah;
        wmma::load_matrix_sync(ah, sAh + (wid * 16) * LDAH + kk * 16, LDAH);
        #pragma unroll
        for (int j = 0; j < 3; j++) {
            wmma::fragment<wmma::matrix_b, 16, 16, 16, __half, wmma::row_major> bh;
            wmma::load_matrix_sync(bh, sBh + kk * 16 * LDB3 + j * 16, LDB3);
            wmma::mma_sync(acc[j], ah, bh, acc[j]);
        }
    }

    __syncthreads();
    float* Cs = (float*)sm;
    #pragma unroll
    for (int j = 0; j < 3; j++)
        wmma::store_matrix_sync(Cs + (size_t)(wid * 16) * LDC3 + j * 16,
                                acc[j], LDC3, wmma::mem_row_major);
    __syncthreads();

    float as1v = a_s[lane], ad1v = a_d[lane];
    float as2v = (lane < 8) ? a_s[32 + lane] : 0.f;
    float ad2v = (lane < 8) ? a_d[32 + lane] : 0.f;
    #pragma unroll
    for (int rr = 0; rr < 16; rr++) {
        int r = wid * 16 + rr;
        int row = row0 + r;
        if (row >= M) break;
        float x1 = Cs[(size_t)r * LDC3 + lane];
        float x2 = (lane < 8) ? Cs[(size_t)r * LDC3 + 32 + lane] : 0.f;
        C[(size_t)row * 40 + lane] = x1;
        if (lane < 8) C[(size_t)row * 40 + 32 + lane] = x2;
        float ps = x1 * as1v + x2 * as2v;
        float pd = x1 * ad1v + x2 * ad2v;
        #pragma unroll
        for (int o = 16; o; o >>= 1) {
            ps += __shfl_xor_sync(0xffffffffu, ps, o);
            pd += __shfl_xor_sync(0xffffffffu, pd, o);
        }
        if (lane == 0) { g_es[row] = ps; g_ed[row] = pd; }
    }
}

// ------------------------- fused GAT agg: max-only pass1, den in pass2 ------
__global__ void agg128(const float* __restrict__ bias,
                       const float* __restrict__ gam, const float* __restrict__ bet,
                       const float* __restrict__ mean, const float* __restrict__ var,
                       const float* __restrict__ res, float* __restrict__ out, int n) {
    int node = blockIdx.x * 8 + (threadIdx.x >> 5);
    if (node >= n) return;
    int lane = threadIdx.x & 31;
    int head = lane >> 3, esub = lane & 7;
    float ed = g_ed[node * 4 + head];
    int s = g_off[node], e = g_off[node + 1];

    // pass 1: max only (order-independent; no exp, no serial rescale)
    float m = -1e30f;
    for (int base = s; base < e; base += 8) {
        int i = base + esub;
        bool val = i < e;
        int u = val ? g_csr[i] : 0;
        float ev = g_es[u * 4 + head] + ed;
        ev = ev > 0.f ? ev : 0.2f * ev;
        if (!val) ev = -1e30f;
        m = fmaxf(m, ev);
    }
    m = fmaxf(m, __shfl_xor_sync(0xffffffffu, m, 1));
    m = fmaxf(m, __shfl_xor_sync(0xffffffffu, m, 2));
    m = fmaxf(m, __shfl_xor_sync(0xffffffffu, m, 4));

    // pass 2: weighted gather + denominator (redundant per lane, same value)
    float4 acc = make_float4(0.f, 0.f, 0.f, 0.f);
    float den = 0.f;
    int i = s;
    for (; i + 3 < e; i += 4) {
        int u0 = g_csr[i], u1 = g_csr[i + 1], u2 = g_csr[i + 2], u3 = g_csr[i + 3];
        float e0 = g_es[u0 * 4 + head] + ed;
        float e1 = g_es[u1 * 4 + head] + ed;
        float e2 = g_es[u2 * 4 + head] + ed;
        float e3 = g_es[u3 * 4 + head] + ed;
        e0 = e0 > 0.f ? e0 : 0.2f * e0;
        e1 = e1 > 0.f ? e1 : 0.2f * e1;
        e2 = e2 > 0.f ? e2 : 0.2f * e2;
        e3 = e3 > 0.f ? e3 : 0.2f * e3;
        float w0 = __expf(e0 - m), w1 = __expf(e1 - m);
        float w2 = __expf(e2 - m), w3 = __expf(e3 - m);
        den += (w0 + w1) + (w2 + w3);
        uint2 p0 = *(const uint2*)(g_xwh + (size_t)u0 * 128 + lane * 4);
        uint2 p1 = *(const uint2*)(g_xwh + (size_t)u1 * 128 + lane * 4);
        uint2 p2 = *(const uint2*)(g_xwh + (size_t)u2 * 128 + lane * 4);
        uint2 p3 = *(const uint2*)(g_xwh + (size_t)u3 * 128 + lane * 4);
        float2 a0 = __half22float2(*(__half2*)&p0.x), b0 = __half22float2(*(__half2*)&p0.y);
        float2 a1 = __half22float2(*(__half2*)&p1.x), b1 = __half22float2(*(__half2*)&p1.y);
        float2 a2 = __half22float2(*(__half2*)&p2.x), b2 = __half22float2(*(__half2*)&p2.y);
        float2 a3 = __half22float2(*(__half2*)&p3.x), b3 = __half22float2(*(__half2*)&p3.y);
        acc.x += w0 * a0.x + w1 * a1.x + w2 * a2.x + w3 * a3.x;
        acc.y += w0 * a0.y + w1 * a1.y + w2 * a2.y + w3 * a3.y;
        acc.z += w0 * b0.x + w1 * b1.x + w2 * b2.x + w3 * b3.x;
        acc.w += w0 * b0.y + w1 * b1.y + w2 * b2.y + w3 * b3.y;
    }
    for (; i < e; i++) {
        int u0 = g_csr[i];
        float e0 = g_es[u0 * 4 + head] + ed;
        e0 = e0 > 0.f ? e0 : 0.2f * e0;
        float w0 = __expf(e0 - m);
        den += w0;
        uint2 p0 = *(const uint2*)(g_xwh + (size_t)u0 * 128 + lane * 4);
        float2 a0 = __half22float2(*(__half2*)&p0.x);
        float2 b0 = __half22float2(*(__half2*)&p0.y);
        acc.x += w0 * a0.x; acc.y += w0 * a0.y;
        acc.z += w0 * b0.x; acc.w += w0 * b0.y;
    }
    float rinv = 1.f / den;

    int c = lane * 4;
    float4 b4 = *(const float4*)(bias + c);
    float4 g4 = *(const float4*)(gam + c);
    float4 e4 = *(const float4*)(bet + c);
    float4 m4 = *(const float4*)(mean + c);
    float4 v4 = *(const float4*)(var + c);
    float4 r4 = *(const float4*)(res + (size_t)node * 128 + c);
    float o0 = (acc.x * rinv + b4.x - m4.x) * rsqrtf(v4.x + GAT_EPS) * g4.x + e4.x + r4.x;
    float o1 = (acc.y * rinv + b4.y - m4.y) * rsqrtf(v4.y + GAT_EPS) * g4.y + e4.y + r4.y;
    float o2 = (acc.z * rinv + b4.z - m4.z) * rsqrtf(v4.z + GAT_EPS) * g4.z + e4.z + r4.z;
    float o3 = (acc.w * rinv + b4.w - m4.w) * rsqrtf(v4.w + GAT_EPS) * g4.w + e4.w + r4.w;
    float4 o = make_float4(o0 > 0.f ? o0 : expm1f(o0),
                           o1 > 0.f ? o1 : expm1f(o1),
                           o2 > 0.f ? o2 : expm1f(o2),
                           o3 > 0.f ? o3 : expm1f(o3));
    *(float4*)(out + (size_t)node * 128 + c) = o;
    __half2 ha = __floats2half2_rn(o.x, o.y);
    __half2 hb = __floats2half2_rn(o.z, o.w);
    uint2 ph = make_uint2(*(unsigned*)&ha, *(unsigned*)&hb);
    *(uint2*)(g_hh + (size_t)node * 128 + c) = ph;
}

// ------------------------- layer-3 agg (fp32, max pass1 + den pass2) --------
__global__ void agg40(const float* __restrict__ xw, const float* __restrict__ bias,
                      float* __restrict__ out, int n) {
    int node = blockIdx.x * 8 + (threadIdx.x >> 5);
    if (node >= n) return;
    int lane = threadIdx.x & 31;
    float ed = g_ed[node];
    int s = g_off[node], e = g_off[node + 1];

    float m = -1e30f;
    for (int base = s; base < e; base += 32) {
        int i = base + lane;
        bool val = i < e;
        int u = val ? g_csr[i] : 0;
        float ev = g_es[u] + ed;
        ev = ev > 0.f ? ev : 0.2f * ev;
        if (!val) ev = -1e30f;
        m = fmaxf(m, ev);
    }
    #pragma unroll
    for (int o = 16; o; o >>= 1) m = fmaxf(m, __shfl_xor_sync(0xffffffffu, m, o));

    float a1 = 0.f, a2 = 0.f, den = 0.f;
    int u = g_csr[s];
    for (int i = s; i < e; i++) {
        int un = g_csr[i + 1];
        float ev = g_es[u] + ed;
        ev = ev > 0.f ? ev : 0.2f * ev;
        float w = __expf(ev - m);
        den += w;
        a1 += w * xw[(size_t)u * 40 + lane];
        if (lane < 8) a2 += w * xw[(size_t)u * 40 + 32 + lane];
        u = un;
    }
    float rinv = 1.f / den;
    out[(size_t)node * 40 + lane] = a1 * rinv + bias[lane];
    if (lane < 8) out[(size_t)node * 40 + 32 + lane] = a2 * rinv + bias[32 + lane];
}

// ------------------------- launch ------------------------------------------
extern "C" void kernel_launch(void* const* d_in, const int* in_sizes, int n_in,
                              void* d_out, int out_size) {
    const float* x    = (const float*)d_in[0];
    const int*   ei   = (const int*)  d_in[1];
    const float* W1   = (const float*)d_in[2];
    const float* as1  = (const float*)d_in[3];
    const float* ad1  = (const float*)d_in[4];
    const float* b1   = (const float*)d_in[5];
    const float* W2   = (const float*)d_in[6];
    const float* as2  = (const float*)d_in[7];
    const float* ad2  = (const float*)d_in[8];
    const float* b2   = (const float*)d_in[9];
    const float* W3   = (const float*)d_in[10];
    const float* as3  = (const float*)d_in[11];
    const float* ad3  = (const float*)d_in[12];
    const float* b3   = (const float*)d_in[13];
    const float* Wres = (const float*)d_in[14];
    const float* g1   = (const float*)d_in[15];
    const float* be1  = (const float*)d_in[16];
    const float* m1   = (const float*)d_in[17];
    const float* v1   = (const float*)d_in[18];
    const float* g2   = (const float*)d_in[19];
    const float* be2  = (const float*)d_in[20];
    const float* m2   = (const float*)d_in[21];
    const float* v2   = (const float*)d_in[22];

    int n = in_sizes[0] / 128;
    int E = in_sizes[1] / 2;
    const int* src = ei;
    const int* dst = ei + E;
    int tot = E + n;
    int nblk = (n + 1023) / 1024;

    float *p_aux, *p_h1, *p_h2, *p_xw3;
    cudaGetSymbolAddress((void**)&p_aux, g_aux);
    cudaGetSymbolAddress((void**)&p_h1,  g_h1);
    cudaGetSymbolAddress((void**)&p_h2,  g_h2);
    cudaGetSymbolAddress((void**)&p_xw3, g_xw3);

    cudaFuncSetAttribute(hgemm_l1,  cudaFuncAttributeMaxDynamicSharedMemorySize, SM_SNGL);
    cudaFuncSetAttribute(hgemm128,  cudaFuncAttributeMaxDynamicSharedMemorySize, SM_SNGL);
    cudaFuncSetAttribute(hgemm40,   cudaFuncAttributeMaxDynamicSharedMemorySize, SM_40);

    int nb_gemm = (n + 127) / 128;
    int nb_warp = (n + 7) / 8;
    int nb_pre  = (tot + 255) / 256;

    preB_histo <<<nb_pre, 256>>>(W1, Wres, W2, W3, dst, E, n);             // 1
    scan1_kernel <<<nblk, 256>>>(n);                                       // 2
    hgemm_l1 <<<2 * nb_gemm, 512, SM_SNGL>>>(x, p_aux, as1, ad1, n, nb_gemm); // 3 (xw+aux)
    scan23_kernel <<<(n + 255) / 256, 256>>>(nblk, n);                     // 4
    scatter_kernel <<<(tot + 255) / 256, 256>>>(src, dst, E, n);           // 5

    // ---- layer 1 aggregation (emits fp16 h1 mirror) ----
    agg128 <<<nb_warp, 256>>>(b1, g1, be1, m1, v1, p_aux, p_h1, n);        // 6

    // ---- layer 2 ----
    hgemm128 <<<nb_gemm, 512, SM_SNGL>>>(n, 32768, as2, ad2);              // 7
    agg128 <<<nb_warp, 256>>>(b2, g2, be2, m2, v2, p_h1, p_h2, n);         // 8

    // ---- layer 3 ----
    hgemm40 <<<nb_gemm, 256, SM_40>>>(as3, ad3, p_xw3, n);                 // 9
    agg40  <<<nb_warp, 256>>>(p_xw3, b3, (float*)d_out, n);                // 10
}